// round 2
// baseline (speedup 1.0000x reference)
#include <cuda_runtime.h>
#include <math.h>

// Problem constants
#define TOKS 4096      // B*S = 2*2048
#define SEQ  2048
#define NB   2
#define NH   16
#define HD   128       // head dim
#define HIDN 2048
#define DLAT 512

// Scratch (device globals; no allocations allowed)
__device__ float g_q[TOKS * 2048];
__device__ float g_k[TOKS * 2048];
__device__ float g_v[TOKS * 2048];
__device__ float g_lat[TOKS * DLAT];
__device__ float g_attn[TOKS * 2048];

// ----------------------------------------------------------------------------
// SGEMM: C[M,N] = A[M,K] @ B[K,N], 128x128 block tile, BK=16, 256 threads,
// 8x8 accumulator per thread. Epilogue remaps columns:
//   out_col = (col >> lgGroup) * outstride + base + (col & (group-1))
// which implements both plain stores (group=N) and the kr/kn head-interleave.
// Requires M%128==0, N%128==0, K%16==0 (true for all calls here).
// ----------------------------------------------------------------------------
__global__ __launch_bounds__(256)
void sgemm128(const float* __restrict__ A, const float* __restrict__ B,
              float* __restrict__ C, int M, int N, int K,
              int lgGroup, int outstride, int base, int ldc)
{
    __shared__ float As[16][132];
    __shared__ float Bs[16][132];
    const int tid = threadIdx.x;
    const int bm = blockIdx.y * 128;
    const int bn = blockIdx.x * 128;
    const int ty = tid >> 4;
    const int tx = tid & 15;

    float acc[8][8];
#pragma unroll
    for (int i = 0; i < 8; ++i)
#pragma unroll
        for (int j = 0; j < 8; ++j) acc[i][j] = 0.0f;

    for (int k0 = 0; k0 < K; k0 += 16) {
        // Load A tile (128 rows x 16 cols), store transposed As[k][m]
#pragma unroll
        for (int i = 0; i < 2; ++i) {
            int f = tid + i * 256;            // 512 float4 total
            int row = f >> 2;                 // 4 float4 per row
            int kc = (f & 3) << 2;
            float4 a = *(const float4*)(A + (size_t)(bm + row) * K + k0 + kc);
            As[kc + 0][row] = a.x;
            As[kc + 1][row] = a.y;
            As[kc + 2][row] = a.z;
            As[kc + 3][row] = a.w;
        }
        // Load B tile (16 rows x 128 cols) direct
#pragma unroll
        for (int i = 0; i < 2; ++i) {
            int f = tid + i * 256;            // 512 float4 total
            int row = f >> 5;                 // 32 float4 per row
            int col = (f & 31) << 2;
            *(float4*)&Bs[row][col] =
                *(const float4*)(B + (size_t)(k0 + row) * N + bn + col);
        }
        __syncthreads();

#pragma unroll
        for (int kk = 0; kk < 16; ++kk) {
            float a_frag[8], b_frag[8];
            *(float4*)&a_frag[0] = *(float4*)&As[kk][ty * 8];
            *(float4*)&a_frag[4] = *(float4*)&As[kk][ty * 8 + 4];
            *(float4*)&b_frag[0] = *(float4*)&Bs[kk][tx * 8];
            *(float4*)&b_frag[4] = *(float4*)&Bs[kk][tx * 8 + 4];
#pragma unroll
            for (int i = 0; i < 8; ++i)
#pragma unroll
                for (int j = 0; j < 8; ++j)
                    acc[i][j] += a_frag[i] * b_frag[j];
        }
        __syncthreads();
    }

    const int gmask = (1 << lgGroup) - 1;
#pragma unroll
    for (int i = 0; i < 8; ++i) {
        int row = bm + ty * 8 + i;
#pragma unroll
        for (int j = 0; j < 8; ++j) {
            int col = bn + tx * 8 + j;
            int oc = ((col >> lgGroup) * outstride) + base + (col & gmask);
            C[(size_t)row * ldc + oc] = acc[i][j];
        }
    }
}

// ----------------------------------------------------------------------------
// Per-head RMSNorm over D=128, in place. One warp per row, 4 floats per lane.
// ----------------------------------------------------------------------------
__global__ __launch_bounds__(256)
void rmsnorm128(float* __restrict__ data, const float* __restrict__ g)
{
    int row = blockIdx.x * 8 + (threadIdx.x >> 5);
    int lane = threadIdx.x & 31;
    float4* p = (float4*)(data + (size_t)row * 128) + lane;
    float4 v = *p;
    float ss = v.x * v.x + v.y * v.y + v.z * v.z + v.w * v.w;
#pragma unroll
    for (int o = 16; o; o >>= 1) ss += __shfl_xor_sync(0xffffffffu, ss, o);
    float r = rsqrtf(ss * (1.0f / 128.0f) + 1e-6f);
    float4 gv = ((const float4*)g)[lane];
    v.x *= r * gv.x; v.y *= r * gv.y; v.z *= r * gv.z; v.w *= r * gv.w;
    *p = v;
}

// ----------------------------------------------------------------------------
// Causal flash attention, fp32. Layouts: q/k/v/out are [tok][h][d] (tok=b*S+s).
// Grid: (B*H, S/8). Block: 256 threads = 8 warps; warp w owns query
// qi = blockIdx.y*8 + w. Online softmax, acc spread 4 floats per lane.
// Keys processed in 32-row smem tiles (K and V co-resident, 32 KB).
// ----------------------------------------------------------------------------
__global__ __launch_bounds__(256)
void attn_causal(const float* __restrict__ q, const float* __restrict__ k,
                 const float* __restrict__ v, float* __restrict__ o)
{
    __shared__ float Ks[32][128];
    __shared__ float Vs[32][128];

    const int bh = blockIdx.x;
    const int b = bh >> 4;
    const int h = bh & 15;
    const int warp = threadIdx.x >> 5;
    const int lane = threadIdx.x & 31;
    const int qi = blockIdx.y * 8 + warp;
    const int tok = b * SEQ + qi;
    const float scale = 0.08838834764831845f;   // 1/sqrt(128)

    float4 q4 = *(const float4*)(q + ((size_t)tok * NH + h) * HD + lane * 4);

    float m = -1e30f, l = 0.0f;
    float4 acc = make_float4(0.f, 0.f, 0.f, 0.f);

    const int kmax = blockIdx.y * 8 + 7;        // largest query in block
    const int ntiles = (kmax >> 5) + 1;

    for (int t = 0; t < ntiles; ++t) {
        const int base_key = t * 32;
        // cooperative load: 32x128 floats x2 = 1024 float4 each
        for (int i = threadIdx.x; i < 1024; i += 256) {
            int kr = i >> 5;
            int kc = (i & 31) << 2;
            size_t off = ((size_t)(b * SEQ + base_key + kr) * NH + h) * HD + kc;
            *(float4*)&Ks[kr][kc] = *(const float4*)(k + off);
            *(float4*)&Vs[kr][kc] = *(const float4*)(v + off);
        }
        __syncthreads();

        int jend = qi - base_key + 1;
        if (jend > 32) jend = 32;
        for (int j = 0; j < jend; ++j) {
            float4 k4 = *(float4*)&Ks[j][lane * 4];
            float s = q4.x * k4.x + q4.y * k4.y + q4.z * k4.z + q4.w * k4.w;
#pragma unroll
            for (int off = 16; off; off >>= 1)
                s += __shfl_xor_sync(0xffffffffu, s, off);
            s *= scale;
            float mn = fmaxf(m, s);
            float al = __expf(m - mn);
            float p = __expf(s - mn);
            m = mn;
            l = l * al + p;
            float4 v4 = *(float4*)&Vs[j][lane * 4];
            acc.x = acc.x * al + p * v4.x;
            acc.y = acc.y * al + p * v4.y;
            acc.z = acc.z * al + p * v4.z;
            acc.w = acc.w * al + p * v4.w;
        }
        __syncthreads();
    }

    float inv = 1.0f / l;
    float4 out4 = make_float4(acc.x * inv, acc.y * inv, acc.z * inv, acc.w * inv);
    *(float4*)(o + ((size_t)tok * NH + h) * HD + lane * 4) = out4;
}

// ----------------------------------------------------------------------------
extern "C" void kernel_launch(void* const* d_in, const int* in_sizes, int n_in,
                              void* d_out, int out_size)
{
    const float* x   = (const float*)d_in[0];
    const float* Wq  = (const float*)d_in[1];
    const float* Wkv = (const float*)d_in[2];
    const float* Wkr = (const float*)d_in[3];
    const float* Wkn = (const float*)d_in[4];
    const float* Wv  = (const float*)d_in[5];
    const float* Wo  = (const float*)d_in[6];
    const float* gq  = (const float*)d_in[7];
    const float* gk  = (const float*)d_in[8];
    float* out = (float*)d_out;

    float *q, *k, *v, *lat, *attn;
    cudaGetSymbolAddress((void**)&q,    g_q);
    cudaGetSymbolAddress((void**)&k,    g_k);
    cudaGetSymbolAddress((void**)&v,    g_v);
    cudaGetSymbolAddress((void**)&lat,  g_lat);
    cudaGetSymbolAddress((void**)&attn, g_attn);

    dim3 blk(256);

    // q = x @ Wq  -> [4096, 2048]
    sgemm128<<<dim3(2048 / 128, TOKS / 128), blk>>>(x, Wq, q, TOKS, 2048, HIDN,
                                                    11, 2048, 0, 2048);
    // lat = x @ Wkv -> [4096, 512]
    sgemm128<<<dim3(DLAT / 128, TOKS / 128), blk>>>(x, Wkv, lat, TOKS, DLAT, HIDN,
                                                    9, DLAT, 0, DLAT);
    // kr = lat @ Wkr -> k[..., h, 0:64]   (col j -> (j/64)*128 + j%64)
    sgemm128<<<dim3(1024 / 128, TOKS / 128), blk>>>(lat, Wkr, k, TOKS, 1024, DLAT,
                                                    6, 128, 0, 2048);
    // kn = lat @ Wkn -> k[..., h, 64:128] (col j -> (j/64)*128 + 64 + j%64)
    sgemm128<<<dim3(1024 / 128, TOKS / 128), blk>>>(lat, Wkn, k, TOKS, 1024, DLAT,
                                                    6, 128, 64, 2048);
    // v = lat @ Wv -> [4096, 2048]
    sgemm128<<<dim3(2048 / 128, TOKS / 128), blk>>>(lat, Wv, v, TOKS, 2048, DLAT,
                                                    11, 2048, 0, 2048);
    // per-head RMSNorm on q and k (65536 rows of 128)
    rmsnorm128<<<TOKS * NH / 8, blk>>>(q, gq);
    rmsnorm128<<<TOKS * NH / 8, blk>>>(k, gk);
    // causal attention -> attn [tok][h][d]
    attn_causal<<<dim3(NB * NH, SEQ / 8), blk>>>(q, k, v, attn);
    // out = attn @ Wo -> [4096, 2048]
    sgemm128<<<dim3(2048 / 128, TOKS / 128), blk>>>(attn, Wo, out, TOKS, 2048, 2048,
                                                    11, 2048, 0, 2048);
}

// round 3
// speedup vs baseline: 1.4664x; 1.4664x over previous
#include <cuda_runtime.h>
#include <cuda_fp16.h>
#include <math.h>
#include <stdint.h>

// Problem constants
#define TOKS 4096      // B*S = 2*2048
#define SEQ  2048
#define NB   2
#define NH   16
#define HD   128
#define HIDN 2048
#define DLAT 512

// fp32 scratch
__device__ float g_q[TOKS * 2048];
__device__ float g_k[TOKS * 2048];
__device__ float g_v[TOKS * 2048];
__device__ float g_lat[TOKS * DLAT];
__device__ float g_attn[TOKS * 2048];

// fp16 scratch (GEMM operands)
__device__ __half h_x[TOKS * HIDN];
__device__ __half h_Wq[HIDN * 2048];
__device__ __half h_Wkv[HIDN * DLAT];
__device__ __half h_Wkr[DLAT * 1024];
__device__ __half h_Wkn[DLAT * 1024];
__device__ __half h_Wv[DLAT * 2048];
__device__ __half h_Wo[2048 * HIDN];
__device__ __half h_lat[TOKS * DLAT];
__device__ __half h_attn[TOKS * 2048];

// ----------------------------------------------------------------------------
// float -> half conversion, 4 elems/thread. n must be a multiple of 1024.
// ----------------------------------------------------------------------------
__global__ __launch_bounds__(256)
void f2h(const float* __restrict__ in, __half* __restrict__ out)
{
    int i = (blockIdx.x * 256 + threadIdx.x) * 4;
    float4 v = *(const float4*)(in + i);
    __half2 lo = __floats2half2_rn(v.x, v.y);
    __half2 hi = __floats2half2_rn(v.z, v.w);
    *(__half2*)(out + i)     = lo;
    *(__half2*)(out + i + 2) = hi;
}

// ----------------------------------------------------------------------------
// Tensor-core GEMM: C[M,N] (fp32) = A[M,K] @ B[K,N] (fp16 in, f32 accumulate).
// 128x128 block tile, BK=32, 256 threads = 8 warps (2 M x 4 N), warp tile
// 64x32 via mma.sync.m16n8k16. Epilogue column remap as before:
//   out_col = (col >> lgGroup) * outstride + base + (col & (group-1))
// ----------------------------------------------------------------------------
#define AS_STRIDE 40    // halves; 80B rows -> ldmatrix conflict-free
#define BS_STRIDE 136   // halves; 272B rows -> ldmatrix conflict-free

__device__ __forceinline__ uint32_t sptr(const void* p)
{
    return (uint32_t)__cvta_generic_to_shared(p);
}

__device__ __forceinline__ void ldsm_x4(uint32_t* r, uint32_t addr)
{
    asm volatile("ldmatrix.sync.aligned.m8n8.x4.shared.b16 {%0,%1,%2,%3}, [%4];\n"
                 : "=r"(r[0]), "=r"(r[1]), "=r"(r[2]), "=r"(r[3]) : "r"(addr));
}

__device__ __forceinline__ void ldsm_x2t(uint32_t* r, uint32_t addr)
{
    asm volatile("ldmatrix.sync.aligned.m8n8.x2.trans.shared.b16 {%0,%1}, [%2];\n"
                 : "=r"(r[0]), "=r"(r[1]) : "r"(addr));
}

__device__ __forceinline__ void mma16816(float* c, const uint32_t* a, const uint32_t* b)
{
    asm volatile(
        "mma.sync.aligned.m16n8k16.row.col.f32.f16.f16.f32 "
        "{%0,%1,%2,%3}, {%4,%5,%6,%7}, {%8,%9}, {%0,%1,%2,%3};\n"
        : "+f"(c[0]), "+f"(c[1]), "+f"(c[2]), "+f"(c[3])
        : "r"(a[0]), "r"(a[1]), "r"(a[2]), "r"(a[3]), "r"(b[0]), "r"(b[1]));
}

__global__ __launch_bounds__(256)
void hgemm128(const __half* __restrict__ A, const __half* __restrict__ B,
              float* __restrict__ C, int M, int N, int K,
              int lgGroup, int outstride, int base, int ldc)
{
    __shared__ __half As[128 * AS_STRIDE];
    __shared__ __half Bs[32 * BS_STRIDE];

    const int tid  = threadIdx.x;
    const int warp = tid >> 5;
    const int lane = tid & 31;
    const int bm = blockIdx.y * 128;
    const int bn = blockIdx.x * 128;
    const int wm = (warp & 1) * 64;
    const int wn = (warp >> 1) * 32;

    float c[4][4][4];
#pragma unroll
    for (int mt = 0; mt < 4; ++mt)
#pragma unroll
        for (int nt = 0; nt < 4; ++nt)
#pragma unroll
            for (int i = 0; i < 4; ++i) c[mt][nt][i] = 0.0f;

    // precomputed ldmatrix smem addresses (per-lane, fixed over k loop)
    const uint32_t a_base = sptr(&As[(wm + (lane & 15)) * AS_STRIDE + (lane >> 4) * 8]);
    const uint32_t b_base = sptr(&Bs[(lane & 15) * BS_STRIDE + wn]);

    for (int k0 = 0; k0 < K; k0 += 32) {
        // fill A tile: 128 rows x 32 halves = 512 x 16B chunks
#pragma unroll
        for (int i = 0; i < 2; ++i) {
            int cch = tid + i * 256;
            int row = cch >> 2;
            int kc = (cch & 3) * 8;
            *(uint4*)&As[row * AS_STRIDE + kc] =
                *(const uint4*)(A + (size_t)(bm + row) * K + k0 + kc);
        }
        // fill B tile: 32 rows x 128 halves = 512 x 16B chunks
#pragma unroll
        for (int i = 0; i < 2; ++i) {
            int cch = tid + i * 256;
            int row = cch >> 4;
            int nc = (cch & 15) * 8;
            *(uint4*)&Bs[row * BS_STRIDE + nc] =
                *(const uint4*)(B + (size_t)(k0 + row) * N + bn + nc);
        }
        __syncthreads();

#pragma unroll
        for (int kt = 0; kt < 2; ++kt) {
            uint32_t a[4][4], b[4][2];
#pragma unroll
            for (int mt = 0; mt < 4; ++mt)
                ldsm_x4(a[mt], a_base + (mt * 16 * AS_STRIDE + kt * 16) * 2);
#pragma unroll
            for (int nt = 0; nt < 4; ++nt)
                ldsm_x2t(b[nt], b_base + (kt * 16 * BS_STRIDE + nt * 8) * 2);
#pragma unroll
            for (int mt = 0; mt < 4; ++mt)
#pragma unroll
                for (int nt = 0; nt < 4; ++nt)
                    mma16816(c[mt][nt], a[mt], b[nt]);
        }
        __syncthreads();
    }

    // epilogue with column remap; c0/c1 and c2/c3 are column-adjacent pairs
    const int gmask = (1 << lgGroup) - 1;
    const int gid = lane >> 2;
    const int tig = lane & 3;
#pragma unroll
    for (int mt = 0; mt < 4; ++mt) {
#pragma unroll
        for (int nt = 0; nt < 4; ++nt) {
            int col = bn + wn + nt * 8 + tig * 2;
            int oc = ((col >> lgGroup) * outstride) + base + (col & gmask);
            int r0 = bm + wm + mt * 16 + gid;
            *(float2*)&C[(size_t)r0 * ldc + oc] = make_float2(c[mt][nt][0], c[mt][nt][1]);
            *(float2*)&C[(size_t)(r0 + 8) * ldc + oc] = make_float2(c[mt][nt][2], c[mt][nt][3]);
        }
    }
}

// ----------------------------------------------------------------------------
// Per-head RMSNorm over D=128, in place. One warp per row, 4 floats per lane.
// ----------------------------------------------------------------------------
__global__ __launch_bounds__(256)
void rmsnorm128(float* __restrict__ data, const float* __restrict__ g)
{
    int row = blockIdx.x * 8 + (threadIdx.x >> 5);
    int lane = threadIdx.x & 31;
    float4* p = (float4*)(data + (size_t)row * 128) + lane;
    float4 v = *p;
    float ss = v.x * v.x + v.y * v.y + v.z * v.z + v.w * v.w;
#pragma unroll
    for (int o = 16; o; o >>= 1) ss += __shfl_xor_sync(0xffffffffu, ss, o);
    float r = rsqrtf(ss * (1.0f / 128.0f) + 1e-6f);
    float4 gv = ((const float4*)g)[lane];
    v.x *= r * gv.x; v.y *= r * gv.y; v.z *= r * gv.z; v.w *= r * gv.w;
    *p = v;
}

// ----------------------------------------------------------------------------
// Causal flash attention, fp32, warp-per-query, 4-key batching for ILP.
// ----------------------------------------------------------------------------
__global__ __launch_bounds__(256)
void attn_causal(const float* __restrict__ q, const float* __restrict__ k,
                 const float* __restrict__ v, float* __restrict__ o)
{
    __shared__ float Ks[32][128];
    __shared__ float Vs[32][128];

    const int bh = blockIdx.x;
    const int b = bh >> 4;
    const int h = bh & 15;
    const int warp = threadIdx.x >> 5;
    const int lane = threadIdx.x & 31;
    const int qi = blockIdx.y * 8 + warp;
    const int tok = b * SEQ + qi;
    const float scale = 0.08838834764831845f;   // 1/sqrt(128)

    float4 q4 = *(const float4*)(q + ((size_t)tok * NH + h) * HD + lane * 4);

    float m = -1e30f, l = 0.0f;
    float4 acc = make_float4(0.f, 0.f, 0.f, 0.f);

    const int kmax = blockIdx.y * 8 + 7;
    const int ntiles = (kmax >> 5) + 1;

    for (int t = 0; t < ntiles; ++t) {
        const int base_key = t * 32;
        for (int i = threadIdx.x; i < 1024; i += 256) {
            int kr = i >> 5;
            int kc = (i & 31) << 2;
            size_t off = ((size_t)(b * SEQ + base_key + kr) * NH + h) * HD + kc;
            *(float4*)&Ks[kr][kc] = *(const float4*)(k + off);
            *(float4*)&Vs[kr][kc] = *(const float4*)(v + off);
        }
        __syncthreads();

        int jcap = qi - base_key + 1;           // #valid keys in this tile
        if (jcap > 32) jcap = 32;
        for (int j0 = 0; j0 < jcap; j0 += 4) {
            float s[4];
#pragma unroll
            for (int i = 0; i < 4; ++i) {
                float4 k4 = *(float4*)&Ks[(j0 + i) & 31][lane * 4];
                s[i] = q4.x * k4.x + q4.y * k4.y + q4.z * k4.z + q4.w * k4.w;
            }
#pragma unroll
            for (int off = 16; off; off >>= 1) {
#pragma unroll
                for (int i = 0; i < 4; ++i)
                    s[i] += __shfl_xor_sync(0xffffffffu, s[i], off);
            }
#pragma unroll
            for (int i = 0; i < 4; ++i)
                s[i] = (j0 + i < jcap) ? s[i] * scale : -1e30f;

            float mt = fmaxf(fmaxf(s[0], s[1]), fmaxf(s[2], s[3]));
            mt = fmaxf(mt, m);
            float al = __expf(m - mt);
            float p0 = __expf(s[0] - mt);
            float p1 = __expf(s[1] - mt);
            float p2 = __expf(s[2] - mt);
            float p3 = __expf(s[3] - mt);
            m = mt;
            l = l * al + (p0 + p1) + (p2 + p3);

            float4 v0 = *(float4*)&Vs[(j0 + 0) & 31][lane * 4];
            float4 v1 = *(float4*)&Vs[(j0 + 1) & 31][lane * 4];
            float4 v2 = *(float4*)&Vs[(j0 + 2) & 31][lane * 4];
            float4 v3 = *(float4*)&Vs[(j0 + 3) & 31][lane * 4];
            acc.x = acc.x * al + p0 * v0.x + p1 * v1.x + p2 * v2.x + p3 * v3.x;
            acc.y = acc.y * al + p0 * v0.y + p1 * v1.y + p2 * v2.y + p3 * v3.y;
            acc.z = acc.z * al + p0 * v0.z + p1 * v1.z + p2 * v2.z + p3 * v3.z;
            acc.w = acc.w * al + p0 * v0.w + p1 * v1.w + p2 * v2.w + p3 * v3.w;
        }
        __syncthreads();
    }

    float inv = 1.0f / l;
    *(float4*)(o + ((size_t)tok * NH + h) * HD + lane * 4) =
        make_float4(acc.x * inv, acc.y * inv, acc.z * inv, acc.w * inv);
}

// ----------------------------------------------------------------------------
extern "C" void kernel_launch(void* const* d_in, const int* in_sizes, int n_in,
                              void* d_out, int out_size)
{
    const float* x   = (const float*)d_in[0];
    const float* Wq  = (const float*)d_in[1];
    const float* Wkv = (const float*)d_in[2];
    const float* Wkr = (const float*)d_in[3];
    const float* Wkn = (const float*)d_in[4];
    const float* Wv  = (const float*)d_in[5];
    const float* Wo  = (const float*)d_in[6];
    const float* gq  = (const float*)d_in[7];
    const float* gk  = (const float*)d_in[8];
    float* out = (float*)d_out;

    float *q, *k, *v, *lat, *attn;
    __half *hx, *hWq, *hWkv, *hWkr, *hWkn, *hWv, *hWo, *hlat, *hattn;
    cudaGetSymbolAddress((void**)&q,    g_q);
    cudaGetSymbolAddress((void**)&k,    g_k);
    cudaGetSymbolAddress((void**)&v,    g_v);
    cudaGetSymbolAddress((void**)&lat,  g_lat);
    cudaGetSymbolAddress((void**)&attn, g_attn);
    cudaGetSymbolAddress((void**)&hx,   h_x);
    cudaGetSymbolAddress((void**)&hWq,  h_Wq);
    cudaGetSymbolAddress((void**)&hWkv, h_Wkv);
    cudaGetSymbolAddress((void**)&hWkr, h_Wkr);
    cudaGetSymbolAddress((void**)&hWkn, h_Wkn);
    cudaGetSymbolAddress((void**)&hWv,  h_Wv);
    cudaGetSymbolAddress((void**)&hWo,  h_Wo);
    cudaGetSymbolAddress((void**)&hlat, h_lat);
    cudaGetSymbolAddress((void**)&hattn, h_attn);

    dim3 blk(256);

    // fp32 -> fp16 conversions (n/1024 blocks each)
    f2h<<<(TOKS * HIDN) / 1024, blk>>>(x, hx);
    f2h<<<(HIDN * 2048) / 1024, blk>>>(Wq, hWq);
    f2h<<<(HIDN * DLAT) / 1024, blk>>>(Wkv, hWkv);
    f2h<<<(DLAT * 1024) / 1024, blk>>>(Wkr, hWkr);
    f2h<<<(DLAT * 1024) / 1024, blk>>>(Wkn, hWkn);
    f2h<<<(DLAT * 2048) / 1024, blk>>>(Wv, hWv);
    f2h<<<(2048 * HIDN) / 1024, blk>>>(Wo, hWo);

    // q = x @ Wq
    hgemm128<<<dim3(16, 32), blk>>>(hx, hWq, q, TOKS, 2048, HIDN, 11, 2048, 0, 2048);
    // lat = x @ Wkv
    hgemm128<<<dim3(4, 32), blk>>>(hx, hWkv, lat, TOKS, DLAT, HIDN, 9, DLAT, 0, DLAT);
    f2h<<<(TOKS * DLAT) / 1024, blk>>>(lat, hlat);
    // kr -> k[..., h, 0:64]
    hgemm128<<<dim3(8, 32), blk>>>(hlat, hWkr, k, TOKS, 1024, DLAT, 6, 128, 0, 2048);
    // kn -> k[..., h, 64:128]
    hgemm128<<<dim3(8, 32), blk>>>(hlat, hWkn, k, TOKS, 1024, DLAT, 6, 128, 64, 2048);
    // v = lat @ Wv
    hgemm128<<<dim3(16, 32), blk>>>(hlat, hWv, v, TOKS, 2048, DLAT, 11, 2048, 0, 2048);

    rmsnorm128<<<TOKS * NH / 8, blk>>>(q, gq);
    rmsnorm128<<<TOKS * NH / 8, blk>>>(k, gk);

    attn_causal<<<dim3(NB * NH, SEQ / 8), blk>>>(q, k, v, attn);

    f2h<<<(TOKS * 2048) / 1024, blk>>>(attn, hattn);
    // out = attn @ Wo
    hgemm128<<<dim3(16, 32), blk>>>(hattn, hWo, out, TOKS, 2048, 2048, 11, 2048, 0, 2048);
}

// round 4
// speedup vs baseline: 8.2290x; 5.6118x over previous
#include <cuda_runtime.h>
#include <cuda_fp16.h>
#include <math.h>
#include <stdint.h>

// Problem constants
#define TOKS 4096      // B*S = 2*2048
#define SEQ  2048
#define NB   2
#define NH   16
#define HD   128
#define HIDN 2048
#define DLAT 512

// fp32 scratch (GEMM outputs pre-norm)
__device__ float g_q[TOKS * 2048];
__device__ float g_k[TOKS * 2048];
__device__ float g_v[TOKS * 2048];
__device__ float g_lat[TOKS * DLAT];

// fp16 scratch
__device__ __half h_x[TOKS * HIDN];
__device__ __half h_Wq[HIDN * 2048];
__device__ __half h_Wkv[HIDN * DLAT];
__device__ __half h_Wkr[DLAT * 1024];
__device__ __half h_Wkn[DLAT * 1024];
__device__ __half h_Wv[DLAT * 2048];
__device__ __half h_Wo[2048 * HIDN];
__device__ __half h_lat[TOKS * DLAT];
__device__ __half h_attn[TOKS * 2048];
__device__ __half h_q[TOKS * 2048];   // [b][h][s][d]
__device__ __half h_k[TOKS * 2048];   // [b][h][s][d]
__device__ __half h_v[TOKS * 2048];   // [b][h][s][d]

// ----------------------------------------------------------------------------
__global__ __launch_bounds__(256)
void f2h(const float* __restrict__ in, __half* __restrict__ out)
{
    int i = (blockIdx.x * 256 + threadIdx.x) * 4;
    float4 v = *(const float4*)(in + i);
    *(__half2*)(out + i)     = __floats2half2_rn(v.x, v.y);
    *(__half2*)(out + i + 2) = __floats2half2_rn(v.z, v.w);
}

// ----------------------------------------------------------------------------
// Tensor-core GEMM (as round 3): C fp32 = A fp16 @ B fp16, 128x128 tile.
// ----------------------------------------------------------------------------
#define AS_STRIDE 40
#define BS_STRIDE 136

__device__ __forceinline__ uint32_t sptr(const void* p)
{
    return (uint32_t)__cvta_generic_to_shared(p);
}
__device__ __forceinline__ void ldsm_x4(uint32_t* r, uint32_t addr)
{
    asm volatile("ldmatrix.sync.aligned.m8n8.x4.shared.b16 {%0,%1,%2,%3}, [%4];\n"
                 : "=r"(r[0]), "=r"(r[1]), "=r"(r[2]), "=r"(r[3]) : "r"(addr));
}
__device__ __forceinline__ void ldsm_x2t(uint32_t* r, uint32_t addr)
{
    asm volatile("ldmatrix.sync.aligned.m8n8.x2.trans.shared.b16 {%0,%1}, [%2];\n"
                 : "=r"(r[0]), "=r"(r[1]) : "r"(addr));
}
__device__ __forceinline__ void ldsm_x4t(uint32_t* r, uint32_t addr)
{
    asm volatile("ldmatrix.sync.aligned.m8n8.x4.trans.shared.b16 {%0,%1,%2,%3}, [%4];\n"
                 : "=r"(r[0]), "=r"(r[1]), "=r"(r[2]), "=r"(r[3]) : "r"(addr));
}
__device__ __forceinline__ void mma16816(float* c, const uint32_t* a, const uint32_t* b)
{
    asm volatile(
        "mma.sync.aligned.m16n8k16.row.col.f32.f16.f16.f32 "
        "{%0,%1,%2,%3}, {%4,%5,%6,%7}, {%8,%9}, {%0,%1,%2,%3};\n"
        : "+f"(c[0]), "+f"(c[1]), "+f"(c[2]), "+f"(c[3])
        : "r"(a[0]), "r"(a[1]), "r"(a[2]), "r"(a[3]), "r"(b[0]), "r"(b[1]));
}

__global__ __launch_bounds__(256)
void hgemm128(const __half* __restrict__ A, const __half* __restrict__ B,
              float* __restrict__ C, int M, int N, int K,
              int lgGroup, int outstride, int base, int ldc)
{
    __shared__ __half As[128 * AS_STRIDE];
    __shared__ __half Bs[32 * BS_STRIDE];

    const int tid  = threadIdx.x;
    const int warp = tid >> 5;
    const int lane = tid & 31;
    const int bm = blockIdx.y * 128;
    const int bn = blockIdx.x * 128;
    const int wm = (warp & 1) * 64;
    const int wn = (warp >> 1) * 32;

    float c[4][4][4];
#pragma unroll
    for (int mt = 0; mt < 4; ++mt)
#pragma unroll
        for (int nt = 0; nt < 4; ++nt)
#pragma unroll
            for (int i = 0; i < 4; ++i) c[mt][nt][i] = 0.0f;

    const uint32_t a_base = sptr(&As[(wm + (lane & 15)) * AS_STRIDE + (lane >> 4) * 8]);
    const uint32_t b_base = sptr(&Bs[(lane & 15) * BS_STRIDE + wn]);

    for (int k0 = 0; k0 < K; k0 += 32) {
#pragma unroll
        for (int i = 0; i < 2; ++i) {
            int cch = tid + i * 256;
            int row = cch >> 2;
            int kc = (cch & 3) * 8;
            *(uint4*)&As[row * AS_STRIDE + kc] =
                *(const uint4*)(A + (size_t)(bm + row) * K + k0 + kc);
        }
#pragma unroll
        for (int i = 0; i < 2; ++i) {
            int cch = tid + i * 256;
            int row = cch >> 4;
            int nc = (cch & 15) * 8;
            *(uint4*)&Bs[row * BS_STRIDE + nc] =
                *(const uint4*)(B + (size_t)(k0 + row) * N + bn + nc);
        }
        __syncthreads();

#pragma unroll
        for (int kt = 0; kt < 2; ++kt) {
            uint32_t a[4][4], b[4][2];
#pragma unroll
            for (int mt = 0; mt < 4; ++mt)
                ldsm_x4(a[mt], a_base + (mt * 16 * AS_STRIDE + kt * 16) * 2);
#pragma unroll
            for (int nt = 0; nt < 4; ++nt)
                ldsm_x2t(b[nt], b_base + (kt * 16 * BS_STRIDE + nt * 8) * 2);
#pragma unroll
            for (int mt = 0; mt < 4; ++mt)
#pragma unroll
                for (int nt = 0; nt < 4; ++nt)
                    mma16816(c[mt][nt], a[mt], b[nt]);
        }
        __syncthreads();
    }

    const int gmask = (1 << lgGroup) - 1;
    const int gid = lane >> 2;
    const int tig = lane & 3;
#pragma unroll
    for (int mt = 0; mt < 4; ++mt) {
#pragma unroll
        for (int nt = 0; nt < 4; ++nt) {
            int col = bn + wn + nt * 8 + tig * 2;
            int oc = ((col >> lgGroup) * outstride) + base + (col & gmask);
            int r0 = bm + wm + mt * 16 + gid;
            *(float2*)&C[(size_t)r0 * ldc + oc] = make_float2(c[mt][nt][0], c[mt][nt][1]);
            *(float2*)&C[(size_t)(r0 + 8) * ldc + oc] = make_float2(c[mt][nt][2], c[mt][nt][3]);
        }
    }
}

// ----------------------------------------------------------------------------
// RMSNorm over D=128 + fp16 repack [tok][h][d] -> [b][h][s][d].
// One warp per (tok,h) row.
// ----------------------------------------------------------------------------
__global__ __launch_bounds__(256)
void rmsnorm_h(const float* __restrict__ in, const float* __restrict__ g,
               __half* __restrict__ out)
{
    int row = blockIdx.x * 8 + (threadIdx.x >> 5);   // row = tok*16 + h
    int lane = threadIdx.x & 31;
    float4 v = *((const float4*)(in + (size_t)row * 128) + lane);
    float ss = v.x * v.x + v.y * v.y + v.z * v.z + v.w * v.w;
#pragma unroll
    for (int o = 16; o; o >>= 1) ss += __shfl_xor_sync(0xffffffffu, ss, o);
    float r = rsqrtf(ss * (1.0f / 128.0f) + 1e-6f);
    float4 gv = ((const float4*)g)[lane];
    int tok = row >> 4, h = row & 15;
    int b = tok >> 11, s = tok & 2047;
    __half* dst = out + ((size_t)(b * 16 + h) * 2048 + s) * 128 + lane * 4;
    *(__half2*)dst       = __floats2half2_rn(v.x * r * gv.x, v.y * r * gv.y);
    *(__half2*)(dst + 2) = __floats2half2_rn(v.z * r * gv.z, v.w * r * gv.w);
}

// fp32 [tok][h][d] -> fp16 [b][h][s][d] (no norm), for V.
__global__ __launch_bounds__(256)
void pack_h(const float* __restrict__ in, __half* __restrict__ out)
{
    int row = blockIdx.x * 8 + (threadIdx.x >> 5);
    int lane = threadIdx.x & 31;
    float4 v = *((const float4*)(in + (size_t)row * 128) + lane);
    int tok = row >> 4, h = row & 15;
    int b = tok >> 11, s = tok & 2047;
    __half* dst = out + ((size_t)(b * 16 + h) * 2048 + s) * 128 + lane * 4;
    *(__half2*)dst       = __floats2half2_rn(v.x, v.y);
    *(__half2*)(dst + 2) = __floats2half2_rn(v.z, v.w);
}

// ----------------------------------------------------------------------------
// Tensor-core causal flash attention.
// Grid: (S/64, B*H). 128 threads = 4 warps; warp w owns query rows
// qb + w*16 .. +15 of head bh. Q a-frags in regs; K/V 64x128 fp16 smem tiles.
// Output written fp16 to h_attn[tok][h*128+d].
// ----------------------------------------------------------------------------
#define KS_STRIDE 136   // halves; 272B rows, 16B aligned, conflict-free

__global__ __launch_bounds__(128)
void attn_mma(const __half* __restrict__ q, const __half* __restrict__ k,
              const __half* __restrict__ v, __half* __restrict__ o)
{
    __shared__ __half Ks[64 * KS_STRIDE];
    __shared__ __half Vs[64 * KS_STRIDE];

    const int bh = blockIdx.y;
    const int b = bh >> 4, h = bh & 15;
    const int qb = blockIdx.x * 64;
    const int tid = threadIdx.x;
    const int warp = tid >> 5, lane = tid & 31;
    const size_t base = (size_t)bh * SEQ * HD;
    const int r0 = warp * 16 + (lane >> 2);   // first local q-row of this lane
    const int c2 = (lane & 3) * 2;
    const float sc = 0.08838834764831845f;    // 1/sqrt(128)

    // Q a-frags: aq[kc][0..3] for k-chunk kc (16 d-values each)
    uint32_t aq[8][4];
    {
        const __half* q0 = q + base + (size_t)(qb + r0) * HD;
#pragma unroll
        for (int kc = 0; kc < 8; ++kc) {
            aq[kc][0] = *(const uint32_t*)(q0 + kc * 16 + c2);
            aq[kc][1] = *(const uint32_t*)(q0 + 8 * HD + kc * 16 + c2);
            aq[kc][2] = *(const uint32_t*)(q0 + kc * 16 + c2 + 8);
            aq[kc][3] = *(const uint32_t*)(q0 + 8 * HD + kc * 16 + c2 + 8);
        }
    }

    float oa[16][4];
#pragma unroll
    for (int nt = 0; nt < 16; ++nt)
#pragma unroll
        for (int i = 0; i < 4; ++i) oa[nt][i] = 0.0f;
    float m0 = -1e30f, m1 = -1e30f, l0 = 0.0f, l1 = 0.0f;

    // ldmatrix lane base addresses
    const uint32_t kaddr = sptr(&Ks[(lane & 7) * KS_STRIDE + (lane >> 3) * 8]);
    const uint32_t vaddr = sptr(&Vs[(lane & 15) * KS_STRIDE + (lane >> 4) * 8]);

    const int ntiles = qb / 64 + 1;
    for (int t = 0; t < ntiles; ++t) {
        const int j0 = t * 64;
        const __half* kg = k + base + (size_t)j0 * HD;
        const __half* vg = v + base + (size_t)j0 * HD;
        __syncthreads();
#pragma unroll
        for (int i = tid; i < 1024; i += 128) {
            int row = i >> 4, col8 = (i & 15) * 8;
            *(uint4*)&Ks[row * KS_STRIDE + col8] = *(const uint4*)(kg + row * HD + col8);
            *(uint4*)&Vs[row * KS_STRIDE + col8] = *(const uint4*)(vg + row * HD + col8);
        }
        __syncthreads();

        // S = Q K^T : s[nt] is m16n8 fp32 frag for keys j0+nt*8..+7
        float s[8][4];
#pragma unroll
        for (int nt = 0; nt < 8; ++nt) {
            s[nt][0] = s[nt][1] = s[nt][2] = s[nt][3] = 0.0f;
            uint32_t bk[4][4];
#pragma unroll
            for (int g = 0; g < 4; ++g)
                ldsm_x4(bk[g], kaddr + (nt * 8 * KS_STRIDE + g * 32) * 2);
#pragma unroll
            for (int kc = 0; kc < 8; ++kc)
                mma16816(s[nt], aq[kc], &bk[kc >> 1][(kc & 1) * 2]);
        }

        // scale + causal mask (only diagonal tile needs masking)
        if (j0 == qb) {
#pragma unroll
            for (int nt = 0; nt < 8; ++nt) {
#pragma unroll
                for (int i = 0; i < 4; ++i) {
                    int col = j0 + nt * 8 + c2 + (i & 1);
                    int rowq = qb + r0 + (i >> 1) * 8;
                    s[nt][i] = (col > rowq) ? -1e30f : s[nt][i] * sc;
                }
            }
        } else {
#pragma unroll
            for (int nt = 0; nt < 8; ++nt)
#pragma unroll
                for (int i = 0; i < 4; ++i) s[nt][i] *= sc;
        }

        // online softmax (rows r0 and r0+8; 4 lanes per row)
        float tm0 = -1e30f, tm1 = -1e30f;
#pragma unroll
        for (int nt = 0; nt < 8; ++nt) {
            tm0 = fmaxf(tm0, fmaxf(s[nt][0], s[nt][1]));
            tm1 = fmaxf(tm1, fmaxf(s[nt][2], s[nt][3]));
        }
        tm0 = fmaxf(tm0, __shfl_xor_sync(0xffffffffu, tm0, 1));
        tm0 = fmaxf(tm0, __shfl_xor_sync(0xffffffffu, tm0, 2));
        tm1 = fmaxf(tm1, __shfl_xor_sync(0xffffffffu, tm1, 1));
        tm1 = fmaxf(tm1, __shfl_xor_sync(0xffffffffu, tm1, 2));
        float mn0 = fmaxf(m0, tm0), mn1 = fmaxf(m1, tm1);
        float al0 = __expf(m0 - mn0), al1 = __expf(m1 - mn1);
        m0 = mn0; m1 = mn1;

        float rs0 = 0.0f, rs1 = 0.0f;
#pragma unroll
        for (int nt = 0; nt < 8; ++nt) {
            s[nt][0] = __expf(s[nt][0] - mn0);
            s[nt][1] = __expf(s[nt][1] - mn0);
            s[nt][2] = __expf(s[nt][2] - mn1);
            s[nt][3] = __expf(s[nt][3] - mn1);
            rs0 += s[nt][0] + s[nt][1];
            rs1 += s[nt][2] + s[nt][3];
        }
        rs0 += __shfl_xor_sync(0xffffffffu, rs0, 1);
        rs0 += __shfl_xor_sync(0xffffffffu, rs0, 2);
        rs1 += __shfl_xor_sync(0xffffffffu, rs1, 1);
        rs1 += __shfl_xor_sync(0xffffffffu, rs1, 2);
        l0 = l0 * al0 + rs0;
        l1 = l1 * al1 + rs1;

        // rescale O accumulators
#pragma unroll
        for (int nt = 0; nt < 16; ++nt) {
            oa[nt][0] *= al0; oa[nt][1] *= al0;
            oa[nt][2] *= al1; oa[nt][3] *= al1;
        }

        // pack P to fp16 a-frags: ap[kc] covers keys kc*16..+15
        uint32_t ap[4][4];
#pragma unroll
        for (int kc = 0; kc < 4; ++kc) {
            __half2 t0 = __floats2half2_rn(s[2 * kc][0], s[2 * kc][1]);
            __half2 t1 = __floats2half2_rn(s[2 * kc][2], s[2 * kc][3]);
            __half2 t2 = __floats2half2_rn(s[2 * kc + 1][0], s[2 * kc + 1][1]);
            __half2 t3 = __floats2half2_rn(s[2 * kc + 1][2], s[2 * kc + 1][3]);
            ap[kc][0] = *(uint32_t*)&t0;
            ap[kc][1] = *(uint32_t*)&t1;
            ap[kc][2] = *(uint32_t*)&t2;
            ap[kc][3] = *(uint32_t*)&t3;
        }

        // O += P V
#pragma unroll
        for (int kc = 0; kc < 4; ++kc) {
#pragma unroll
            for (int ntp = 0; ntp < 8; ++ntp) {
                uint32_t bv[4];
                ldsm_x4t(bv, vaddr + (kc * 16 * KS_STRIDE + ntp * 16) * 2);
                mma16816(oa[ntp * 2], ap[kc], &bv[0]);
                mma16816(oa[ntp * 2 + 1], ap[kc], &bv[2]);
            }
        }
    }

    // epilogue: O / l, write fp16 to [tok][h*128+d]
    float inv0 = 1.0f / l0, inv1 = 1.0f / l1;
    size_t tok0 = (size_t)b * SEQ + qb + r0;
    __half* d0 = o + tok0 * 2048 + h * 128 + c2;
    __half* d1 = d0 + (size_t)8 * 2048;
#pragma unroll
    for (int nt = 0; nt < 16; ++nt) {
        *(__half2*)(d0 + nt * 8) = __floats2half2_rn(oa[nt][0] * inv0, oa[nt][1] * inv0);
        *(__half2*)(d1 + nt * 8) = __floats2half2_rn(oa[nt][2] * inv1, oa[nt][3] * inv1);
    }
}

// ----------------------------------------------------------------------------
extern "C" void kernel_launch(void* const* d_in, const int* in_sizes, int n_in,
                              void* d_out, int out_size)
{
    const float* x   = (const float*)d_in[0];
    const float* Wq  = (const float*)d_in[1];
    const float* Wkv = (const float*)d_in[2];
    const float* Wkr = (const float*)d_in[3];
    const float* Wkn = (const float*)d_in[4];
    const float* Wv  = (const float*)d_in[5];
    const float* Wo  = (const float*)d_in[6];
    const float* gq  = (const float*)d_in[7];
    const float* gk  = (const float*)d_in[8];
    float* out = (float*)d_out;

    float *q, *k, *v, *lat;
    __half *hx, *hWq, *hWkv, *hWkr, *hWkn, *hWv, *hWo, *hlat, *hattn, *hq, *hk, *hv;
    cudaGetSymbolAddress((void**)&q,    g_q);
    cudaGetSymbolAddress((void**)&k,    g_k);
    cudaGetSymbolAddress((void**)&v,    g_v);
    cudaGetSymbolAddress((void**)&lat,  g_lat);
    cudaGetSymbolAddress((void**)&hx,   h_x);
    cudaGetSymbolAddress((void**)&hWq,  h_Wq);
    cudaGetSymbolAddress((void**)&hWkv, h_Wkv);
    cudaGetSymbolAddress((void**)&hWkr, h_Wkr);
    cudaGetSymbolAddress((void**)&hWkn, h_Wkn);
    cudaGetSymbolAddress((void**)&hWv,  h_Wv);
    cudaGetSymbolAddress((void**)&hWo,  h_Wo);
    cudaGetSymbolAddress((void**)&hlat, h_lat);
    cudaGetSymbolAddress((void**)&hattn, h_attn);
    cudaGetSymbolAddress((void**)&hq,   h_q);
    cudaGetSymbolAddress((void**)&hk,   h_k);
    cudaGetSymbolAddress((void**)&hv,   h_v);

    dim3 blk(256);

    f2h<<<(TOKS * HIDN) / 1024, blk>>>(x, hx);
    f2h<<<(HIDN * 2048) / 1024, blk>>>(Wq, hWq);
    f2h<<<(HIDN * DLAT) / 1024, blk>>>(Wkv, hWkv);
    f2h<<<(DLAT * 1024) / 1024, blk>>>(Wkr, hWkr);
    f2h<<<(DLAT * 1024) / 1024, blk>>>(Wkn, hWkn);
    f2h<<<(DLAT * 2048) / 1024, blk>>>(Wv, hWv);
    f2h<<<(2048 * HIDN) / 1024, blk>>>(Wo, hWo);

    // projections (fp32 outputs, k head-interleaved)
    hgemm128<<<dim3(16, 32), blk>>>(hx, hWq, q, TOKS, 2048, HIDN, 11, 2048, 0, 2048);
    hgemm128<<<dim3(4, 32), blk>>>(hx, hWkv, lat, TOKS, DLAT, HIDN, 9, DLAT, 0, DLAT);
    f2h<<<(TOKS * DLAT) / 1024, blk>>>(lat, hlat);
    hgemm128<<<dim3(8, 32), blk>>>(hlat, hWkr, k, TOKS, 1024, DLAT, 6, 128, 0, 2048);
    hgemm128<<<dim3(8, 32), blk>>>(hlat, hWkn, k, TOKS, 1024, DLAT, 6, 128, 64, 2048);
    hgemm128<<<dim3(16, 32), blk>>>(hlat, hWv, v, TOKS, 2048, DLAT, 11, 2048, 0, 2048);

    // norm + repack to fp16 [b][h][s][d]
    rmsnorm_h<<<TOKS * NH / 8, blk>>>(q, gq, hq);
    rmsnorm_h<<<TOKS * NH / 8, blk>>>(k, gk, hk);
    pack_h<<<TOKS * NH / 8, blk>>>(v, hv);

    // tensor-core causal attention -> h_attn [tok][2048] fp16
    attn_mma<<<dim3(SEQ / 64, NB * NH), dim3(128)>>>(hq, hk, hv, hattn);

    // out = attn @ Wo
    hgemm128<<<dim3(16, 32), blk>>>(hattn, hWo, out, TOKS, 2048, 2048, 11, 2048, 0, 2048);
}

// round 5
// speedup vs baseline: 9.0082x; 1.0947x over previous
#include <cuda_runtime.h>
#include <cuda_fp16.h>
#include <math.h>
#include <stdint.h>

// Problem constants
#define TOKS 4096      // B*S = 2*2048
#define SEQ  2048
#define NB   2
#define NH   16
#define HD   128
#define HIDN 2048
#define DLAT 512

// fp32 scratch (GEMM outputs pre-norm)
__device__ float g_q[TOKS * 2048];
__device__ float g_k[TOKS * 2048];
__device__ float g_v[TOKS * 2048];
__device__ float g_lat[TOKS * DLAT];

// fp16 scratch
__device__ __half h_x[TOKS * HIDN];
__device__ __half h_Wq[HIDN * 2048];
__device__ __half h_Wkv[HIDN * DLAT];
__device__ __half h_Wkr[DLAT * 1024];
__device__ __half h_Wkn[DLAT * 1024];
__device__ __half h_Wv[DLAT * 2048];
__device__ __half h_Wo[2048 * HIDN];
__device__ __half h_lat[TOKS * DLAT];
__device__ __half h_attn[TOKS * 2048];
__device__ __half h_q[TOKS * 2048];   // [b][h][s][d]
__device__ __half h_k[TOKS * 2048];   // [b][h][s][d]
__device__ __half h_v[TOKS * 2048];   // [b][h][s][d]

// ----------------------------------------------------------------------------
__global__ __launch_bounds__(256)
void f2h(const float* __restrict__ in, __half* __restrict__ out)
{
    int i = (blockIdx.x * 256 + threadIdx.x) * 4;
    float4 v = *(const float4*)(in + i);
    *(__half2*)(out + i)     = __floats2half2_rn(v.x, v.y);
    *(__half2*)(out + i + 2) = __floats2half2_rn(v.z, v.w);
}

// ----------------------------------------------------------------------------
#define AS_STRIDE 40    // halves
#define BS_STRIDE 136   // halves

__device__ __forceinline__ uint32_t sptr(const void* p)
{
    return (uint32_t)__cvta_generic_to_shared(p);
}
__device__ __forceinline__ void ldsm_x4(uint32_t* r, uint32_t addr)
{
    asm volatile("ldmatrix.sync.aligned.m8n8.x4.shared.b16 {%0,%1,%2,%3}, [%4];\n"
                 : "=r"(r[0]), "=r"(r[1]), "=r"(r[2]), "=r"(r[3]) : "r"(addr));
}
__device__ __forceinline__ void ldsm_x2t(uint32_t* r, uint32_t addr)
{
    asm volatile("ldmatrix.sync.aligned.m8n8.x2.trans.shared.b16 {%0,%1}, [%2];\n"
                 : "=r"(r[0]), "=r"(r[1]) : "r"(addr));
}
__device__ __forceinline__ void ldsm_x4t(uint32_t* r, uint32_t addr)
{
    asm volatile("ldmatrix.sync.aligned.m8n8.x4.trans.shared.b16 {%0,%1,%2,%3}, [%4];\n"
                 : "=r"(r[0]), "=r"(r[1]), "=r"(r[2]), "=r"(r[3]) : "r"(addr));
}
__device__ __forceinline__ void mma16816(float* c, const uint32_t* a, const uint32_t* b)
{
    asm volatile(
        "mma.sync.aligned.m16n8k16.row.col.f32.f16.f16.f32 "
        "{%0,%1,%2,%3}, {%4,%5,%6,%7}, {%8,%9}, {%0,%1,%2,%3};\n"
        : "+f"(c[0]), "+f"(c[1]), "+f"(c[2]), "+f"(c[3])
        : "r"(a[0]), "r"(a[1]), "r"(a[2]), "r"(a[3]), "r"(b[0]), "r"(b[1]));
}
__device__ __forceinline__ void cp16(uint32_t saddr, const void* g)
{
    asm volatile("cp.async.cg.shared.global [%0], [%1], 16;\n" :: "r"(saddr), "l"(g));
}
__device__ __forceinline__ void cp_commit()
{
    asm volatile("cp.async.commit_group;\n");
}
template <int N>
__device__ __forceinline__ void cp_wait()
{
    asm volatile("cp.async.wait_group %0;\n" :: "n"(N));
}

// ----------------------------------------------------------------------------
// Tensor-core GEMM: C fp32 = A fp16 @ B fp16, 128x128 block tile, BK=32,
// cp.async 2-stage double buffering. 8 warps (2Mx4N), warp tile 64x32.
// Epilogue column remap: out_col = (col>>lgGroup)*outstride + base + (col&mask)
// ----------------------------------------------------------------------------
__global__ __launch_bounds__(256)
void hgemm128(const __half* __restrict__ A, const __half* __restrict__ B,
              float* __restrict__ C, int M, int N, int K,
              int lgGroup, int outstride, int base, int ldc)
{
    __shared__ __half As[2][128 * AS_STRIDE];
    __shared__ __half Bs[2][32 * BS_STRIDE];

    const int tid  = threadIdx.x;
    const int warp = tid >> 5;
    const int lane = tid & 31;
    const int bm = blockIdx.y * 128;
    const int bn = blockIdx.x * 128;
    const int wm = (warp & 1) * 64;
    const int wn = (warp >> 1) * 32;

    float c[4][4][4];
#pragma unroll
    for (int mt = 0; mt < 4; ++mt)
#pragma unroll
        for (int nt = 0; nt < 4; ++nt)
#pragma unroll
            for (int i = 0; i < 4; ++i) c[mt][nt][i] = 0.0f;

    // per-thread load coords
    const int arow0 = tid >> 2,  akc = (tid & 3) * 8;       // +64 rows for chunk 2
    const int brow0 = tid >> 4,  bnc = (tid & 15) * 8;      // +16 rows for chunk 2

    const uint32_t a_base = sptr(&As[0][(wm + (lane & 15)) * AS_STRIDE + (lane >> 4) * 8]);
    const uint32_t b_base = sptr(&Bs[0][(lane & 15) * BS_STRIDE + wn]);
    const uint32_t a_st = 128 * AS_STRIDE * 2;   // bytes per stage
    const uint32_t b_st = 32 * BS_STRIDE * 2;

    const int nk = K >> 5;

    // prefetch stage 0
    {
        cp16(sptr(&As[0][arow0 * AS_STRIDE + akc]), A + (size_t)(bm + arow0) * K + akc);
        cp16(sptr(&As[0][(arow0 + 64) * AS_STRIDE + akc]), A + (size_t)(bm + arow0 + 64) * K + akc);
        cp16(sptr(&Bs[0][brow0 * BS_STRIDE + bnc]), B + (size_t)brow0 * N + bn + bnc);
        cp16(sptr(&Bs[0][(brow0 + 16) * BS_STRIDE + bnc]), B + (size_t)(brow0 + 16) * N + bn + bnc);
        cp_commit();
    }

    for (int t = 0; t < nk; ++t) {
        if (t + 1 < nk) {
            const int st = (t + 1) & 1;
            const int k0 = (t + 1) << 5;
            cp16(sptr(&As[st][arow0 * AS_STRIDE + akc]), A + (size_t)(bm + arow0) * K + k0 + akc);
            cp16(sptr(&As[st][(arow0 + 64) * AS_STRIDE + akc]), A + (size_t)(bm + arow0 + 64) * K + k0 + akc);
            cp16(sptr(&Bs[st][brow0 * BS_STRIDE + bnc]), B + (size_t)(k0 + brow0) * N + bn + bnc);
            cp16(sptr(&Bs[st][(brow0 + 16) * BS_STRIDE + bnc]), B + (size_t)(k0 + brow0 + 16) * N + bn + bnc);
            cp_commit();
            cp_wait<1>();
        } else {
            cp_wait<0>();
        }
        __syncthreads();

        const uint32_t ab = a_base + (t & 1) * a_st;
        const uint32_t bb = b_base + (t & 1) * b_st;
#pragma unroll
        for (int kt = 0; kt < 2; ++kt) {
            uint32_t a[4][4], b[4][2];
#pragma unroll
            for (int mt = 0; mt < 4; ++mt)
                ldsm_x4(a[mt], ab + (mt * 16 * AS_STRIDE + kt * 16) * 2);
#pragma unroll
            for (int nt = 0; nt < 4; ++nt)
                ldsm_x2t(b[nt], bb + (kt * 16 * BS_STRIDE + nt * 8) * 2);
#pragma unroll
            for (int mt = 0; mt < 4; ++mt)
#pragma unroll
                for (int nt = 0; nt < 4; ++nt)
                    mma16816(c[mt][nt], a[mt], b[nt]);
        }
        __syncthreads();
    }

    const int gmask = (1 << lgGroup) - 1;
    const int gid = lane >> 2;
    const int tig = lane & 3;
#pragma unroll
    for (int mt = 0; mt < 4; ++mt) {
#pragma unroll
        for (int nt = 0; nt < 4; ++nt) {
            int col = bn + wn + nt * 8 + tig * 2;
            int oc = ((col >> lgGroup) * outstride) + base + (col & gmask);
            int r0 = bm + wm + mt * 16 + gid;
            *(float2*)&C[(size_t)r0 * ldc + oc] = make_float2(c[mt][nt][0], c[mt][nt][1]);
            *(float2*)&C[(size_t)(r0 + 8) * ldc + oc] = make_float2(c[mt][nt][2], c[mt][nt][3]);
        }
    }
}

// ----------------------------------------------------------------------------
// RMSNorm over D=128 (+ extra output scale) + fp16 repack -> [b][h][s][d].
// ----------------------------------------------------------------------------
__global__ __launch_bounds__(256)
void rmsnorm_h(const float* __restrict__ in, const float* __restrict__ g,
               __half* __restrict__ out, float pscale)
{
    int row = blockIdx.x * 8 + (threadIdx.x >> 5);   // row = tok*16 + h
    int lane = threadIdx.x & 31;
    float4 v = *((const float4*)(in + (size_t)row * 128) + lane);
    float ss = v.x * v.x + v.y * v.y + v.z * v.z + v.w * v.w;
#pragma unroll
    for (int o = 16; o; o >>= 1) ss += __shfl_xor_sync(0xffffffffu, ss, o);
    float r = rsqrtf(ss * (1.0f / 128.0f) + 1e-6f) * pscale;
    float4 gv = ((const float4*)g)[lane];
    int tok = row >> 4, h = row & 15;
    int b = tok >> 11, s = tok & 2047;
    __half* dst = out + ((size_t)(b * 16 + h) * 2048 + s) * 128 + lane * 4;
    *(__half2*)dst       = __floats2half2_rn(v.x * r * gv.x, v.y * r * gv.y);
    *(__half2*)(dst + 2) = __floats2half2_rn(v.z * r * gv.z, v.w * r * gv.w);
}

// fp32 [tok][h][d] -> fp16 [b][h][s][d] (no norm), for V.
__global__ __launch_bounds__(256)
void pack_h(const float* __restrict__ in, __half* __restrict__ out)
{
    int row = blockIdx.x * 8 + (threadIdx.x >> 5);
    int lane = threadIdx.x & 31;
    float4 v = *((const float4*)(in + (size_t)row * 128) + lane);
    int tok = row >> 4, h = row & 15;
    int b = tok >> 11, s = tok & 2047;
    __half* dst = out + ((size_t)(b * 16 + h) * 2048 + s) * 128 + lane * 4;
    *(__half2*)dst       = __floats2half2_rn(v.x, v.y);
    *(__half2*)(dst + 2) = __floats2half2_rn(v.z, v.w);
}

// ----------------------------------------------------------------------------
// Tensor-core causal flash attention. Grid: (S/128, B*H), 256 threads = 8
// warps; warp w owns query rows qb + w*16 .. +15. Q is pre-scaled by 1/sqrt(D)
// (folded into rmsnorm). K/V in 64x128 fp16 smem tiles.
// ----------------------------------------------------------------------------
#define KS_STRIDE 136

__global__ __launch_bounds__(256)
void attn_mma(const __half* __restrict__ q, const __half* __restrict__ k,
              const __half* __restrict__ v, __half* __restrict__ o)
{
    __shared__ __half Ks[64 * KS_STRIDE];
    __shared__ __half Vs[64 * KS_STRIDE];

    const int bh = blockIdx.y;
    const int b = bh >> 4, h = bh & 15;
    const int qb = blockIdx.x * 128;
    const int tid = threadIdx.x;
    const int warp = tid >> 5, lane = tid & 31;
    const size_t base = (size_t)bh * SEQ * HD;
    const int r0 = warp * 16 + (lane >> 2);   // first local q-row of this lane
    const int w0 = qb + warp * 16;            // warp's first global q-row
    const int c2 = (lane & 3) * 2;

    // Q a-frags
    uint32_t aq[8][4];
    {
        const __half* q0 = q + base + (size_t)(qb + r0) * HD;
#pragma unroll
        for (int kc = 0; kc < 8; ++kc) {
            aq[kc][0] = *(const uint32_t*)(q0 + kc * 16 + c2);
            aq[kc][1] = *(const uint32_t*)(q0 + 8 * HD + kc * 16 + c2);
            aq[kc][2] = *(const uint32_t*)(q0 + kc * 16 + c2 + 8);
            aq[kc][3] = *(const uint32_t*)(q0 + 8 * HD + kc * 16 + c2 + 8);
        }
    }

    float oa[16][4];
#pragma unroll
    for (int nt = 0; nt < 16; ++nt)
#pragma unroll
        for (int i = 0; i < 4; ++i) oa[nt][i] = 0.0f;
    float m0 = -1e30f, m1 = -1e30f, l0 = 0.0f, l1 = 0.0f;

    const uint32_t kaddr = sptr(&Ks[(lane & 7) * KS_STRIDE + (lane >> 3) * 8]);
    const uint32_t vaddr = sptr(&Vs[(lane & 15) * KS_STRIDE + (lane >> 4) * 8]);

    const int ntiles = qb / 64 + 2;
    for (int t = 0; t < ntiles; ++t) {
        const int j0 = t * 64;
        const __half* kg = k + base + (size_t)j0 * HD;
        const __half* vg = v + base + (size_t)j0 * HD;
#pragma unroll
        for (int i = tid; i < 1024; i += 256) {
            int row = i >> 4, col8 = (i & 15) * 8;
            *(uint4*)&Ks[row * KS_STRIDE + col8] = *(const uint4*)(kg + row * HD + col8);
            *(uint4*)&Vs[row * KS_STRIDE + col8] = *(const uint4*)(vg + row * HD + col8);
        }
        __syncthreads();

        if (j0 <= w0 + 15) {      // tile not entirely above this warp's rows
            // S = Q K^T
            float s[8][4];
#pragma unroll
            for (int nt = 0; nt < 8; ++nt) {
                s[nt][0] = s[nt][1] = s[nt][2] = s[nt][3] = 0.0f;
                uint32_t bk[4][4];
#pragma unroll
                for (int g = 0; g < 4; ++g)
                    ldsm_x4(bk[g], kaddr + (nt * 8 * KS_STRIDE + g * 32) * 2);
#pragma unroll
                for (int kc = 0; kc < 8; ++kc)
                    mma16816(s[nt], aq[kc], &bk[kc >> 1][(kc & 1) * 2]);
            }

            // causal mask (only the warp's diagonal tile)
            if (j0 + 63 > w0) {
#pragma unroll
                for (int nt = 0; nt < 8; ++nt) {
#pragma unroll
                    for (int i = 0; i < 4; ++i) {
                        int col = j0 + nt * 8 + c2 + (i & 1);
                        int rowq = qb + r0 + (i >> 1) * 8;
                        if (col > rowq) s[nt][i] = -1e30f;
                    }
                }
            }

            // online softmax
            float tm0 = -1e30f, tm1 = -1e30f;
#pragma unroll
            for (int nt = 0; nt < 8; ++nt) {
                tm0 = fmaxf(tm0, fmaxf(s[nt][0], s[nt][1]));
                tm1 = fmaxf(tm1, fmaxf(s[nt][2], s[nt][3]));
            }
            tm0 = fmaxf(tm0, __shfl_xor_sync(0xffffffffu, tm0, 1));
            tm0 = fmaxf(tm0, __shfl_xor_sync(0xffffffffu, tm0, 2));
            tm1 = fmaxf(tm1, __shfl_xor_sync(0xffffffffu, tm1, 1));
            tm1 = fmaxf(tm1, __shfl_xor_sync(0xffffffffu, tm1, 2));
            float mn0 = fmaxf(m0, tm0), mn1 = fmaxf(m1, tm1);
            float al0 = __expf(m0 - mn0), al1 = __expf(m1 - mn1);
            m0 = mn0; m1 = mn1;

            float rs0 = 0.0f, rs1 = 0.0f;
#pragma unroll
            for (int nt = 0; nt < 8; ++nt) {
                s[nt][0] = __expf(s[nt][0] - mn0);
                s[nt][1] = __expf(s[nt][1] - mn0);
                s[nt][2] = __expf(s[nt][2] - mn1);
                s[nt][3] = __expf(s[nt][3] - mn1);
                rs0 += s[nt][0] + s[nt][1];
                rs1 += s[nt][2] + s[nt][3];
            }
            rs0 += __shfl_xor_sync(0xffffffffu, rs0, 1);
            rs0 += __shfl_xor_sync(0xffffffffu, rs0, 2);
            rs1 += __shfl_xor_sync(0xffffffffu, rs1, 1);
            rs1 += __shfl_xor_sync(0xffffffffu, rs1, 2);
            l0 = l0 * al0 + rs0;
            l1 = l1 * al1 + rs1;

#pragma unroll
            for (int nt = 0; nt < 16; ++nt) {
                oa[nt][0] *= al0; oa[nt][1] *= al0;
                oa[nt][2] *= al1; oa[nt][3] *= al1;
            }

            // pack P -> fp16 a-frags
            uint32_t ap[4][4];
#pragma unroll
            for (int kc = 0; kc < 4; ++kc) {
                __half2 t0 = __floats2half2_rn(s[2 * kc][0], s[2 * kc][1]);
                __half2 t1 = __floats2half2_rn(s[2 * kc][2], s[2 * kc][3]);
                __half2 t2 = __floats2half2_rn(s[2 * kc + 1][0], s[2 * kc + 1][1]);
                __half2 t3 = __floats2half2_rn(s[2 * kc + 1][2], s[2 * kc + 1][3]);
                ap[kc][0] = *(uint32_t*)&t0;
                ap[kc][1] = *(uint32_t*)&t1;
                ap[kc][2] = *(uint32_t*)&t2;
                ap[kc][3] = *(uint32_t*)&t3;
            }

            // O += P V
#pragma unroll
            for (int kc = 0; kc < 4; ++kc) {
#pragma unroll
                for (int ntp = 0; ntp < 8; ++ntp) {
                    uint32_t bv[4];
                    ldsm_x4t(bv, vaddr + (kc * 16 * KS_STRIDE + ntp * 16) * 2);
                    mma16816(oa[ntp * 2], ap[kc], &bv[0]);
                    mma16816(oa[ntp * 2 + 1], ap[kc], &bv[2]);
                }
            }
        }
        __syncthreads();
    }

    // epilogue
    float inv0 = 1.0f / l0, inv1 = 1.0f / l1;
    size_t tok0 = (size_t)b * SEQ + qb + r0;
    __half* d0 = o + tok0 * 2048 + h * 128 + c2;
    __half* d1 = d0 + (size_t)8 * 2048;
#pragma unroll
    for (int nt = 0; nt < 16; ++nt) {
        *(__half2*)(d0 + nt * 8) = __floats2half2_rn(oa[nt][0] * inv0, oa[nt][1] * inv0);
        *(__half2*)(d1 + nt * 8) = __floats2half2_rn(oa[nt][2] * inv1, oa[nt][3] * inv1);
    }
}

// ----------------------------------------------------------------------------
extern "C" void kernel_launch(void* const* d_in, const int* in_sizes, int n_in,
                              void* d_out, int out_size)
{
    const float* x   = (const float*)d_in[0];
    const float* Wq  = (const float*)d_in[1];
    const float* Wkv = (const float*)d_in[2];
    const float* Wkr = (const float*)d_in[3];
    const float* Wkn = (const float*)d_in[4];
    const float* Wv  = (const float*)d_in[5];
    const float* Wo  = (const float*)d_in[6];
    const float* gq  = (const float*)d_in[7];
    const float* gk  = (const float*)d_in[8];
    float* out = (float*)d_out;

    float *q, *k, *v, *lat;
    __half *hx, *hWq, *hWkv, *hWkr, *hWkn, *hWv, *hWo, *hlat, *hattn, *hq, *hk, *hv;
    cudaGetSymbolAddress((void**)&q,    g_q);
    cudaGetSymbolAddress((void**)&k,    g_k);
    cudaGetSymbolAddress((void**)&v,    g_v);
    cudaGetSymbolAddress((void**)&lat,  g_lat);
    cudaGetSymbolAddress((void**)&hx,   h_x);
    cudaGetSymbolAddress((void**)&hWq,  h_Wq);
    cudaGetSymbolAddress((void**)&hWkv, h_Wkv);
    cudaGetSymbolAddress((void**)&hWkr, h_Wkr);
    cudaGetSymbolAddress((void**)&hWkn, h_Wkn);
    cudaGetSymbolAddress((void**)&hWv,  h_Wv);
    cudaGetSymbolAddress((void**)&hWo,  h_Wo);
    cudaGetSymbolAddress((void**)&hlat, h_lat);
    cudaGetSymbolAddress((void**)&hattn, h_attn);
    cudaGetSymbolAddress((void**)&hq,   h_q);
    cudaGetSymbolAddress((void**)&hk,   h_k);
    cudaGetSymbolAddress((void**)&hv,   h_v);

    dim3 blk(256);

    f2h<<<(TOKS * HIDN) / 1024, blk>>>(x, hx);
    f2h<<<(HIDN * 2048) / 1024, blk>>>(Wq, hWq);
    f2h<<<(HIDN * DLAT) / 1024, blk>>>(Wkv, hWkv);
    f2h<<<(DLAT * 1024) / 1024, blk>>>(Wkr, hWkr);
    f2h<<<(DLAT * 1024) / 1024, blk>>>(Wkn, hWkn);
    f2h<<<(DLAT * 2048) / 1024, blk>>>(Wv, hWv);
    f2h<<<(2048 * HIDN) / 1024, blk>>>(Wo, hWo);

    // projections (fp32 outputs; k head-interleaved)
    hgemm128<<<dim3(16, 32), blk>>>(hx, hWq, q, TOKS, 2048, HIDN, 11, 2048, 0, 2048);
    hgemm128<<<dim3(4, 32), blk>>>(hx, hWkv, lat, TOKS, DLAT, HIDN, 9, DLAT, 0, DLAT);
    f2h<<<(TOKS * DLAT) / 1024, blk>>>(lat, hlat);
    hgemm128<<<dim3(8, 32), blk>>>(hlat, hWkr, k, TOKS, 1024, DLAT, 6, 128, 0, 2048);
    hgemm128<<<dim3(8, 32), blk>>>(hlat, hWkn, k, TOKS, 1024, DLAT, 6, 128, 64, 2048);
    hgemm128<<<dim3(16, 32), blk>>>(hlat, hWv, v, TOKS, 2048, DLAT, 11, 2048, 0, 2048);

    // norm + repack to fp16 [b][h][s][d]; 1/sqrt(D) folded into q
    rmsnorm_h<<<TOKS * NH / 8, blk>>>(q, gq, hq, 0.08838834764831845f);
    rmsnorm_h<<<TOKS * NH / 8, blk>>>(k, gk, hk, 1.0f);
    pack_h<<<TOKS * NH / 8, blk>>>(v, hv);

    // tensor-core causal attention -> h_attn [tok][2048] fp16
    attn_mma<<<dim3(SEQ / 128, NB * NH), dim3(256)>>>(hq, hk, hv, hattn);

    // out = attn @ Wo
    hgemm128<<<dim3(16, 32), blk>>>(hattn, hWo, out, TOKS, 2048, 2048, 11, 2048, 0, 2048);
}

// round 9
// speedup vs baseline: 9.2867x; 1.0309x over previous
#include <cuda_runtime.h>
#include <cuda_fp16.h>
#include <math.h>
#include <stdint.h>

// Problem constants
#define TOKS 4096      // B*S = 2*2048
#define SEQ  2048
#define NB   2
#define NH   16
#define HD   128
#define HIDN 2048
#define DLAT 512

// fp32 scratch (GEMM outputs pre-norm)
__device__ float g_q[TOKS * 2048];
__device__ float g_k[TOKS * 2048];
__device__ float g_v[TOKS * 2048];

// fp16 scratch
__device__ __half h_x[TOKS * HIDN];
__device__ __half h_Wq[HIDN * 2048];
__device__ __half h_Wkv[HIDN * DLAT];
__device__ __half h_Wkrn[DLAT * 2048];   // combined head-interleaved kr|kn weight
__device__ __half h_Wv[DLAT * 2048];
__device__ __half h_Wo[2048 * HIDN];
__device__ __half h_lat[TOKS * DLAT];
__device__ __half h_attn[TOKS * 2048];
__device__ __half h_q[TOKS * 2048];   // [b][h][s][d]
__device__ __half h_k[TOKS * 2048];   // [b][h][s][d]
__device__ __half h_v[TOKS * 2048];   // [b][h][s][d]

// ----------------------------------------------------------------------------
// Fused fp32->fp16 conversion of x + all weights, with Wkr/Wkn column remap
// into the combined h_Wkrn.
// ----------------------------------------------------------------------------
#define V4_X    2097152L
#define V4_WQ   1048576L
#define V4_WKV   262144L
#define V4_WKR   131072L
#define V4_WKN   131072L
#define V4_WV    262144L
#define V4_WO   1048576L
#define CV_B0 (V4_X)
#define CV_B1 (CV_B0 + V4_WQ)
#define CV_B2 (CV_B1 + V4_WKV)
#define CV_B3 (CV_B2 + V4_WKR)
#define CV_B4 (CV_B3 + V4_WKN)
#define CV_B5 (CV_B4 + V4_WV)
#define CV_B6 (CV_B5 + V4_WO)
#define CV_BLOCKS (CV_B6 / 256)

__device__ __forceinline__ void cvt4(const float* s, __half* d, long si, long di)
{
    float4 v = *(const float4*)(s + si * 4);
    *(__half2*)(d + di * 4)     = __floats2half2_rn(v.x, v.y);
    *(__half2*)(d + di * 4 + 2) = __floats2half2_rn(v.z, v.w);
}

__global__ __launch_bounds__(256)
void convert_all(const float* __restrict__ x,  const float* __restrict__ Wq,
                 const float* __restrict__ Wkv, const float* __restrict__ Wkr,
                 const float* __restrict__ Wkn, const float* __restrict__ Wv,
                 const float* __restrict__ Wo,
                 __half* __restrict__ hx,  __half* __restrict__ hWq,
                 __half* __restrict__ hWkv, __half* __restrict__ hWkrn,
                 __half* __restrict__ hWv, __half* __restrict__ hWo)
{
    long v4 = (long)blockIdx.x * 256 + threadIdx.x;
    if (v4 < CV_B0)      cvt4(x,   hx,   v4, v4);
    else if (v4 < CV_B1) cvt4(Wq,  hWq,  v4 - CV_B0, v4 - CV_B0);
    else if (v4 < CV_B2) cvt4(Wkv, hWkv, v4 - CV_B1, v4 - CV_B1);
    else if (v4 < CV_B3) {
        long e = v4 - CV_B2;            // vec4 within Wkr [512 x 1024]
        long row = e >> 8;
        int j = (int)(e & 255) * 4;
        int h = j >> 6, c = j & 63;
        long dst = row * 2048 + h * 128 + c;
        cvt4(Wkr, hWkrn, e, dst >> 2);
    } else if (v4 < CV_B4) {
        long e = v4 - CV_B3;            // vec4 within Wkn [512 x 1024]
        long row = e >> 8;
        int j = (int)(e & 255) * 4;
        int h = j >> 6, c = j & 63;
        long dst = row * 2048 + h * 128 + 64 + c;
        cvt4(Wkn, hWkrn, e, dst >> 2);
    }
    else if (v4 < CV_B5) cvt4(Wv, hWv, v4 - CV_B4, v4 - CV_B4);
    else                 cvt4(Wo, hWo, v4 - CV_B5, v4 - CV_B5);
}

// ----------------------------------------------------------------------------
#define AS_STRIDE 40    // halves
#define BS_STRIDE 136   // halves
#define A_STG (128 * AS_STRIDE)   // 5120 halves per stage
#define B_STG (32 * BS_STRIDE)    // 4352 halves per stage

__device__ __forceinline__ uint32_t sptr(const void* p)
{
    return (uint32_t)__cvta_generic_to_shared(p);
}
__device__ __forceinline__ void ldsm_x4(uint32_t* r, uint32_t addr)
{
    asm volatile("ldmatrix.sync.aligned.m8n8.x4.shared.b16 {%0,%1,%2,%3}, [%4];\n"
                 : "=r"(r[0]), "=r"(r[1]), "=r"(r[2]), "=r"(r[3]) : "r"(addr));
}
__device__ __forceinline__ void ldsm_x2t(uint32_t* r, uint32_t addr)
{
    asm volatile("ldmatrix.sync.aligned.m8n8.x2.trans.shared.b16 {%0,%1}, [%2];\n"
                 : "=r"(r[0]), "=r"(r[1]) : "r"(addr));
}
__device__ __forceinline__ void ldsm_x4t(uint32_t* r, uint32_t addr)
{
    asm volatile("ldmatrix.sync.aligned.m8n8.x4.trans.shared.b16 {%0,%1,%2,%3}, [%4];\n"
                 : "=r"(r[0]), "=r"(r[1]), "=r"(r[2]), "=r"(r[3]) : "r"(addr));
}
__device__ __forceinline__ void mma16816(float* c, const uint32_t* a, const uint32_t* b)
{
    asm volatile(
        "mma.sync.aligned.m16n8k16.row.col.f32.f16.f16.f32 "
        "{%0,%1,%2,%3}, {%4,%5,%6,%7}, {%8,%9}, {%0,%1,%2,%3};\n"
        : "+f"(c[0]), "+f"(c[1]), "+f"(c[2]), "+f"(c[3])
        : "r"(a[0]), "r"(a[1]), "r"(a[2]), "r"(a[3]), "r"(b[0]), "r"(b[1]));
}
__device__ __forceinline__ void cp16(uint32_t saddr, const void* g)
{
    asm volatile("cp.async.cg.shared.global [%0], [%1], 16;\n" :: "r"(saddr), "l"(g));
}
__device__ __forceinline__ void cp_commit()
{
    asm volatile("cp.async.commit_group;\n");
}
template <int N>
__device__ __forceinline__ void cp_wait()
{
    asm volatile("cp.async.wait_group %0;\n" :: "n"(N));
}

// ----------------------------------------------------------------------------
// Tensor-core GEMM: C (fp32 or fp16) = A fp16 @ B fp16, 128x128 block tile,
// BK=32, STATIC-smem 2-stage cp.async pipeline, ONE __syncthreads per
// iteration (wait -> barrier -> prefetch next -> compute).
// Epilogue column remap: out_col = (col>>lgGroup)*outstride + base + (col&mask)
// ----------------------------------------------------------------------------
template <typename T>
__global__ __launch_bounds__(256)
void hgemm128(const __half* __restrict__ A, const __half* __restrict__ B,
              T* __restrict__ C, int M, int N, int K,
              int lgGroup, int outstride, int base, int ldc)
{
    __shared__ __half Asb[2 * A_STG];
    __shared__ __half Bsb[2 * B_STG];

    const int tid  = threadIdx.x;
    const int warp = tid >> 5;
    const int lane = tid & 31;
    const int bm = blockIdx.y * 128;
    const int bn = blockIdx.x * 128;
    const int wm = (warp & 1) * 64;
    const int wn = (warp >> 1) * 32;

    float c[4][4][4];
#pragma unroll
    for (int mt = 0; mt < 4; ++mt)
#pragma unroll
        for (int nt = 0; nt < 4; ++nt)
#pragma unroll
            for (int i = 0; i < 4; ++i) c[mt][nt][i] = 0.0f;

    const int arow0 = tid >> 2,  akc = (tid & 3) * 8;
    const int brow0 = tid >> 4,  bnc = (tid & 15) * 8;

    const uint32_t a_base = sptr(&Asb[(wm + (lane & 15)) * AS_STRIDE + (lane >> 4) * 8]);
    const uint32_t b_base = sptr(&Bsb[(lane & 15) * BS_STRIDE + wn]);

    const int nk = K >> 5;

#define GEMM_LOAD_STAGE(s, k0)                                                        \
    do {                                                                              \
        cp16(sptr(&Asb[(s) * A_STG + arow0 * AS_STRIDE + akc]),                       \
             A + (size_t)(bm + arow0) * K + (k0) + akc);                              \
        cp16(sptr(&Asb[(s) * A_STG + (arow0 + 64) * AS_STRIDE + akc]),                \
             A + (size_t)(bm + arow0 + 64) * K + (k0) + akc);                         \
        cp16(sptr(&Bsb[(s) * B_STG + brow0 * BS_STRIDE + bnc]),                       \
             B + (size_t)((k0) + brow0) * N + bn + bnc);                              \
        cp16(sptr(&Bsb[(s) * B_STG + (brow0 + 16) * BS_STRIDE + bnc]),                \
             B + (size_t)((k0) + brow0 + 16) * N + bn + bnc);                         \
    } while (0)

    GEMM_LOAD_STAGE(0, 0);
    cp_commit();

    for (int t = 0; t < nk; ++t) {
        cp_wait<0>();            // stage t arrived (only pending group)
        __syncthreads();         // everyone done reading the buffer we overwrite
        if (t + 1 < nk) {
            GEMM_LOAD_STAGE((t + 1) & 1, (t + 1) << 5);
            cp_commit();
        }

        const uint32_t ab = a_base + (t & 1) * A_STG * 2;
        const uint32_t bb = b_base + (t & 1) * B_STG * 2;
#pragma unroll
        for (int kt = 0; kt < 2; ++kt) {
            uint32_t a[4][4], b[4][2];
#pragma unroll
            for (int mt = 0; mt < 4; ++mt)
                ldsm_x4(a[mt], ab + (mt * 16 * AS_STRIDE + kt * 16) * 2);
#pragma unroll
            for (int nt = 0; nt < 4; ++nt)
                ldsm_x2t(b[nt], bb + (kt * 16 * BS_STRIDE + nt * 8) * 2);
#pragma unroll
            for (int mt = 0; mt < 4; ++mt)
#pragma unroll
                for (int nt = 0; nt < 4; ++nt)
                    mma16816(c[mt][nt], a[mt], b[nt]);
        }
    }

    const int gmask = (1 << lgGroup) - 1;
    const int gid = lane >> 2;
    const int tig = lane & 3;
#pragma unroll
    for (int mt = 0; mt < 4; ++mt) {
#pragma unroll
        for (int nt = 0; nt < 4; ++nt) {
            int col = bn + wn + nt * 8 + tig * 2;
            int oc = ((col >> lgGroup) * outstride) + base + (col & gmask);
            int r0 = bm + wm + mt * 16 + gid;
            if (sizeof(T) == 4) {
                *(float2*)&((float*)C)[(size_t)r0 * ldc + oc] =
                    make_float2(c[mt][nt][0], c[mt][nt][1]);
                *(float2*)&((float*)C)[(size_t)(r0 + 8) * ldc + oc] =
                    make_float2(c[mt][nt][2], c[mt][nt][3]);
            } else {
                *(__half2*)&((__half*)C)[(size_t)r0 * ldc + oc] =
                    __floats2half2_rn(c[mt][nt][0], c[mt][nt][1]);
                *(__half2*)&((__half*)C)[(size_t)(r0 + 8) * ldc + oc] =
                    __floats2half2_rn(c[mt][nt][2], c[mt][nt][3]);
            }
        }
    }
}

// ----------------------------------------------------------------------------
// RMSNorm over D=128 (+ extra output scale) + fp16 repack -> [b][h][s][d].
// ----------------------------------------------------------------------------
__global__ __launch_bounds__(256)
void rmsnorm_h(const float* __restrict__ in, const float* __restrict__ g,
               __half* __restrict__ out, float pscale)
{
    int row = blockIdx.x * 8 + (threadIdx.x >> 5);   // row = tok*16 + h
    int lane = threadIdx.x & 31;
    float4 v = *((const float4*)(in + (size_t)row * 128) + lane);
    float ss = v.x * v.x + v.y * v.y + v.z * v.z + v.w * v.w;
#pragma unroll
    for (int o = 16; o; o >>= 1) ss += __shfl_xor_sync(0xffffffffu, ss, o);
    float r = rsqrtf(ss * (1.0f / 128.0f) + 1e-6f) * pscale;
    float4 gv = ((const float4*)g)[lane];
    int tok = row >> 4, h = row & 15;
    int b = tok >> 11, s = tok & 2047;
    __half* dst = out + ((size_t)(b * 16 + h) * 2048 + s) * 128 + lane * 4;
    *(__half2*)dst       = __floats2half2_rn(v.x * r * gv.x, v.y * r * gv.y);
    *(__half2*)(dst + 2) = __floats2half2_rn(v.z * r * gv.z, v.w * r * gv.w);
}

__global__ __launch_bounds__(256)
void pack_h(const float* __restrict__ in, __half* __restrict__ out)
{
    int row = blockIdx.x * 8 + (threadIdx.x >> 5);
    int lane = threadIdx.x & 31;
    float4 v = *((const float4*)(in + (size_t)row * 128) + lane);
    int tok = row >> 4, h = row & 15;
    int b = tok >> 11, s = tok & 2047;
    __half* dst = out + ((size_t)(b * 16 + h) * 2048 + s) * 128 + lane * 4;
    *(__half2*)dst       = __floats2half2_rn(v.x, v.y);
    *(__half2*)(dst + 2) = __floats2half2_rn(v.z, v.w);
}

// ----------------------------------------------------------------------------
// Tensor-core causal flash attention (round-5 proven body, static smem).
// Grid: (S/128, B*H), 256 threads = 8 warps; warp w owns 16 query rows.
// Q pre-scaled by 1/sqrt(D). CTA order reversed (heavy blocks first).
// ----------------------------------------------------------------------------
#define KS_STRIDE 136

__global__ __launch_bounds__(256)
void attn_mma(const __half* __restrict__ q, const __half* __restrict__ k,
              const __half* __restrict__ v, __half* __restrict__ o)
{
    __shared__ __half Ks[64 * KS_STRIDE];
    __shared__ __half Vs[64 * KS_STRIDE];

    const int bh = blockIdx.y;
    const int b = bh >> 4, h = bh & 15;
    const int qb = ((int)gridDim.x - 1 - (int)blockIdx.x) * 128;   // heavy first
    const int tid = threadIdx.x;
    const int warp = tid >> 5, lane = tid & 31;
    const size_t base = (size_t)bh * SEQ * HD;
    const int r0 = warp * 16 + (lane >> 2);
    const int w0 = qb + warp * 16;
    const int c2 = (lane & 3) * 2;

    // Q a-frags
    uint32_t aq[8][4];
    {
        const __half* q0 = q + base + (size_t)(qb + r0) * HD;
#pragma unroll
        for (int kc = 0; kc < 8; ++kc) {
            aq[kc][0] = *(const uint32_t*)(q0 + kc * 16 + c2);
            aq[kc][1] = *(const uint32_t*)(q0 + 8 * HD + kc * 16 + c2);
            aq[kc][2] = *(const uint32_t*)(q0 + kc * 16 + c2 + 8);
            aq[kc][3] = *(const uint32_t*)(q0 + 8 * HD + kc * 16 + c2 + 8);
        }
    }

    float oa[16][4];
#pragma unroll
    for (int nt = 0; nt < 16; ++nt)
#pragma unroll
        for (int i = 0; i < 4; ++i) oa[nt][i] = 0.0f;
    float m0 = -1e30f, m1 = -1e30f, l0 = 0.0f, l1 = 0.0f;

    const uint32_t kaddr = sptr(&Ks[(lane & 7) * KS_STRIDE + (lane >> 3) * 8]);
    const uint32_t vaddr = sptr(&Vs[(lane & 15) * KS_STRIDE + (lane >> 4) * 8]);

    const int ntiles = qb / 64 + 2;
    for (int t = 0; t < ntiles; ++t) {
        const int j0 = t * 64;
        const __half* kg = k + base + (size_t)j0 * HD;
        const __half* vg = v + base + (size_t)j0 * HD;
#pragma unroll
        for (int i = tid; i < 1024; i += 256) {
            int row = i >> 4, col8 = (i & 15) * 8;
            *(uint4*)&Ks[row * KS_STRIDE + col8] = *(const uint4*)(kg + row * HD + col8);
            *(uint4*)&Vs[row * KS_STRIDE + col8] = *(const uint4*)(vg + row * HD + col8);
        }
        __syncthreads();

        if (j0 <= w0 + 15) {
            float s[8][4];
#pragma unroll
            for (int nt = 0; nt < 8; ++nt) {
                s[nt][0] = s[nt][1] = s[nt][2] = s[nt][3] = 0.0f;
                uint32_t bk[4][4];
#pragma unroll
                for (int g = 0; g < 4; ++g)
                    ldsm_x4(bk[g], kaddr + (nt * 8 * KS_STRIDE + g * 32) * 2);
#pragma unroll
                for (int kc = 0; kc < 8; ++kc)
                    mma16816(s[nt], aq[kc], &bk[kc >> 1][(kc & 1) * 2]);
            }

            if (j0 + 63 > w0) {
#pragma unroll
                for (int nt = 0; nt < 8; ++nt) {
#pragma unroll
                    for (int i = 0; i < 4; ++i) {
                        int col = j0 + nt * 8 + c2 + (i & 1);
                        int rowq = qb + r0 + (i >> 1) * 8;
                        if (col > rowq) s[nt][i] = -1e30f;
                    }
                }
            }

            float tm0 = -1e30f, tm1 = -1e30f;
#pragma unroll
            for (int nt = 0; nt < 8; ++nt) {
                tm0 = fmaxf(tm0, fmaxf(s[nt][0], s[nt][1]));
                tm1 = fmaxf(tm1, fmaxf(s[nt][2], s[nt][3]));
            }
            tm0 = fmaxf(tm0, __shfl_xor_sync(0xffffffffu, tm0, 1));
            tm0 = fmaxf(tm0, __shfl_xor_sync(0xffffffffu, tm0, 2));
            tm1 = fmaxf(tm1, __shfl_xor_sync(0xffffffffu, tm1, 1));
            tm1 = fmaxf(tm1, __shfl_xor_sync(0xffffffffu, tm1, 2));
            float mn0 = fmaxf(m0, tm0), mn1 = fmaxf(m1, tm1);
            float al0 = __expf(m0 - mn0), al1 = __expf(m1 - mn1);
            m0 = mn0; m1 = mn1;

            float rs0 = 0.0f, rs1 = 0.0f;
#pragma unroll
            for (int nt = 0; nt < 8; ++nt) {
                s[nt][0] = __expf(s[nt][0] - mn0);
                s[nt][1] = __expf(s[nt][1] - mn0);
                s[nt][2] = __expf(s[nt][2] - mn1);
                s[nt][3] = __expf(s[nt][3] - mn1);
                rs0 += s[nt][0] + s[nt][1];
                rs1 += s[nt][2] + s[nt][3];
            }
            rs0 += __shfl_xor_sync(0xffffffffu, rs0, 1);
            rs0 += __shfl_xor_sync(0xffffffffu, rs0, 2);
            rs1 += __shfl_xor_sync(0xffffffffu, rs1, 1);
            rs1 += __shfl_xor_sync(0xffffffffu, rs1, 2);
            l0 = l0 * al0 + rs0;
            l1 = l1 * al1 + rs1;

#pragma unroll
            for (int nt = 0; nt < 16; ++nt) {
                oa[nt][0] *= al0; oa[nt][1] *= al0;
                oa[nt][2] *= al1; oa[nt][3] *= al1;
            }

            uint32_t ap[4][4];
#pragma unroll
            for (int kc = 0; kc < 4; ++kc) {
                __half2 t0 = __floats2half2_rn(s[2 * kc][0], s[2 * kc][1]);
                __half2 t1 = __floats2half2_rn(s[2 * kc][2], s[2 * kc][3]);
                __half2 t2 = __floats2half2_rn(s[2 * kc + 1][0], s[2 * kc + 1][1]);
                __half2 t3 = __floats2half2_rn(s[2 * kc + 1][2], s[2 * kc + 1][3]);
                ap[kc][0] = *(uint32_t*)&t0;
                ap[kc][1] = *(uint32_t*)&t1;
                ap[kc][2] = *(uint32_t*)&t2;
                ap[kc][3] = *(uint32_t*)&t3;
            }

#pragma unroll
            for (int kc = 0; kc < 4; ++kc) {
#pragma unroll
                for (int ntp = 0; ntp < 8; ++ntp) {
                    uint32_t bv[4];
                    ldsm_x4t(bv, vaddr + (kc * 16 * KS_STRIDE + ntp * 16) * 2);
                    mma16816(oa[ntp * 2], ap[kc], &bv[0]);
                    mma16816(oa[ntp * 2 + 1], ap[kc], &bv[2]);
                }
            }
        }
        __syncthreads();
    }

    float inv0 = 1.0f / l0, inv1 = 1.0f / l1;
    size_t tok0 = (size_t)b * SEQ + qb + r0;
    __half* d0 = o + tok0 * 2048 + h * 128 + c2;
    __half* d1 = d0 + (size_t)8 * 2048;
#pragma unroll
    for (int nt = 0; nt < 16; ++nt) {
        *(__half2*)(d0 + nt * 8) = __floats2half2_rn(oa[nt][0] * inv0, oa[nt][1] * inv0);
        *(__half2*)(d1 + nt * 8) = __floats2half2_rn(oa[nt][2] * inv1, oa[nt][3] * inv1);
    }
}

// ----------------------------------------------------------------------------
extern "C" void kernel_launch(void* const* d_in, const int* in_sizes, int n_in,
                              void* d_out, int out_size)
{
    const float* x   = (const float*)d_in[0];
    const float* Wq  = (const float*)d_in[1];
    const float* Wkv = (const float*)d_in[2];
    const float* Wkr = (const float*)d_in[3];
    const float* Wkn = (const float*)d_in[4];
    const float* Wv  = (const float*)d_in[5];
    const float* Wo  = (const float*)d_in[6];
    const float* gq  = (const float*)d_in[7];
    const float* gk  = (const float*)d_in[8];
    float* out = (float*)d_out;

    float *q, *k, *v;
    __half *hx, *hWq, *hWkv, *hWkrn, *hWv, *hWo, *hlat, *hattn, *hq, *hk, *hv;
    cudaGetSymbolAddress((void**)&q,    g_q);
    cudaGetSymbolAddress((void**)&k,    g_k);
    cudaGetSymbolAddress((void**)&v,    g_v);
    cudaGetSymbolAddress((void**)&hx,   h_x);
    cudaGetSymbolAddress((void**)&hWq,  h_Wq);
    cudaGetSymbolAddress((void**)&hWkv, h_Wkv);
    cudaGetSymbolAddress((void**)&hWkrn, h_Wkrn);
    cudaGetSymbolAddress((void**)&hWv,  h_Wv);
    cudaGetSymbolAddress((void**)&hWo,  h_Wo);
    cudaGetSymbolAddress((void**)&hlat, h_lat);
    cudaGetSymbolAddress((void**)&hattn, h_attn);
    cudaGetSymbolAddress((void**)&hq,   h_q);
    cudaGetSymbolAddress((void**)&hk,   h_k);
    cudaGetSymbolAddress((void**)&hv,   h_v);

    dim3 blk(256);

    // fused conversions (1 launch)
    convert_all<<<CV_BLOCKS, blk>>>(x, Wq, Wkv, Wkr, Wkn, Wv, Wo,
                                    hx, hWq, hWkv, hWkrn, hWv, hWo);

    // q = x @ Wq -> fp32 [tok][h*128+d]
    hgemm128<float><<<dim3(16, 32), blk>>>(hx, hWq, q, TOKS, 2048, HIDN,
                                           11, 2048, 0, 2048);
    // lat = x @ Wkv -> fp16 directly
    hgemm128<__half><<<dim3(4, 32), blk>>>(hx, hWkv, hlat, TOKS, DLAT, HIDN,
                                           9, DLAT, 0, DLAT);
    // k = lat @ Wkrn (combined, pre-interleaved) -> fp32 [tok][h*128+d]
    hgemm128<float><<<dim3(16, 32), blk>>>(hlat, hWkrn, k, TOKS, 2048, DLAT,
                                           11, 2048, 0, 2048);
    // v = lat @ Wv -> fp32
    hgemm128<float><<<dim3(16, 32), blk>>>(hlat, hWv, v, TOKS, 2048, DLAT,
                                           11, 2048, 0, 2048);

    // norm + repack to fp16 [b][h][s][d]; 1/sqrt(D) folded into q
    rmsnorm_h<<<TOKS * NH / 8, blk>>>(q, gq, hq, 0.08838834764831845f);
    rmsnorm_h<<<TOKS * NH / 8, blk>>>(k, gk, hk, 1.0f);
    pack_h<<<TOKS * NH / 8, blk>>>(v, hv);

    // causal attention -> h_attn [tok][2048] fp16
    attn_mma<<<dim3(SEQ / 128, NB * NH), blk>>>(hq, hk, hv, hattn);

    // out = attn @ Wo
    hgemm128<float><<<dim3(16, 32), blk>>>(hattn, hWo, out, TOKS, 2048, 2048,
                                           11, 2048, 0, 2048);
}

// round 10
// speedup vs baseline: 9.6558x; 1.0397x over previous
#include <cuda_runtime.h>
#include <cuda_fp16.h>
#include <math.h>
#include <stdint.h>

// Problem constants
#define TOKS 4096      // B*S = 2*2048
#define SEQ  2048
#define NB   2
#define NH   16
#define HD   128
#define HIDN 2048
#define DLAT 512

// fp32 scratch (GEMM outputs pre-norm)
__device__ float g_q[TOKS * 2048];
__device__ float g_k[TOKS * 2048];

// fp16 scratch
__device__ __half h_x[TOKS * HIDN];
__device__ __half h_Wq[HIDN * 2048];
__device__ __half h_Wkv[HIDN * DLAT];
__device__ __half h_Wkrn[DLAT * 2048];   // combined head-interleaved kr|kn weight
__device__ __half h_Wv[DLAT * 2048];
__device__ __half h_Wo[2048 * HIDN];
__device__ __half h_lat[TOKS * DLAT];
__device__ __half h_attn[TOKS * 2048];
__device__ __half h_q[TOKS * 2048];   // [b][h][s][d]
__device__ __half h_k[TOKS * 2048];   // [b][h][s][d]
__device__ __half h_v[TOKS * 2048];   // [tok][h][d]  (GEMM-direct)

// ----------------------------------------------------------------------------
// Fused fp32->fp16 conversion of x + all weights, with Wkr/Wkn column remap
// into the combined h_Wkrn.
// ----------------------------------------------------------------------------
#define V4_X    2097152L
#define V4_WQ   1048576L
#define V4_WKV   262144L
#define V4_WKR   131072L
#define V4_WKN   131072L
#define V4_WV    262144L
#define V4_WO   1048576L
#define CV_B0 (V4_X)
#define CV_B1 (CV_B0 + V4_WQ)
#define CV_B2 (CV_B1 + V4_WKV)
#define CV_B3 (CV_B2 + V4_WKR)
#define CV_B4 (CV_B3 + V4_WKN)
#define CV_B5 (CV_B4 + V4_WV)
#define CV_B6 (CV_B5 + V4_WO)
#define CV_BLOCKS (CV_B6 / 256)

__device__ __forceinline__ void cvt4(const float* s, __half* d, long si, long di)
{
    float4 v = *(const float4*)(s + si * 4);
    *(__half2*)(d + di * 4)     = __floats2half2_rn(v.x, v.y);
    *(__half2*)(d + di * 4 + 2) = __floats2half2_rn(v.z, v.w);
}

__global__ __launch_bounds__(256)
void convert_all(const float* __restrict__ x,  const float* __restrict__ Wq,
                 const float* __restrict__ Wkv, const float* __restrict__ Wkr,
                 const float* __restrict__ Wkn, const float* __restrict__ Wv,
                 const float* __restrict__ Wo,
                 __half* __restrict__ hx,  __half* __restrict__ hWq,
                 __half* __restrict__ hWkv, __half* __restrict__ hWkrn,
                 __half* __restrict__ hWv, __half* __restrict__ hWo)
{
    long v4 = (long)blockIdx.x * 256 + threadIdx.x;
    if (v4 < CV_B0)      cvt4(x,   hx,   v4, v4);
    else if (v4 < CV_B1) cvt4(Wq,  hWq,  v4 - CV_B0, v4 - CV_B0);
    else if (v4 < CV_B2) cvt4(Wkv, hWkv, v4 - CV_B1, v4 - CV_B1);
    else if (v4 < CV_B3) {
        long e = v4 - CV_B2;            // vec4 within Wkr [512 x 1024]
        long row = e >> 8;
        int j = (int)(e & 255) * 4;
        int h = j >> 6, c = j & 63;
        long dst = row * 2048 + h * 128 + c;
        cvt4(Wkr, hWkrn, e, dst >> 2);
    } else if (v4 < CV_B4) {
        long e = v4 - CV_B3;            // vec4 within Wkn [512 x 1024]
        long row = e >> 8;
        int j = (int)(e & 255) * 4;
        int h = j >> 6, c = j & 63;
        long dst = row * 2048 + h * 128 + 64 + c;
        cvt4(Wkn, hWkrn, e, dst >> 2);
    }
    else if (v4 < CV_B5) cvt4(Wv, hWv, v4 - CV_B4, v4 - CV_B4);
    else                 cvt4(Wo, hWo, v4 - CV_B5, v4 - CV_B5);
}

// ----------------------------------------------------------------------------
#define AS_STRIDE 40    // halves
#define BS_STRIDE 136   // halves
#define A_STG (128 * AS_STRIDE)   // 5120 halves per stage
#define B_STG (32 * BS_STRIDE)    // 4352 halves per stage

__device__ __forceinline__ uint32_t sptr(const void* p)
{
    return (uint32_t)__cvta_generic_to_shared(p);
}
__device__ __forceinline__ void ldsm_x4(uint32_t* r, uint32_t addr)
{
    asm volatile("ldmatrix.sync.aligned.m8n8.x4.shared.b16 {%0,%1,%2,%3}, [%4];\n"
                 : "=r"(r[0]), "=r"(r[1]), "=r"(r[2]), "=r"(r[3]) : "r"(addr));
}
__device__ __forceinline__ void ldsm_x2t(uint32_t* r, uint32_t addr)
{
    asm volatile("ldmatrix.sync.aligned.m8n8.x2.trans.shared.b16 {%0,%1}, [%2];\n"
                 : "=r"(r[0]), "=r"(r[1]) : "r"(addr));
}
__device__ __forceinline__ void ldsm_x4t(uint32_t* r, uint32_t addr)
{
    asm volatile("ldmatrix.sync.aligned.m8n8.x4.trans.shared.b16 {%0,%1,%2,%3}, [%4];\n"
                 : "=r"(r[0]), "=r"(r[1]), "=r"(r[2]), "=r"(r[3]) : "r"(addr));
}
__device__ __forceinline__ void mma16816(float* c, const uint32_t* a, const uint32_t* b)
{
    asm volatile(
        "mma.sync.aligned.m16n8k16.row.col.f32.f16.f16.f32 "
        "{%0,%1,%2,%3}, {%4,%5,%6,%7}, {%8,%9}, {%0,%1,%2,%3};\n"
        : "+f"(c[0]), "+f"(c[1]), "+f"(c[2]), "+f"(c[3])
        : "r"(a[0]), "r"(a[1]), "r"(a[2]), "r"(a[3]), "r"(b[0]), "r"(b[1]));
}
__device__ __forceinline__ void cp16(uint32_t saddr, const void* g)
{
    asm volatile("cp.async.cg.shared.global [%0], [%1], 16;\n" :: "r"(saddr), "l"(g));
}
__device__ __forceinline__ void cp_commit()
{
    asm volatile("cp.async.commit_group;\n");
}
template <int N>
__device__ __forceinline__ void cp_wait()
{
    asm volatile("cp.async.wait_group %0;\n" :: "n"(N));
}

// ----------------------------------------------------------------------------
// Tensor-core GEMM: C (fp32 or fp16) = A fp16 @ B fp16, 128x128 block tile,
// BK=32, STATIC-smem 2-stage cp.async pipeline, ONE __syncthreads per iter.
// Epilogue column remap: out_col = (col>>lgGroup)*outstride + base + (col&mask)
// ----------------------------------------------------------------------------
template <typename T>
__global__ __launch_bounds__(256, 2)
void hgemm128(const __half* __restrict__ A, const __half* __restrict__ B,
              T* __restrict__ C, int M, int N, int K,
              int lgGroup, int outstride, int base, int ldc)
{
    __shared__ __half Asb[2 * A_STG];
    __shared__ __half Bsb[2 * B_STG];

    const int tid  = threadIdx.x;
    const int warp = tid >> 5;
    const int lane = tid & 31;
    const int bm = blockIdx.y * 128;
    const int bn = blockIdx.x * 128;
    const int wm = (warp & 1) * 64;
    const int wn = (warp >> 1) * 32;

    float c[4][4][4];
#pragma unroll
    for (int mt = 0; mt < 4; ++mt)
#pragma unroll
        for (int nt = 0; nt < 4; ++nt)
#pragma unroll
            for (int i = 0; i < 4; ++i) c[mt][nt][i] = 0.0f;

    const int arow0 = tid >> 2,  akc = (tid & 3) * 8;
    const int brow0 = tid >> 4,  bnc = (tid & 15) * 8;

    const uint32_t a_base = sptr(&Asb[(wm + (lane & 15)) * AS_STRIDE + (lane >> 4) * 8]);
    const uint32_t b_base = sptr(&Bsb[(lane & 15) * BS_STRIDE + wn]);

    const int nk = K >> 5;

#define GEMM_LOAD_STAGE(s, k0)                                                        \
    do {                                                                              \
        cp16(sptr(&Asb[(s) * A_STG + arow0 * AS_STRIDE + akc]),                       \
             A + (size_t)(bm + arow0) * K + (k0) + akc);                              \
        cp16(sptr(&Asb[(s) * A_STG + (arow0 + 64) * AS_STRIDE + akc]),                \
             A + (size_t)(bm + arow0 + 64) * K + (k0) + akc);                         \
        cp16(sptr(&Bsb[(s) * B_STG + brow0 * BS_STRIDE + bnc]),                       \
             B + (size_t)((k0) + brow0) * N + bn + bnc);                              \
        cp16(sptr(&Bsb[(s) * B_STG + (brow0 + 16) * BS_STRIDE + bnc]),                \
             B + (size_t)((k0) + brow0 + 16) * N + bn + bnc);                         \
    } while (0)

    GEMM_LOAD_STAGE(0, 0);
    cp_commit();

    for (int t = 0; t < nk; ++t) {
        cp_wait<0>();
        __syncthreads();
        if (t + 1 < nk) {
            GEMM_LOAD_STAGE((t + 1) & 1, (t + 1) << 5);
            cp_commit();
        }

        const uint32_t ab = a_base + (t & 1) * A_STG * 2;
        const uint32_t bb = b_base + (t & 1) * B_STG * 2;
#pragma unroll
        for (int kt = 0; kt < 2; ++kt) {
            uint32_t a[4][4], b[4][2];
#pragma unroll
            for (int mt = 0; mt < 4; ++mt)
                ldsm_x4(a[mt], ab + (mt * 16 * AS_STRIDE + kt * 16) * 2);
#pragma unroll
            for (int nt = 0; nt < 4; ++nt)
                ldsm_x2t(b[nt], bb + (kt * 16 * BS_STRIDE + nt * 8) * 2);
#pragma unroll
            for (int mt = 0; mt < 4; ++mt)
#pragma unroll
                for (int nt = 0; nt < 4; ++nt)
                    mma16816(c[mt][nt], a[mt], b[nt]);
        }
    }

    const int gmask = (1 << lgGroup) - 1;
    const int gid = lane >> 2;
    const int tig = lane & 3;
#pragma unroll
    for (int mt = 0; mt < 4; ++mt) {
#pragma unroll
        for (int nt = 0; nt < 4; ++nt) {
            int col = bn + wn + nt * 8 + tig * 2;
            int oc = ((col >> lgGroup) * outstride) + base + (col & gmask);
            int r0 = bm + wm + mt * 16 + gid;
            if (sizeof(T) == 4) {
                *(float2*)&((float*)C)[(size_t)r0 * ldc + oc] =
                    make_float2(c[mt][nt][0], c[mt][nt][1]);
                *(float2*)&((float*)C)[(size_t)(r0 + 8) * ldc + oc] =
                    make_float2(c[mt][nt][2], c[mt][nt][3]);
            } else {
                *(__half2*)&((__half*)C)[(size_t)r0 * ldc + oc] =
                    __floats2half2_rn(c[mt][nt][0], c[mt][nt][1]);
                *(__half2*)&((__half*)C)[(size_t)(r0 + 8) * ldc + oc] =
                    __floats2half2_rn(c[mt][nt][2], c[mt][nt][3]);
            }
        }
    }
}

// ----------------------------------------------------------------------------
// RMSNorm over D=128 (+ extra output scale) + fp16 repack -> [b][h][s][d].
// ----------------------------------------------------------------------------
__global__ __launch_bounds__(256)
void rmsnorm_h(const float* __restrict__ in, const float* __restrict__ g,
               __half* __restrict__ out, float pscale)
{
    int row = blockIdx.x * 8 + (threadIdx.x >> 5);   // row = tok*16 + h
    int lane = threadIdx.x & 31;
    float4 v = *((const float4*)(in + (size_t)row * 128) + lane);
    float ss = v.x * v.x + v.y * v.y + v.z * v.z + v.w * v.w;
#pragma unroll
    for (int o = 16; o; o >>= 1) ss += __shfl_xor_sync(0xffffffffu, ss, o);
    float r = rsqrtf(ss * (1.0f / 128.0f) + 1e-6f) * pscale;
    float4 gv = ((const float4*)g)[lane];
    int tok = row >> 4, h = row & 15;
    int b = tok >> 11, s = tok & 2047;
    __half* dst = out + ((size_t)(b * 16 + h) * 2048 + s) * 128 + lane * 4;
    *(__half2*)dst       = __floats2half2_rn(v.x * r * gv.x, v.y * r * gv.y);
    *(__half2*)(dst + 2) = __floats2half2_rn(v.z * r * gv.z, v.w * r * gv.w);
}

// ----------------------------------------------------------------------------
// Tensor-core causal flash attention, single-buffered cp.async pipeline:
//   wait K(t) -> QK(t) [V(t) in flight] -> wait V(t) -> issue K(t+1)
//   -> softmax+PV(t) -> issue V(t+1)
// K in [b][h][s][d]; V read directly from GEMM output [tok][h][d].
// Grid: (S/128, B*H), 256 threads = 8 warps; Q pre-scaled by 1/sqrt(D).
// ----------------------------------------------------------------------------
#define KS_STRIDE 136

__global__ __launch_bounds__(256)
void attn_mma(const __half* __restrict__ q, const __half* __restrict__ k,
              const __half* __restrict__ v, __half* __restrict__ o)
{
    __shared__ __half Ks[64 * KS_STRIDE];
    __shared__ __half Vs[64 * KS_STRIDE];

    const int bh = blockIdx.y;
    const int b = bh >> 4, h = bh & 15;
    const int qb = ((int)gridDim.x - 1 - (int)blockIdx.x) * 128;   // heavy first
    const int tid = threadIdx.x;
    const int warp = tid >> 5, lane = tid & 31;
    const size_t base = (size_t)bh * SEQ * HD;
    const int r0 = warp * 16 + (lane >> 2);
    const int w0 = qb + warp * 16;
    const int c2 = (lane & 3) * 2;

    // Q a-frags
    uint32_t aq[8][4];
    {
        const __half* q0 = q + base + (size_t)(qb + r0) * HD;
#pragma unroll
        for (int kc = 0; kc < 8; ++kc) {
            aq[kc][0] = *(const uint32_t*)(q0 + kc * 16 + c2);
            aq[kc][1] = *(const uint32_t*)(q0 + 8 * HD + kc * 16 + c2);
            aq[kc][2] = *(const uint32_t*)(q0 + kc * 16 + c2 + 8);
            aq[kc][3] = *(const uint32_t*)(q0 + 8 * HD + kc * 16 + c2 + 8);
        }
    }

    float oa[16][4];
#pragma unroll
    for (int nt = 0; nt < 16; ++nt)
#pragma unroll
        for (int i = 0; i < 4; ++i) oa[nt][i] = 0.0f;
    float m0 = -1e30f, m1 = -1e30f, l0 = 0.0f, l1 = 0.0f;

    const uint32_t kaddr = sptr(&Ks[(lane & 7) * KS_STRIDE + (lane >> 3) * 8]);
    const uint32_t vaddr = sptr(&Vs[(lane & 15) * KS_STRIDE + (lane >> 4) * 8]);

#define LOAD_K(t_)                                                                 \
    do {                                                                           \
        const __half* kg_ = k + base + (size_t)(t_) * 64 * HD;                     \
        for (int i = tid; i < 1024; i += 256) {                                    \
            int r_ = i >> 4, c_ = (i & 15) * 8;                                    \
            cp16(sptr(&Ks[r_ * KS_STRIDE + c_]), kg_ + r_ * HD + c_);              \
        }                                                                          \
    } while (0)
#define LOAD_V(t_)                                                                 \
    do {                                                                           \
        const __half* vg_ = v + ((size_t)(b * SEQ + (t_) * 64) * 16 + h) * 128;    \
        for (int i = tid; i < 1024; i += 256) {                                    \
            int r_ = i >> 4, c_ = (i & 15) * 8;                                    \
            cp16(sptr(&Vs[r_ * KS_STRIDE + c_]), vg_ + r_ * 2048 + c_);            \
        }                                                                          \
    } while (0)

    const int ntiles = qb / 64 + 2;
    LOAD_K(0); cp_commit();
    LOAD_V(0); cp_commit();

    for (int t = 0; t < ntiles; ++t) {
        const int j0 = t * 64;
        const bool live = (j0 <= w0 + 15);

        cp_wait<1>();            // K(t) resident (V(t) may still be in flight)
        __syncthreads();

        float s[8][4];
        if (live) {
#pragma unroll
            for (int nt = 0; nt < 8; ++nt) {
                s[nt][0] = s[nt][1] = s[nt][2] = s[nt][3] = 0.0f;
                uint32_t bk[4][4];
#pragma unroll
                for (int g = 0; g < 4; ++g)
                    ldsm_x4(bk[g], kaddr + (nt * 8 * KS_STRIDE + g * 32) * 2);
#pragma unroll
                for (int kc = 0; kc < 8; ++kc)
                    mma16816(s[nt], aq[kc], &bk[kc >> 1][(kc & 1) * 2]);
            }
        }

        cp_wait<0>();            // V(t) resident; K buffer free after barrier
        __syncthreads();
        if (t + 1 < ntiles) LOAD_K(t + 1);
        cp_commit();             // lands during softmax+PV

        if (live) {
            if (j0 + 63 > w0) {
#pragma unroll
                for (int nt = 0; nt < 8; ++nt) {
#pragma unroll
                    for (int i = 0; i < 4; ++i) {
                        int col = j0 + nt * 8 + c2 + (i & 1);
                        int rowq = qb + r0 + (i >> 1) * 8;
                        if (col > rowq) s[nt][i] = -1e30f;
                    }
                }
            }

            float tm0 = -1e30f, tm1 = -1e30f;
#pragma unroll
            for (int nt = 0; nt < 8; ++nt) {
                tm0 = fmaxf(tm0, fmaxf(s[nt][0], s[nt][1]));
                tm1 = fmaxf(tm1, fmaxf(s[nt][2], s[nt][3]));
            }
            tm0 = fmaxf(tm0, __shfl_xor_sync(0xffffffffu, tm0, 1));
            tm0 = fmaxf(tm0, __shfl_xor_sync(0xffffffffu, tm0, 2));
            tm1 = fmaxf(tm1, __shfl_xor_sync(0xffffffffu, tm1, 1));
            tm1 = fmaxf(tm1, __shfl_xor_sync(0xffffffffu, tm1, 2));
            float mn0 = fmaxf(m0, tm0), mn1 = fmaxf(m1, tm1);
            float al0 = __expf(m0 - mn0), al1 = __expf(m1 - mn1);
            m0 = mn0; m1 = mn1;

            float rs0 = 0.0f, rs1 = 0.0f;
#pragma unroll
            for (int nt = 0; nt < 8; ++nt) {
                s[nt][0] = __expf(s[nt][0] - mn0);
                s[nt][1] = __expf(s[nt][1] - mn0);
                s[nt][2] = __expf(s[nt][2] - mn1);
                s[nt][3] = __expf(s[nt][3] - mn1);
                rs0 += s[nt][0] + s[nt][1];
                rs1 += s[nt][2] + s[nt][3];
            }
            rs0 += __shfl_xor_sync(0xffffffffu, rs0, 1);
            rs0 += __shfl_xor_sync(0xffffffffu, rs0, 2);
            rs1 += __shfl_xor_sync(0xffffffffu, rs1, 1);
            rs1 += __shfl_xor_sync(0xffffffffu, rs1, 2);
            l0 = l0 * al0 + rs0;
            l1 = l1 * al1 + rs1;

#pragma unroll
            for (int nt = 0; nt < 16; ++nt) {
                oa[nt][0] *= al0; oa[nt][1] *= al0;
                oa[nt][2] *= al1; oa[nt][3] *= al1;
            }

            uint32_t ap[4][4];
#pragma unroll
            for (int kc = 0; kc < 4; ++kc) {
                __half2 t0 = __floats2half2_rn(s[2 * kc][0], s[2 * kc][1]);
                __half2 t1 = __floats2half2_rn(s[2 * kc][2], s[2 * kc][3]);
                __half2 t2 = __floats2half2_rn(s[2 * kc + 1][0], s[2 * kc + 1][1]);
                __half2 t3 = __floats2half2_rn(s[2 * kc + 1][2], s[2 * kc + 1][3]);
                ap[kc][0] = *(uint32_t*)&t0;
                ap[kc][1] = *(uint32_t*)&t1;
                ap[kc][2] = *(uint32_t*)&t2;
                ap[kc][3] = *(uint32_t*)&t3;
            }

#pragma unroll
            for (int kc = 0; kc < 4; ++kc) {
#pragma unroll
                for (int ntp = 0; ntp < 8; ++ntp) {
                    uint32_t bv[4];
                    ldsm_x4t(bv, vaddr + (kc * 16 * KS_STRIDE + ntp * 16) * 2);
                    mma16816(oa[ntp * 2], ap[kc], &bv[0]);
                    mma16816(oa[ntp * 2 + 1], ap[kc], &bv[2]);
                }
            }
        }

        __syncthreads();         // all warps done reading V(t)
        if (t + 1 < ntiles) LOAD_V(t + 1);
        cp_commit();             // lands during next tile's QK
    }

    float inv0 = 1.0f / l0, inv1 = 1.0f / l1;
    size_t tok0 = (size_t)b * SEQ + qb + r0;
    __half* d0 = o + tok0 * 2048 + h * 128 + c2;
    __half* d1 = d0 + (size_t)8 * 2048;
#pragma unroll
    for (int nt = 0; nt < 16; ++nt) {
        *(__half2*)(d0 + nt * 8) = __floats2half2_rn(oa[nt][0] * inv0, oa[nt][1] * inv0);
        *(__half2*)(d1 + nt * 8) = __floats2half2_rn(oa[nt][2] * inv1, oa[nt][3] * inv1);
    }
}

// ----------------------------------------------------------------------------
extern "C" void kernel_launch(void* const* d_in, const int* in_sizes, int n_in,
                              void* d_out, int out_size)
{
    const float* x   = (const float*)d_in[0];
    const float* Wq  = (const float*)d_in[1];
    const float* Wkv = (const float*)d_in[2];
    const float* Wkr = (const float*)d_in[3];
    const float* Wkn = (const float*)d_in[4];
    const float* Wv  = (const float*)d_in[5];
    const float* Wo  = (const float*)d_in[6];
    const float* gq  = (const float*)d_in[7];
    const float* gk  = (const float*)d_in[8];
    float* out = (float*)d_out;

    float *q, *k;
    __half *hx, *hWq, *hWkv, *hWkrn, *hWv, *hWo, *hlat, *hattn, *hq, *hk, *hv;
    cudaGetSymbolAddress((void**)&q,    g_q);
    cudaGetSymbolAddress((void**)&k,    g_k);
    cudaGetSymbolAddress((void**)&hx,   h_x);
    cudaGetSymbolAddress((void**)&hWq,  h_Wq);
    cudaGetSymbolAddress((void**)&hWkv, h_Wkv);
    cudaGetSymbolAddress((void**)&hWkrn, h_Wkrn);
    cudaGetSymbolAddress((void**)&hWv,  h_Wv);
    cudaGetSymbolAddress((void**)&hWo,  h_Wo);
    cudaGetSymbolAddress((void**)&hlat, h_lat);
    cudaGetSymbolAddress((void**)&hattn, h_attn);
    cudaGetSymbolAddress((void**)&hq,   h_q);
    cudaGetSymbolAddress((void**)&hk,   h_k);
    cudaGetSymbolAddress((void**)&hv,   h_v);

    dim3 blk(256);

    // fused conversions (1 launch)
    convert_all<<<CV_BLOCKS, blk>>>(x, Wq, Wkv, Wkr, Wkn, Wv, Wo,
                                    hx, hWq, hWkv, hWkrn, hWv, hWo);

    // q = x @ Wq -> fp32 [tok][h*128+d]
    hgemm128<float><<<dim3(16, 32), blk>>>(hx, hWq, q, TOKS, 2048, HIDN,
                                           11, 2048, 0, 2048);
    // lat = x @ Wkv -> fp16 directly
    hgemm128<__half><<<dim3(4, 32), blk>>>(hx, hWkv, hlat, TOKS, DLAT, HIDN,
                                           9, DLAT, 0, DLAT);
    // k = lat @ Wkrn (combined, pre-interleaved) -> fp32 [tok][h*128+d]
    hgemm128<float><<<dim3(16, 32), blk>>>(hlat, hWkrn, k, TOKS, 2048, DLAT,
                                           11, 2048, 0, 2048);
    // v = lat @ Wv -> fp16 [tok][h][d] directly (same rounding as old pack_h)
    hgemm128<__half><<<dim3(16, 32), blk>>>(hlat, hWv, hv, TOKS, 2048, DLAT,
                                            11, 2048, 0, 2048);

    // norm + repack q/k to fp16 [b][h][s][d]; 1/sqrt(D) folded into q
    rmsnorm_h<<<TOKS * NH / 8, blk>>>(q, gq, hq, 0.08838834764831845f);
    rmsnorm_h<<<TOKS * NH / 8, blk>>>(k, gk, hk, 1.0f);

    // causal attention -> h_attn [tok][2048] fp16
    attn_mma<<<dim3(SEQ / 128, NB * NH), blk>>>(hq, hk, hv, hattn);

    // out = attn @ Wo
    hgemm128<float><<<dim3(16, 32), blk>>>(hattn, hWo, out, TOKS, 2048, 2048,
                                           11, 2048, 0, 2048);
}

// round 11
// speedup vs baseline: 10.1272x; 1.0488x over previous
#include <cuda_runtime.h>
#include <cuda_fp16.h>
#include <math.h>
#include <stdint.h>

// Problem constants
#define TOKS 4096      // B*S = 2*2048
#define SEQ  2048
#define NB   2
#define NH   16
#define HD   128
#define HIDN 2048
#define DLAT 512

// fp32 scratch (GEMM outputs pre-norm)
__device__ float g_q[TOKS * 2048];
__device__ float g_k[TOKS * 2048];

// fp16 scratch
__device__ __half h_x[TOKS * HIDN];
__device__ __half h_Wq[HIDN * 2048];
__device__ __half h_Wkv[HIDN * DLAT];
__device__ __half h_Wkrn[DLAT * 2048];   // combined head-interleaved kr|kn weight
__device__ __half h_Wv[DLAT * 2048];
__device__ __half h_Wo[2048 * HIDN];
__device__ __half h_lat[TOKS * DLAT];
__device__ __half h_attn[TOKS * 2048];
__device__ __half h_q[TOKS * 2048];   // [b][h][s][d], pre-scaled by log2e/sqrt(D)
__device__ __half h_k[TOKS * 2048];   // [b][h][s][d]
__device__ __half h_v[TOKS * 2048];   // [tok][h][d]  (GEMM-direct)

// ----------------------------------------------------------------------------
// Fused fp32->fp16 conversion of x + all weights, with Wkr/Wkn column remap
// into the combined h_Wkrn.
// ----------------------------------------------------------------------------
#define V4_X    2097152L
#define V4_WQ   1048576L
#define V4_WKV   262144L
#define V4_WKR   131072L
#define V4_WKN   131072L
#define V4_WV    262144L
#define V4_WO   1048576L
#define CV_B0 (V4_X)
#define CV_B1 (CV_B0 + V4_WQ)
#define CV_B2 (CV_B1 + V4_WKV)
#define CV_B3 (CV_B2 + V4_WKR)
#define CV_B4 (CV_B3 + V4_WKN)
#define CV_B5 (CV_B4 + V4_WV)
#define CV_B6 (CV_B5 + V4_WO)
#define CV_BLOCKS (CV_B6 / 256)

__device__ __forceinline__ void cvt4(const float* s, __half* d, long si, long di)
{
    float4 v = *(const float4*)(s + si * 4);
    *(__half2*)(d + di * 4)     = __floats2half2_rn(v.x, v.y);
    *(__half2*)(d + di * 4 + 2) = __floats2half2_rn(v.z, v.w);
}

__global__ __launch_bounds__(256)
void convert_all(const float* __restrict__ x,  const float* __restrict__ Wq,
                 const float* __restrict__ Wkv, const float* __restrict__ Wkr,
                 const float* __restrict__ Wkn, const float* __restrict__ Wv,
                 const float* __restrict__ Wo,
                 __half* __restrict__ hx,  __half* __restrict__ hWq,
                 __half* __restrict__ hWkv, __half* __restrict__ hWkrn,
                 __half* __restrict__ hWv, __half* __restrict__ hWo)
{
    long v4 = (long)blockIdx.x * 256 + threadIdx.x;
    if (v4 < CV_B0)      cvt4(x,   hx,   v4, v4);
    else if (v4 < CV_B1) cvt4(Wq,  hWq,  v4 - CV_B0, v4 - CV_B0);
    else if (v4 < CV_B2) cvt4(Wkv, hWkv, v4 - CV_B1, v4 - CV_B1);
    else if (v4 < CV_B3) {
        long e = v4 - CV_B2;            // vec4 within Wkr [512 x 1024]
        long row = e >> 8;
        int j = (int)(e & 255) * 4;
        int h = j >> 6, c = j & 63;
        long dst = row * 2048 + h * 128 + c;
        cvt4(Wkr, hWkrn, e, dst >> 2);
    } else if (v4 < CV_B4) {
        long e = v4 - CV_B3;            // vec4 within Wkn [512 x 1024]
        long row = e >> 8;
        int j = (int)(e & 255) * 4;
        int h = j >> 6, c = j & 63;
        long dst = row * 2048 + h * 128 + 64 + c;
        cvt4(Wkn, hWkrn, e, dst >> 2);
    }
    else if (v4 < CV_B5) cvt4(Wv, hWv, v4 - CV_B4, v4 - CV_B4);
    else                 cvt4(Wo, hWo, v4 - CV_B5, v4 - CV_B5);
}

// ----------------------------------------------------------------------------
#define AS_STRIDE 40    // halves
#define BS_STRIDE 136   // halves
#define A_STG (128 * AS_STRIDE)   // 5120 halves per stage
#define B_STG (32 * BS_STRIDE)    // 4352 halves per stage

__device__ __forceinline__ uint32_t sptr(const void* p)
{
    return (uint32_t)__cvta_generic_to_shared(p);
}
__device__ __forceinline__ void ldsm_x4(uint32_t* r, uint32_t addr)
{
    asm volatile("ldmatrix.sync.aligned.m8n8.x4.shared.b16 {%0,%1,%2,%3}, [%4];\n"
                 : "=r"(r[0]), "=r"(r[1]), "=r"(r[2]), "=r"(r[3]) : "r"(addr));
}
__device__ __forceinline__ void ldsm_x2t(uint32_t* r, uint32_t addr)
{
    asm volatile("ldmatrix.sync.aligned.m8n8.x2.trans.shared.b16 {%0,%1}, [%2];\n"
                 : "=r"(r[0]), "=r"(r[1]) : "r"(addr));
}
__device__ __forceinline__ void ldsm_x4t(uint32_t* r, uint32_t addr)
{
    asm volatile("ldmatrix.sync.aligned.m8n8.x4.trans.shared.b16 {%0,%1,%2,%3}, [%4];\n"
                 : "=r"(r[0]), "=r"(r[1]), "=r"(r[2]), "=r"(r[3]) : "r"(addr));
}
__device__ __forceinline__ void mma16816(float* c, const uint32_t* a, const uint32_t* b)
{
    asm volatile(
        "mma.sync.aligned.m16n8k16.row.col.f32.f16.f16.f32 "
        "{%0,%1,%2,%3}, {%4,%5,%6,%7}, {%8,%9}, {%0,%1,%2,%3};\n"
        : "+f"(c[0]), "+f"(c[1]), "+f"(c[2]), "+f"(c[3])
        : "r"(a[0]), "r"(a[1]), "r"(a[2]), "r"(a[3]), "r"(b[0]), "r"(b[1]));
}
__device__ __forceinline__ void cp16(uint32_t saddr, const void* g)
{
    asm volatile("cp.async.cg.shared.global [%0], [%1], 16;\n" :: "r"(saddr), "l"(g));
}
__device__ __forceinline__ void cp_commit()
{
    asm volatile("cp.async.commit_group;\n");
}
template <int N>
__device__ __forceinline__ void cp_wait()
{
    asm volatile("cp.async.wait_group %0;\n" :: "n"(N));
}

// ----------------------------------------------------------------------------
// Tensor-core GEMM: C (fp32 or fp16) = A fp16 @ B fp16, 128x128 block tile,
// BK=32, STATIC-smem 2-stage cp.async pipeline, ONE __syncthreads per iter.
// Epilogue column remap: out_col = (col>>lgGroup)*outstride + base + (col&mask)
// ----------------------------------------------------------------------------
template <typename T>
__global__ __launch_bounds__(256, 2)
void hgemm128(const __half* __restrict__ A, const __half* __restrict__ B,
              T* __restrict__ C, int M, int N, int K,
              int lgGroup, int outstride, int base, int ldc)
{
    __shared__ __half Asb[2 * A_STG];
    __shared__ __half Bsb[2 * B_STG];

    const int tid  = threadIdx.x;
    const int warp = tid >> 5;
    const int lane = tid & 31;
    const int bm = blockIdx.y * 128;
    const int bn = blockIdx.x * 128;
    const int wm = (warp & 1) * 64;
    const int wn = (warp >> 1) * 32;

    float c[4][4][4];
#pragma unroll
    for (int mt = 0; mt < 4; ++mt)
#pragma unroll
        for (int nt = 0; nt < 4; ++nt)
#pragma unroll
            for (int i = 0; i < 4; ++i) c[mt][nt][i] = 0.0f;

    const int arow0 = tid >> 2,  akc = (tid & 3) * 8;
    const int brow0 = tid >> 4,  bnc = (tid & 15) * 8;

    const uint32_t a_base = sptr(&Asb[(wm + (lane & 15)) * AS_STRIDE + (lane >> 4) * 8]);
    const uint32_t b_base = sptr(&Bsb[(lane & 15) * BS_STRIDE + wn]);

    const int nk = K >> 5;

#define GEMM_LOAD_STAGE(s, k0)                                                        \
    do {                                                                              \
        cp16(sptr(&Asb[(s) * A_STG + arow0 * AS_STRIDE + akc]),                       \
             A + (size_t)(bm + arow0) * K + (k0) + akc);                              \
        cp16(sptr(&Asb[(s) * A_STG + (arow0 + 64) * AS_STRIDE + akc]),                \
             A + (size_t)(bm + arow0 + 64) * K + (k0) + akc);                         \
        cp16(sptr(&Bsb[(s) * B_STG + brow0 * BS_STRIDE + bnc]),                       \
             B + (size_t)((k0) + brow0) * N + bn + bnc);                              \
        cp16(sptr(&Bsb[(s) * B_STG + (brow0 + 16) * BS_STRIDE + bnc]),                \
             B + (size_t)((k0) + brow0 + 16) * N + bn + bnc);                         \
    } while (0)

    GEMM_LOAD_STAGE(0, 0);
    cp_commit();

    for (int t = 0; t < nk; ++t) {
        cp_wait<0>();
        __syncthreads();
        if (t + 1 < nk) {
            GEMM_LOAD_STAGE((t + 1) & 1, (t + 1) << 5);
            cp_commit();
        }

        const uint32_t ab = a_base + (t & 1) * A_STG * 2;
        const uint32_t bb = b_base + (t & 1) * B_STG * 2;
#pragma unroll
        for (int kt = 0; kt < 2; ++kt) {
            uint32_t a[4][4], b[4][2];
#pragma unroll
            for (int mt = 0; mt < 4; ++mt)
                ldsm_x4(a[mt], ab + (mt * 16 * AS_STRIDE + kt * 16) * 2);
#pragma unroll
            for (int nt = 0; nt < 4; ++nt)
                ldsm_x2t(b[nt], bb + (kt * 16 * BS_STRIDE + nt * 8) * 2);
#pragma unroll
            for (int mt = 0; mt < 4; ++mt)
#pragma unroll
                for (int nt = 0; nt < 4; ++nt)
                    mma16816(c[mt][nt], a[mt], b[nt]);
        }
    }

    const int gmask = (1 << lgGroup) - 1;
    const int gid = lane >> 2;
    const int tig = lane & 3;
#pragma unroll
    for (int mt = 0; mt < 4; ++mt) {
#pragma unroll
        for (int nt = 0; nt < 4; ++nt) {
            int col = bn + wn + nt * 8 + tig * 2;
            int oc = ((col >> lgGroup) * outstride) + base + (col & gmask);
            int r0 = bm + wm + mt * 16 + gid;
            if (sizeof(T) == 4) {
                *(float2*)&((float*)C)[(size_t)r0 * ldc + oc] =
                    make_float2(c[mt][nt][0], c[mt][nt][1]);
                *(float2*)&((float*)C)[(size_t)(r0 + 8) * ldc + oc] =
                    make_float2(c[mt][nt][2], c[mt][nt][3]);
            } else {
                *(__half2*)&((__half*)C)[(size_t)r0 * ldc + oc] =
                    __floats2half2_rn(c[mt][nt][0], c[mt][nt][1]);
                *(__half2*)&((__half*)C)[(size_t)(r0 + 8) * ldc + oc] =
                    __floats2half2_rn(c[mt][nt][2], c[mt][nt][3]);
            }
        }
    }
}

// ----------------------------------------------------------------------------
// RMSNorm over D=128 (+ extra output scale) + fp16 repack -> [b][h][s][d].
// ----------------------------------------------------------------------------
__global__ __launch_bounds__(256)
void rmsnorm_h(const float* __restrict__ in, const float* __restrict__ g,
               __half* __restrict__ out, float pscale)
{
    int row = blockIdx.x * 8 + (threadIdx.x >> 5);   // row = tok*16 + h
    int lane = threadIdx.x & 31;
    float4 v = *((const float4*)(in + (size_t)row * 128) + lane);
    float ss = v.x * v.x + v.y * v.y + v.z * v.z + v.w * v.w;
#pragma unroll
    for (int o = 16; o; o >>= 1) ss += __shfl_xor_sync(0xffffffffu, ss, o);
    float r = rsqrtf(ss * (1.0f / 128.0f) + 1e-6f) * pscale;
    float4 gv = ((const float4*)g)[lane];
    int tok = row >> 4, h = row & 15;
    int b = tok >> 11, s = tok & 2047;
    __half* dst = out + ((size_t)(b * 16 + h) * 2048 + s) * 128 + lane * 4;
    *(__half2*)dst       = __floats2half2_rn(v.x * r * gv.x, v.y * r * gv.y);
    *(__half2*)(dst + 2) = __floats2half2_rn(v.z * r * gv.z, v.w * r * gv.w);
}

// ----------------------------------------------------------------------------
// Tensor-core causal flash attention, FIXED-SHIFT softmax (no online max):
//   scores s are in log2 domain (log2e/sqrt(D) folded into Q);
//   |s| <= sqrt(128)*log2e = 16.32, so p = exp2(s - C2) <= 2^13.4 < fp16 max.
//   No max tracking, no rescale, l reduced once after the loop.
// Single-buffered cp.async pipeline as round 10.
// ----------------------------------------------------------------------------
#define KS_STRIDE 136
#define SOFTMAX_SHIFT 2.8853900817779268f   /* 2*log2e: p <= 2^13.4, >= typ 2^-3 */

__global__ __launch_bounds__(256)
void attn_mma(const __half* __restrict__ q, const __half* __restrict__ k,
              const __half* __restrict__ v, __half* __restrict__ o)
{
    __shared__ __half Ks[64 * KS_STRIDE];
    __shared__ __half Vs[64 * KS_STRIDE];

    const int bh = blockIdx.y;
    const int b = bh >> 4, h = bh & 15;
    const int qb = ((int)gridDim.x - 1 - (int)blockIdx.x) * 128;   // heavy first
    const int tid = threadIdx.x;
    const int warp = tid >> 5, lane = tid & 31;
    const size_t base = (size_t)bh * SEQ * HD;
    const int r0 = warp * 16 + (lane >> 2);
    const int w0 = qb + warp * 16;
    const int c2 = (lane & 3) * 2;

    // Q a-frags (pre-scaled by log2e/sqrt(D) in rmsnorm)
    uint32_t aq[8][4];
    {
        const __half* q0 = q + base + (size_t)(qb + r0) * HD;
#pragma unroll
        for (int kc = 0; kc < 8; ++kc) {
            aq[kc][0] = *(const uint32_t*)(q0 + kc * 16 + c2);
            aq[kc][1] = *(const uint32_t*)(q0 + 8 * HD + kc * 16 + c2);
            aq[kc][2] = *(const uint32_t*)(q0 + kc * 16 + c2 + 8);
            aq[kc][3] = *(const uint32_t*)(q0 + 8 * HD + kc * 16 + c2 + 8);
        }
    }

    float oa[16][4];
#pragma unroll
    for (int nt = 0; nt < 16; ++nt)
#pragma unroll
        for (int i = 0; i < 4; ++i) oa[nt][i] = 0.0f;
    float l0 = 0.0f, l1 = 0.0f;          // per-lane partial sums of p

    const uint32_t kaddr = sptr(&Ks[(lane & 7) * KS_STRIDE + (lane >> 3) * 8]);
    const uint32_t vaddr = sptr(&Vs[(lane & 15) * KS_STRIDE + (lane >> 4) * 8]);

#define LOAD_K(t_)                                                                 \
    do {                                                                           \
        const __half* kg_ = k + base + (size_t)(t_) * 64 * HD;                     \
        for (int i = tid; i < 1024; i += 256) {                                    \
            int r_ = i >> 4, c_ = (i & 15) * 8;                                    \
            cp16(sptr(&Ks[r_ * KS_STRIDE + c_]), kg_ + r_ * HD + c_);              \
        }                                                                          \
    } while (0)
#define LOAD_V(t_)                                                                 \
    do {                                                                           \
        const __half* vg_ = v + ((size_t)(b * SEQ + (t_) * 64) * 16 + h) * 128;    \
        for (int i = tid; i < 1024; i += 256) {                                    \
            int r_ = i >> 4, c_ = (i & 15) * 8;                                    \
            cp16(sptr(&Vs[r_ * KS_STRIDE + c_]), vg_ + r_ * 2048 + c_);            \
        }                                                                          \
    } while (0)

    const int ntiles = qb / 64 + 2;
    LOAD_K(0); cp_commit();
    LOAD_V(0); cp_commit();

    for (int t = 0; t < ntiles; ++t) {
        const int j0 = t * 64;
        const bool live = (j0 <= w0 + 15);

        cp_wait<1>();            // K(t) resident (V(t) may still be in flight)
        __syncthreads();

        float s[8][4];
        if (live) {
#pragma unroll
            for (int nt = 0; nt < 8; ++nt) {
                s[nt][0] = s[nt][1] = s[nt][2] = s[nt][3] = 0.0f;
                uint32_t bk[4][4];
#pragma unroll
                for (int g = 0; g < 4; ++g)
                    ldsm_x4(bk[g], kaddr + (nt * 8 * KS_STRIDE + g * 32) * 2);
#pragma unroll
                for (int kc = 0; kc < 8; ++kc)
                    mma16816(s[nt], aq[kc], &bk[kc >> 1][(kc & 1) * 2]);
            }
        }

        cp_wait<0>();            // V(t) resident; K buffer free after barrier
        __syncthreads();
        if (t + 1 < ntiles) LOAD_K(t + 1);
        cp_commit();             // lands during softmax+PV

        if (live) {
            if (j0 + 63 > w0) {  // diagonal masking
#pragma unroll
                for (int nt = 0; nt < 8; ++nt) {
#pragma unroll
                    for (int i = 0; i < 4; ++i) {
                        int col = j0 + nt * 8 + c2 + (i & 1);
                        int rowq = qb + r0 + (i >> 1) * 8;
                        if (col > rowq) s[nt][i] = -1e30f;
                    }
                }
            }

            // fixed-shift exp2: p = 2^(s - C2); accumulate l per-lane
#pragma unroll
            for (int nt = 0; nt < 8; ++nt) {
                s[nt][0] = exp2f(s[nt][0] - SOFTMAX_SHIFT);
                s[nt][1] = exp2f(s[nt][1] - SOFTMAX_SHIFT);
                s[nt][2] = exp2f(s[nt][2] - SOFTMAX_SHIFT);
                s[nt][3] = exp2f(s[nt][3] - SOFTMAX_SHIFT);
                l0 += s[nt][0] + s[nt][1];
                l1 += s[nt][2] + s[nt][3];
            }

            // pack P -> fp16 a-frags
            uint32_t ap[4][4];
#pragma unroll
            for (int kc = 0; kc < 4; ++kc) {
                __half2 t0 = __floats2half2_rn(s[2 * kc][0], s[2 * kc][1]);
                __half2 t1 = __floats2half2_rn(s[2 * kc][2], s[2 * kc][3]);
                __half2 t2 = __floats2half2_rn(s[2 * kc + 1][0], s[2 * kc + 1][1]);
                __half2 t3 = __floats2half2_rn(s[2 * kc + 1][2], s[2 * kc + 1][3]);
                ap[kc][0] = *(uint32_t*)&t0;
                ap[kc][1] = *(uint32_t*)&t1;
                ap[kc][2] = *(uint32_t*)&t2;
                ap[kc][3] = *(uint32_t*)&t3;
            }

            // O += P V (no rescale ever needed)
#pragma unroll
            for (int kc = 0; kc < 4; ++kc) {
#pragma unroll
                for (int ntp = 0; ntp < 8; ++ntp) {
                    uint32_t bv[4];
                    ldsm_x4t(bv, vaddr + (kc * 16 * KS_STRIDE + ntp * 16) * 2);
                    mma16816(oa[ntp * 2], ap[kc], &bv[0]);
                    mma16816(oa[ntp * 2 + 1], ap[kc], &bv[2]);
                }
            }
        }

        __syncthreads();         // all warps done reading V(t)
        if (t + 1 < ntiles) LOAD_V(t + 1);
        cp_commit();             // lands during next tile's QK
    }

    // single row-sum reduction of l (4 lanes per row), then normalize
    l0 += __shfl_xor_sync(0xffffffffu, l0, 1);
    l0 += __shfl_xor_sync(0xffffffffu, l0, 2);
    l1 += __shfl_xor_sync(0xffffffffu, l1, 1);
    l1 += __shfl_xor_sync(0xffffffffu, l1, 2);
    float inv0 = 1.0f / l0, inv1 = 1.0f / l1;
    size_t tok0 = (size_t)b * SEQ + qb + r0;
    __half* d0 = o + tok0 * 2048 + h * 128 + c2;
    __half* d1 = d0 + (size_t)8 * 2048;
#pragma unroll
    for (int nt = 0; nt < 16; ++nt) {
        *(__half2*)(d0 + nt * 8) = __floats2half2_rn(oa[nt][0] * inv0, oa[nt][1] * inv0);
        *(__half2*)(d1 + nt * 8) = __floats2half2_rn(oa[nt][2] * inv1, oa[nt][3] * inv1);
    }
}

// ----------------------------------------------------------------------------
extern "C" void kernel_launch(void* const* d_in, const int* in_sizes, int n_in,
                              void* d_out, int out_size)
{
    const float* x   = (const float*)d_in[0];
    const float* Wq  = (const float*)d_in[1];
    const float* Wkv = (const float*)d_in[2];
    const float* Wkr = (const float*)d_in[3];
    const float* Wkn = (const float*)d_in[4];
    const float* Wv  = (const float*)d_in[5];
    const float* Wo  = (const float*)d_in[6];
    const float* gq  = (const float*)d_in[7];
    const float* gk  = (const float*)d_in[8];
    float* out = (float*)d_out;

    float *q, *k;
    __half *hx, *hWq, *hWkv, *hWkrn, *hWv, *hWo, *hlat, *hattn, *hq, *hk, *hv;
    cudaGetSymbolAddress((void**)&q,    g_q);
    cudaGetSymbolAddress((void**)&k,    g_k);
    cudaGetSymbolAddress((void**)&hx,   h_x);
    cudaGetSymbolAddress((void**)&hWq,  h_Wq);
    cudaGetSymbolAddress((void**)&hWkv, h_Wkv);
    cudaGetSymbolAddress((void**)&hWkrn, h_Wkrn);
    cudaGetSymbolAddress((void**)&hWv,  h_Wv);
    cudaGetSymbolAddress((void**)&hWo,  h_Wo);
    cudaGetSymbolAddress((void**)&hlat, h_lat);
    cudaGetSymbolAddress((void**)&hattn, h_attn);
    cudaGetSymbolAddress((void**)&hq,   h_q);
    cudaGetSymbolAddress((void**)&hk,   h_k);
    cudaGetSymbolAddress((void**)&hv,   h_v);

    dim3 blk(256);

    // fused conversions (1 launch)
    convert_all<<<CV_BLOCKS, blk>>>(x, Wq, Wkv, Wkr, Wkn, Wv, Wo,
                                    hx, hWq, hWkv, hWkrn, hWv, hWo);

    // q = x @ Wq -> fp32 [tok][h*128+d]
    hgemm128<float><<<dim3(16, 32), blk>>>(hx, hWq, q, TOKS, 2048, HIDN,
                                           11, 2048, 0, 2048);
    // lat = x @ Wkv -> fp16 directly
    hgemm128<__half><<<dim3(4, 32), blk>>>(hx, hWkv, hlat, TOKS, DLAT, HIDN,
                                           9, DLAT, 0, DLAT);
    // k = lat @ Wkrn (combined, pre-interleaved) -> fp32 [tok][h*128+d]
    hgemm128<float><<<dim3(16, 32), blk>>>(hlat, hWkrn, k, TOKS, 2048, DLAT,
                                           11, 2048, 0, 2048);
    // v = lat @ Wv -> fp16 [tok][h][d] directly
    hgemm128<__half><<<dim3(16, 32), blk>>>(hlat, hWv, hv, TOKS, 2048, DLAT,
                                            11, 2048, 0, 2048);

    // norm + repack q/k to fp16 [b][h][s][d];
    // q gets log2e/sqrt(D) folded in (scores land in log2 domain)
    rmsnorm_h<<<TOKS * NH / 8, blk>>>(q, gq, hq, 0.12751677572069723f);
    rmsnorm_h<<<TOKS * NH / 8, blk>>>(k, gk, hk, 1.0f);

    // causal attention -> h_attn [tok][2048] fp16
    attn_mma<<<dim3(SEQ / 128, NB * NH), blk>>>(hq, hk, hv, hattn);

    // out = attn @ Wo
    hgemm128<float><<<dim3(16, 32), blk>>>(hattn, hWo, out, TOKS, 2048, 2048,
                                           11, 2048, 0, 2048);
}

// round 12
// speedup vs baseline: 10.3991x; 1.0268x over previous
#include <cuda_runtime.h>
#include <cuda_fp16.h>
#include <math.h>
#include <stdint.h>

// Problem constants
#define TOKS 4096      // B*S = 2*2048
#define SEQ  2048
#define NB   2
#define NH   16
#define HD   128
#define HIDN 2048
#define DLAT 512

// fp32 scratch (GEMM outputs pre-norm)
__device__ float g_q[TOKS * 2048];
__device__ float g_k[TOKS * 2048];

// fp16 scratch
__device__ __half h_x[TOKS * HIDN];
__device__ __half h_Wq[HIDN * 2048];
__device__ __half h_Wkv[HIDN * DLAT];
__device__ __half h_Wkrn[DLAT * 2048];   // combined head-interleaved kr|kn weight
__device__ __half h_Wv[DLAT * 2048];
__device__ __half h_Wo[2048 * HIDN];
__device__ __half h_lat[TOKS * DLAT];
__device__ __half h_attn[TOKS * 2048];
__device__ __half h_q[TOKS * 2048];   // [b][h][s][d], pre-scaled by log2e/sqrt(D)
__device__ __half h_k[TOKS * 2048];   // [b][h][s][d]
__device__ __half h_v[TOKS * 2048];   // [tok][h][d]  (GEMM-direct)

// ----------------------------------------------------------------------------
// Fused fp32->fp16 conversion of x + all weights, with Wkr/Wkn column remap
// into the combined h_Wkrn.
// ----------------------------------------------------------------------------
#define V4_X    2097152L
#define V4_WQ   1048576L
#define V4_WKV   262144L
#define V4_WKR   131072L
#define V4_WKN   131072L
#define V4_WV    262144L
#define V4_WO   1048576L
#define CV_B0 (V4_X)
#define CV_B1 (CV_B0 + V4_WQ)
#define CV_B2 (CV_B1 + V4_WKV)
#define CV_B3 (CV_B2 + V4_WKR)
#define CV_B4 (CV_B3 + V4_WKN)
#define CV_B5 (CV_B4 + V4_WV)
#define CV_B6 (CV_B5 + V4_WO)
#define CV_BLOCKS (CV_B6 / 256)

__device__ __forceinline__ void cvt4(const float* s, __half* d, long si, long di)
{
    float4 v = *(const float4*)(s + si * 4);
    *(__half2*)(d + di * 4)     = __floats2half2_rn(v.x, v.y);
    *(__half2*)(d + di * 4 + 2) = __floats2half2_rn(v.z, v.w);
}

__global__ __launch_bounds__(256)
void convert_all(const float* __restrict__ x,  const float* __restrict__ Wq,
                 const float* __restrict__ Wkv, const float* __restrict__ Wkr,
                 const float* __restrict__ Wkn, const float* __restrict__ Wv,
                 const float* __restrict__ Wo,
                 __half* __restrict__ hx,  __half* __restrict__ hWq,
                 __half* __restrict__ hWkv, __half* __restrict__ hWkrn,
                 __half* __restrict__ hWv, __half* __restrict__ hWo)
{
    long v4 = (long)blockIdx.x * 256 + threadIdx.x;
    if (v4 < CV_B0)      cvt4(x,   hx,   v4, v4);
    else if (v4 < CV_B1) cvt4(Wq,  hWq,  v4 - CV_B0, v4 - CV_B0);
    else if (v4 < CV_B2) cvt4(Wkv, hWkv, v4 - CV_B1, v4 - CV_B1);
    else if (v4 < CV_B3) {
        long e = v4 - CV_B2;            // vec4 within Wkr [512 x 1024]
        long row = e >> 8;
        int j = (int)(e & 255) * 4;
        int h = j >> 6, c = j & 63;
        long dst = row * 2048 + h * 128 + c;
        cvt4(Wkr, hWkrn, e, dst >> 2);
    } else if (v4 < CV_B4) {
        long e = v4 - CV_B3;            // vec4 within Wkn [512 x 1024]
        long row = e >> 8;
        int j = (int)(e & 255) * 4;
        int h = j >> 6, c = j & 63;
        long dst = row * 2048 + h * 128 + 64 + c;
        cvt4(Wkn, hWkrn, e, dst >> 2);
    }
    else if (v4 < CV_B5) cvt4(Wv, hWv, v4 - CV_B4, v4 - CV_B4);
    else                 cvt4(Wo, hWo, v4 - CV_B5, v4 - CV_B5);
}

// ----------------------------------------------------------------------------
#define AS_STRIDE 40    // halves
#define BS_STRIDE 136   // halves
#define A_STG (128 * AS_STRIDE)   // 5120 halves per stage
#define B_STG (32 * BS_STRIDE)    // 4352 halves per stage

__device__ __forceinline__ uint32_t sptr(const void* p)
{
    return (uint32_t)__cvta_generic_to_shared(p);
}
__device__ __forceinline__ void ldsm_x4(uint32_t* r, uint32_t addr)
{
    asm volatile("ldmatrix.sync.aligned.m8n8.x4.shared.b16 {%0,%1,%2,%3}, [%4];\n"
                 : "=r"(r[0]), "=r"(r[1]), "=r"(r[2]), "=r"(r[3]) : "r"(addr));
}
__device__ __forceinline__ void ldsm_x2t(uint32_t* r, uint32_t addr)
{
    asm volatile("ldmatrix.sync.aligned.m8n8.x2.trans.shared.b16 {%0,%1}, [%2];\n"
                 : "=r"(r[0]), "=r"(r[1]) : "r"(addr));
}
__device__ __forceinline__ void ldsm_x4t(uint32_t* r, uint32_t addr)
{
    asm volatile("ldmatrix.sync.aligned.m8n8.x4.trans.shared.b16 {%0,%1,%2,%3}, [%4];\n"
                 : "=r"(r[0]), "=r"(r[1]), "=r"(r[2]), "=r"(r[3]) : "r"(addr));
}
__device__ __forceinline__ void mma16816(float* c, const uint32_t* a, const uint32_t* b)
{
    asm volatile(
        "mma.sync.aligned.m16n8k16.row.col.f32.f16.f16.f32 "
        "{%0,%1,%2,%3}, {%4,%5,%6,%7}, {%8,%9}, {%0,%1,%2,%3};\n"
        : "+f"(c[0]), "+f"(c[1]), "+f"(c[2]), "+f"(c[3])
        : "r"(a[0]), "r"(a[1]), "r"(a[2]), "r"(a[3]), "r"(b[0]), "r"(b[1]));
}
__device__ __forceinline__ void cp16(uint32_t saddr, const void* g)
{
    asm volatile("cp.async.cg.shared.global [%0], [%1], 16;\n" :: "r"(saddr), "l"(g));
}
__device__ __forceinline__ void cp_commit()
{
    asm volatile("cp.async.commit_group;\n");
}
template <int N>
__device__ __forceinline__ void cp_wait()
{
    asm volatile("cp.async.wait_group %0;\n" :: "n"(N));
}

// ----------------------------------------------------------------------------
// Tensor-core GEMM: C (fp32 or fp16) = A fp16 @ B fp16, 128x128 block tile,
// BK=32, STATIC-smem 2-stage cp.async pipeline, ONE __syncthreads per iter.
// Epilogue column remap: out_col = (col>>lgGroup)*outstride + base + (col&mask)
// ----------------------------------------------------------------------------
template <typename T>
__global__ __launch_bounds__(256, 2)
void hgemm128(const __half* __restrict__ A, const __half* __restrict__ B,
              T* __restrict__ C, int M, int N, int K,
              int lgGroup, int outstride, int base, int ldc)
{
    __shared__ __half Asb[2 * A_STG];
    __shared__ __half Bsb[2 * B_STG];

    const int tid  = threadIdx.x;
    const int warp = tid >> 5;
    const int lane = tid & 31;
    const int bm = blockIdx.y * 128;
    const int bn = blockIdx.x * 128;
    const int wm = (warp & 1) * 64;
    const int wn = (warp >> 1) * 32;

    float c[4][4][4];
#pragma unroll
    for (int mt = 0; mt < 4; ++mt)
#pragma unroll
        for (int nt = 0; nt < 4; ++nt)
#pragma unroll
            for (int i = 0; i < 4; ++i) c[mt][nt][i] = 0.0f;

    const int arow0 = tid >> 2,  akc = (tid & 3) * 8;
    const int brow0 = tid >> 4,  bnc = (tid & 15) * 8;

    const uint32_t a_base = sptr(&Asb[(wm + (lane & 15)) * AS_STRIDE + (lane >> 4) * 8]);
    const uint32_t b_base = sptr(&Bsb[(lane & 15) * BS_STRIDE + wn]);

    const int nk = K >> 5;

#define GEMM_LOAD_STAGE(s, k0)                                                        \
    do {                                                                              \
        cp16(sptr(&Asb[(s) * A_STG + arow0 * AS_STRIDE + akc]),                       \
             A + (size_t)(bm + arow0) * K + (k0) + akc);                              \
        cp16(sptr(&Asb[(s) * A_STG + (arow0 + 64) * AS_STRIDE + akc]),                \
             A + (size_t)(bm + arow0 + 64) * K + (k0) + akc);                         \
        cp16(sptr(&Bsb[(s) * B_STG + brow0 * BS_STRIDE + bnc]),                       \
             B + (size_t)((k0) + brow0) * N + bn + bnc);                              \
        cp16(sptr(&Bsb[(s) * B_STG + (brow0 + 16) * BS_STRIDE + bnc]),                \
             B + (size_t)((k0) + brow0 + 16) * N + bn + bnc);                         \
    } while (0)

    GEMM_LOAD_STAGE(0, 0);
    cp_commit();

    for (int t = 0; t < nk; ++t) {
        cp_wait<0>();
        __syncthreads();
        if (t + 1 < nk) {
            GEMM_LOAD_STAGE((t + 1) & 1, (t + 1) << 5);
            cp_commit();
        }

        const uint32_t ab = a_base + (t & 1) * A_STG * 2;
        const uint32_t bb = b_base + (t & 1) * B_STG * 2;
#pragma unroll
        for (int kt = 0; kt < 2; ++kt) {
            uint32_t a[4][4], b[4][2];
#pragma unroll
            for (int mt = 0; mt < 4; ++mt)
                ldsm_x4(a[mt], ab + (mt * 16 * AS_STRIDE + kt * 16) * 2);
#pragma unroll
            for (int nt = 0; nt < 4; ++nt)
                ldsm_x2t(b[nt], bb + (kt * 16 * BS_STRIDE + nt * 8) * 2);
#pragma unroll
            for (int mt = 0; mt < 4; ++mt)
#pragma unroll
                for (int nt = 0; nt < 4; ++nt)
                    mma16816(c[mt][nt], a[mt], b[nt]);
        }
    }

    const int gmask = (1 << lgGroup) - 1;
    const int gid = lane >> 2;
    const int tig = lane & 3;
#pragma unroll
    for (int mt = 0; mt < 4; ++mt) {
#pragma unroll
        for (int nt = 0; nt < 4; ++nt) {
            int col = bn + wn + nt * 8 + tig * 2;
            int oc = ((col >> lgGroup) * outstride) + base + (col & gmask);
            int r0 = bm + wm + mt * 16 + gid;
            if (sizeof(T) == 4) {
                *(float2*)&((float*)C)[(size_t)r0 * ldc + oc] =
                    make_float2(c[mt][nt][0], c[mt][nt][1]);
                *(float2*)&((float*)C)[(size_t)(r0 + 8) * ldc + oc] =
                    make_float2(c[mt][nt][2], c[mt][nt][3]);
            } else {
                *(__half2*)&((__half*)C)[(size_t)r0 * ldc + oc] =
                    __floats2half2_rn(c[mt][nt][0], c[mt][nt][1]);
                *(__half2*)&((__half*)C)[(size_t)(r0 + 8) * ldc + oc] =
                    __floats2half2_rn(c[mt][nt][2], c[mt][nt][3]);
            }
        }
    }
}

// ----------------------------------------------------------------------------
// RMSNorm over D=128 (+ extra output scale) + fp16 repack -> [b][h][s][d].
// ----------------------------------------------------------------------------
__global__ __launch_bounds__(256)
void rmsnorm_h(const float* __restrict__ in, const float* __restrict__ g,
               __half* __restrict__ out, float pscale)
{
    int row = blockIdx.x * 8 + (threadIdx.x >> 5);   // row = tok*16 + h
    int lane = threadIdx.x & 31;
    float4 v = *((const float4*)(in + (size_t)row * 128) + lane);
    float ss = v.x * v.x + v.y * v.y + v.z * v.z + v.w * v.w;
#pragma unroll
    for (int o = 16; o; o >>= 1) ss += __shfl_xor_sync(0xffffffffu, ss, o);
    float r = rsqrtf(ss * (1.0f / 128.0f) + 1e-6f) * pscale;
    float4 gv = ((const float4*)g)[lane];
    int tok = row >> 4, h = row & 15;
    int b = tok >> 11, s = tok & 2047;
    __half* dst = out + ((size_t)(b * 16 + h) * 2048 + s) * 128 + lane * 4;
    *(__half2*)dst       = __floats2half2_rn(v.x * r * gv.x, v.y * r * gv.y);
    *(__half2*)(dst + 2) = __floats2half2_rn(v.z * r * gv.z, v.w * r * gv.w);
}

// ----------------------------------------------------------------------------
// Tensor-core causal flash attention, FIXED-SHIFT softmax, 128 threads /
// 4 warps / 64 query rows per CTA for 3 CTAs/SM (bubble hiding).
// Single-buffered cp.async K/V pipeline as before.
// ----------------------------------------------------------------------------
#define KS_STRIDE 136
#define SOFTMAX_SHIFT 2.8853900817779268f   /* 2*log2e */

__global__ __launch_bounds__(128, 3)
void attn_mma(const __half* __restrict__ q, const __half* __restrict__ k,
              const __half* __restrict__ v, __half* __restrict__ o)
{
    __shared__ __half Ks[64 * KS_STRIDE];
    __shared__ __half Vs[64 * KS_STRIDE];

    const int bh = blockIdx.y;
    const int b = bh >> 4, h = bh & 15;
    const int qb = ((int)gridDim.x - 1 - (int)blockIdx.x) * 64;   // heavy first
    const int tid = threadIdx.x;
    const int warp = tid >> 5, lane = tid & 31;
    const size_t base = (size_t)bh * SEQ * HD;
    const int r0 = warp * 16 + (lane >> 2);
    const int w0 = qb + warp * 16;
    const int c2 = (lane & 3) * 2;

    // Q a-frags (pre-scaled by log2e/sqrt(D) in rmsnorm)
    uint32_t aq[8][4];
    {
        const __half* q0 = q + base + (size_t)(qb + r0) * HD;
#pragma unroll
        for (int kc = 0; kc < 8; ++kc) {
            aq[kc][0] = *(const uint32_t*)(q0 + kc * 16 + c2);
            aq[kc][1] = *(const uint32_t*)(q0 + 8 * HD + kc * 16 + c2);
            aq[kc][2] = *(const uint32_t*)(q0 + kc * 16 + c2 + 8);
            aq[kc][3] = *(const uint32_t*)(q0 + 8 * HD + kc * 16 + c2 + 8);
        }
    }

    float oa[16][4];
#pragma unroll
    for (int nt = 0; nt < 16; ++nt)
#pragma unroll
        for (int i = 0; i < 4; ++i) oa[nt][i] = 0.0f;
    float l0 = 0.0f, l1 = 0.0f;          // per-lane partial sums of p

    const uint32_t kaddr = sptr(&Ks[(lane & 7) * KS_STRIDE + (lane >> 3) * 8]);
    const uint32_t vaddr = sptr(&Vs[(lane & 15) * KS_STRIDE + (lane >> 4) * 8]);

#define LOAD_K(t_)                                                                 \
    do {                                                                           \
        const __half* kg_ = k + base + (size_t)(t_) * 64 * HD;                     \
        for (int i = tid; i < 1024; i += 128) {                                    \
            int r_ = i >> 4, c_ = (i & 15) * 8;                                    \
            cp16(sptr(&Ks[r_ * KS_STRIDE + c_]), kg_ + r_ * HD + c_);              \
        }                                                                          \
    } while (0)
#define LOAD_V(t_)                                                                 \
    do {                                                                           \
        const __half* vg_ = v + ((size_t)(b * SEQ + (t_) * 64) * 16 + h) * 128;    \
        for (int i = tid; i < 1024; i += 128) {                                    \
            int r_ = i >> 4, c_ = (i & 15) * 8;                                    \
            cp16(sptr(&Vs[r_ * KS_STRIDE + c_]), vg_ + r_ * 2048 + c_);            \
        }                                                                          \
    } while (0)

    const int ntiles = qb / 64 + 1;      // keys 0 .. qb+63
    LOAD_K(0); cp_commit();
    LOAD_V(0); cp_commit();

    for (int t = 0; t < ntiles; ++t) {
        const int j0 = t * 64;

        cp_wait<1>();            // K(t) resident (V(t) may still be in flight)
        __syncthreads();

        // S = Q K^T
        float s[8][4];
#pragma unroll
        for (int nt = 0; nt < 8; ++nt) {
            s[nt][0] = s[nt][1] = s[nt][2] = s[nt][3] = 0.0f;
            uint32_t bk[4][4];
#pragma unroll
            for (int g = 0; g < 4; ++g)
                ldsm_x4(bk[g], kaddr + (nt * 8 * KS_STRIDE + g * 32) * 2);
#pragma unroll
            for (int kc = 0; kc < 8; ++kc)
                mma16816(s[nt], aq[kc], &bk[kc >> 1][(kc & 1) * 2]);
        }

        cp_wait<0>();            // V(t) resident; K buffer free after barrier
        __syncthreads();
        if (t + 1 < ntiles) LOAD_K(t + 1);
        cp_commit();             // lands during softmax+PV

        if (j0 + 63 > w0) {      // diagonal masking (last tile only)
#pragma unroll
            for (int nt = 0; nt < 8; ++nt) {
#pragma unroll
                for (int i = 0; i < 4; ++i) {
                    int col = j0 + nt * 8 + c2 + (i & 1);
                    int rowq = qb + r0 + (i >> 1) * 8;
                    if (col > rowq) s[nt][i] = -1e30f;
                }
            }
        }

        // fixed-shift exp2: p = 2^(s - C2); accumulate l per-lane
#pragma unroll
        for (int nt = 0; nt < 8; ++nt) {
            s[nt][0] = exp2f(s[nt][0] - SOFTMAX_SHIFT);
            s[nt][1] = exp2f(s[nt][1] - SOFTMAX_SHIFT);
            s[nt][2] = exp2f(s[nt][2] - SOFTMAX_SHIFT);
            s[nt][3] = exp2f(s[nt][3] - SOFTMAX_SHIFT);
            l0 += s[nt][0] + s[nt][1];
            l1 += s[nt][2] + s[nt][3];
        }

        // pack P -> fp16 a-frags
        uint32_t ap[4][4];
#pragma unroll
        for (int kc = 0; kc < 4; ++kc) {
            __half2 t0 = __floats2half2_rn(s[2 * kc][0], s[2 * kc][1]);
            __half2 t1 = __floats2half2_rn(s[2 * kc][2], s[2 * kc][3]);
            __half2 t2 = __floats2half2_rn(s[2 * kc + 1][0], s[2 * kc + 1][1]);
            __half2 t3 = __floats2half2_rn(s[2 * kc + 1][2], s[2 * kc + 1][3]);
            ap[kc][0] = *(uint32_t*)&t0;
            ap[kc][1] = *(uint32_t*)&t1;
            ap[kc][2] = *(uint32_t*)&t2;
            ap[kc][3] = *(uint32_t*)&t3;
        }

        // O += P V (no rescale ever needed)
#pragma unroll
        for (int kc = 0; kc < 4; ++kc) {
#pragma unroll
            for (int ntp = 0; ntp < 8; ++ntp) {
                uint32_t bv[4];
                ldsm_x4t(bv, vaddr + (kc * 16 * KS_STRIDE + ntp * 16) * 2);
                mma16816(oa[ntp * 2], ap[kc], &bv[0]);
                mma16816(oa[ntp * 2 + 1], ap[kc], &bv[2]);
            }
        }

        __syncthreads();         // all warps done reading V(t)
        if (t + 1 < ntiles) LOAD_V(t + 1);
        cp_commit();             // lands during next tile's QK
    }

    // single row-sum reduction of l (4 lanes per row), then normalize
    l0 += __shfl_xor_sync(0xffffffffu, l0, 1);
    l0 += __shfl_xor_sync(0xffffffffu, l0, 2);
    l1 += __shfl_xor_sync(0xffffffffu, l1, 1);
    l1 += __shfl_xor_sync(0xffffffffu, l1, 2);
    float inv0 = 1.0f / l0, inv1 = 1.0f / l1;
    size_t tok0 = (size_t)b * SEQ + qb + r0;
    __half* d0 = o + tok0 * 2048 + h * 128 + c2;
    __half* d1 = d0 + (size_t)8 * 2048;
#pragma unroll
    for (int nt = 0; nt < 16; ++nt) {
        *(__half2*)(d0 + nt * 8) = __floats2half2_rn(oa[nt][0] * inv0, oa[nt][1] * inv0);
        *(__half2*)(d1 + nt * 8) = __floats2half2_rn(oa[nt][2] * inv1, oa[nt][3] * inv1);
    }
}

// ----------------------------------------------------------------------------
extern "C" void kernel_launch(void* const* d_in, const int* in_sizes, int n_in,
                              void* d_out, int out_size)
{
    const float* x   = (const float*)d_in[0];
    const float* Wq  = (const float*)d_in[1];
    const float* Wkv = (const float*)d_in[2];
    const float* Wkr = (const float*)d_in[3];
    const float* Wkn = (const float*)d_in[4];
    const float* Wv  = (const float*)d_in[5];
    const float* Wo  = (const float*)d_in[6];
    const float* gq  = (const float*)d_in[7];
    const float* gk  = (const float*)d_in[8];
    float* out = (float*)d_out;

    float *q, *k;
    __half *hx, *hWq, *hWkv, *hWkrn, *hWv, *hWo, *hlat, *hattn, *hq, *hk, *hv;
    cudaGetSymbolAddress((void**)&q,    g_q);
    cudaGetSymbolAddress((void**)&k,    g_k);
    cudaGetSymbolAddress((void**)&hx,   h_x);
    cudaGetSymbolAddress((void**)&hWq,  h_Wq);
    cudaGetSymbolAddress((void**)&hWkv, h_Wkv);
    cudaGetSymbolAddress((void**)&hWkrn, h_Wkrn);
    cudaGetSymbolAddress((void**)&hWv,  h_Wv);
    cudaGetSymbolAddress((void**)&hWo,  h_Wo);
    cudaGetSymbolAddress((void**)&hlat, h_lat);
    cudaGetSymbolAddress((void**)&hattn, h_attn);
    cudaGetSymbolAddress((void**)&hq,   h_q);
    cudaGetSymbolAddress((void**)&hk,   h_k);
    cudaGetSymbolAddress((void**)&hv,   h_v);

    dim3 blk(256);

    // fused conversions (1 launch)
    convert_all<<<CV_BLOCKS, blk>>>(x, Wq, Wkv, Wkr, Wkn, Wv, Wo,
                                    hx, hWq, hWkv, hWkrn, hWv, hWo);

    // q = x @ Wq -> fp32 [tok][h*128+d]
    hgemm128<float><<<dim3(16, 32), blk>>>(hx, hWq, q, TOKS, 2048, HIDN,
                                           11, 2048, 0, 2048);
    // lat = x @ Wkv -> fp16 directly
    hgemm128<__half><<<dim3(4, 32), blk>>>(hx, hWkv, hlat, TOKS, DLAT, HIDN,
                                           9, DLAT, 0, DLAT);
    // k = lat @ Wkrn (combined, pre-interleaved) -> fp32 [tok][h*128+d]
    hgemm128<float><<<dim3(16, 32), blk>>>(hlat, hWkrn, k, TOKS, 2048, DLAT,
                                           11, 2048, 0, 2048);
    // v = lat @ Wv -> fp16 [tok][h][d] directly
    hgemm128<__half><<<dim3(16, 32), blk>>>(hlat, hWv, hv, TOKS, 2048, DLAT,
                                            11, 2048, 0, 2048);

    // norm + repack q/k to fp16 [b][h][s][d];
    // q gets log2e/sqrt(D) folded in (scores land in log2 domain)
    rmsnorm_h<<<TOKS * NH / 8, blk>>>(q, gq, hq, 0.12751677572069723f);
    rmsnorm_h<<<TOKS * NH / 8, blk>>>(k, gk, hk, 1.0f);

    // causal attention -> h_attn [tok][2048] fp16; 64 q-rows per CTA
    attn_mma<<<dim3(SEQ / 64, NB * NH), dim3(128)>>>(hq, hk, hv, hattn);

    // out = attn @ Wo
    hgemm128<float><<<dim3(16, 32), blk>>>(hattn, hWo, out, TOKS, 2048, 2048,
                                           11, 2048, 0, 2048);
}

// round 13
// speedup vs baseline: 10.4457x; 1.0045x over previous
#include <cuda_runtime.h>
#include <cuda_fp16.h>
#include <math.h>
#include <stdint.h>

// Problem constants
#define TOKS 4096      // B*S = 2*2048
#define SEQ  2048
#define NB   2
#define NH   16
#define HD   128
#define HIDN 2048
#define DLAT 512

// fp32 scratch (GEMM outputs pre-norm)
__device__ float g_q[TOKS * 2048];
__device__ float g_k[TOKS * 2048];

// fp16 scratch
__device__ __half h_x[TOKS * HIDN];
__device__ __half h_Wq[HIDN * 2048];
__device__ __half h_Wkv[HIDN * DLAT];
__device__ __half h_Wkrn[DLAT * 2048];   // combined head-interleaved kr|kn weight
__device__ __half h_Wv[DLAT * 2048];
__device__ __half h_Wo[2048 * HIDN];
__device__ __half h_lat[TOKS * DLAT];
__device__ __half h_attn[TOKS * 2048];
__device__ __half h_q[TOKS * 2048];   // [b][h][s][d], pre-scaled by log2e/sqrt(D)
__device__ __half h_k[TOKS * 2048];   // [b][h][s][d]
__device__ __half h_v[TOKS * 2048];   // [tok][h][d]  (GEMM-direct)

// ----------------------------------------------------------------------------
// Fused fp32->fp16 conversion of x + all weights, with Wkr/Wkn column remap
// into the combined h_Wkrn.
// ----------------------------------------------------------------------------
#define V4_X    2097152L
#define V4_WQ   1048576L
#define V4_WKV   262144L
#define V4_WKR   131072L
#define V4_WKN   131072L
#define V4_WV    262144L
#define V4_WO   1048576L
#define CV_B0 (V4_X)
#define CV_B1 (CV_B0 + V4_WQ)
#define CV_B2 (CV_B1 + V4_WKV)
#define CV_B3 (CV_B2 + V4_WKR)
#define CV_B4 (CV_B3 + V4_WKN)
#define CV_B5 (CV_B4 + V4_WV)
#define CV_B6 (CV_B5 + V4_WO)
#define CV_BLOCKS (CV_B6 / 256)

__device__ __forceinline__ void cvt4(const float* s, __half* d, long si, long di)
{
    float4 v = *(const float4*)(s + si * 4);
    *(__half2*)(d + di * 4)     = __floats2half2_rn(v.x, v.y);
    *(__half2*)(d + di * 4 + 2) = __floats2half2_rn(v.z, v.w);
}

__global__ __launch_bounds__(256)
void convert_all(const float* __restrict__ x,  const float* __restrict__ Wq,
                 const float* __restrict__ Wkv, const float* __restrict__ Wkr,
                 const float* __restrict__ Wkn, const float* __restrict__ Wv,
                 const float* __restrict__ Wo,
                 __half* __restrict__ hx,  __half* __restrict__ hWq,
                 __half* __restrict__ hWkv, __half* __restrict__ hWkrn,
                 __half* __restrict__ hWv, __half* __restrict__ hWo)
{
    long v4 = (long)blockIdx.x * 256 + threadIdx.x;
    if (v4 < CV_B0)      cvt4(x,   hx,   v4, v4);
    else if (v4 < CV_B1) cvt4(Wq,  hWq,  v4 - CV_B0, v4 - CV_B0);
    else if (v4 < CV_B2) cvt4(Wkv, hWkv, v4 - CV_B1, v4 - CV_B1);
    else if (v4 < CV_B3) {
        long e = v4 - CV_B2;            // vec4 within Wkr [512 x 1024]
        long row = e >> 8;
        int j = (int)(e & 255) * 4;
        int h = j >> 6, c = j & 63;
        long dst = row * 2048 + h * 128 + c;
        cvt4(Wkr, hWkrn, e, dst >> 2);
    } else if (v4 < CV_B4) {
        long e = v4 - CV_B3;            // vec4 within Wkn [512 x 1024]
        long row = e >> 8;
        int j = (int)(e & 255) * 4;
        int h = j >> 6, c = j & 63;
        long dst = row * 2048 + h * 128 + 64 + c;
        cvt4(Wkn, hWkrn, e, dst >> 2);
    }
    else if (v4 < CV_B5) cvt4(Wv, hWv, v4 - CV_B4, v4 - CV_B4);
    else                 cvt4(Wo, hWo, v4 - CV_B5, v4 - CV_B5);
}

// ----------------------------------------------------------------------------
#define AS_STRIDE 40    // halves
#define BS_STRIDE 136   // halves
#define A_STG (128 * AS_STRIDE)   // 5120 halves per stage
#define B_STG (32 * BS_STRIDE)    // 4352 halves per stage

__device__ __forceinline__ uint32_t sptr(const void* p)
{
    return (uint32_t)__cvta_generic_to_shared(p);
}
__device__ __forceinline__ void ldsm_x4(uint32_t* r, uint32_t addr)
{
    asm volatile("ldmatrix.sync.aligned.m8n8.x4.shared.b16 {%0,%1,%2,%3}, [%4];\n"
                 : "=r"(r[0]), "=r"(r[1]), "=r"(r[2]), "=r"(r[3]) : "r"(addr));
}
__device__ __forceinline__ void ldsm_x2t(uint32_t* r, uint32_t addr)
{
    asm volatile("ldmatrix.sync.aligned.m8n8.x2.trans.shared.b16 {%0,%1}, [%2];\n"
                 : "=r"(r[0]), "=r"(r[1]) : "r"(addr));
}
__device__ __forceinline__ void ldsm_x4t(uint32_t* r, uint32_t addr)
{
    asm volatile("ldmatrix.sync.aligned.m8n8.x4.trans.shared.b16 {%0,%1,%2,%3}, [%4];\n"
                 : "=r"(r[0]), "=r"(r[1]), "=r"(r[2]), "=r"(r[3]) : "r"(addr));
}
__device__ __forceinline__ void mma16816(float* c, const uint32_t* a, const uint32_t* b)
{
    asm volatile(
        "mma.sync.aligned.m16n8k16.row.col.f32.f16.f16.f32 "
        "{%0,%1,%2,%3}, {%4,%5,%6,%7}, {%8,%9}, {%0,%1,%2,%3};\n"
        : "+f"(c[0]), "+f"(c[1]), "+f"(c[2]), "+f"(c[3])
        : "r"(a[0]), "r"(a[1]), "r"(a[2]), "r"(a[3]), "r"(b[0]), "r"(b[1]));
}
__device__ __forceinline__ void cp16(uint32_t saddr, const void* g)
{
    asm volatile("cp.async.cg.shared.global [%0], [%1], 16;\n" :: "r"(saddr), "l"(g));
}
__device__ __forceinline__ void cp_commit()
{
    asm volatile("cp.async.commit_group;\n");
}
template <int N>
__device__ __forceinline__ void cp_wait()
{
    asm volatile("cp.async.wait_group %0;\n" :: "n"(N));
}
// Raw MUFU exp2 — one EX2 instruction, no software fixup path.
__device__ __forceinline__ float fast_ex2(float x)
{
    float y;
    asm("ex2.approx.ftz.f32 %0, %1;\n" : "=f"(y) : "f"(x));
    return y;
}

// ----------------------------------------------------------------------------
// Tensor-core GEMM: C (fp32 or fp16) = A fp16 @ B fp16, 128x128 block tile,
// BK=32, STATIC-smem 2-stage cp.async pipeline, ONE __syncthreads per iter.
// Epilogue column remap: out_col = (col>>lgGroup)*outstride + base + (col&mask)
// ----------------------------------------------------------------------------
template <typename T>
__global__ __launch_bounds__(256, 2)
void hgemm128(const __half* __restrict__ A, const __half* __restrict__ B,
              T* __restrict__ C, int M, int N, int K,
              int lgGroup, int outstride, int base, int ldc)
{
    __shared__ __half Asb[2 * A_STG];
    __shared__ __half Bsb[2 * B_STG];

    const int tid  = threadIdx.x;
    const int warp = tid >> 5;
    const int lane = tid & 31;
    const int bm = blockIdx.y * 128;
    const int bn = blockIdx.x * 128;
    const int wm = (warp & 1) * 64;
    const int wn = (warp >> 1) * 32;

    float c[4][4][4];
#pragma unroll
    for (int mt = 0; mt < 4; ++mt)
#pragma unroll
        for (int nt = 0; nt < 4; ++nt)
#pragma unroll
            for (int i = 0; i < 4; ++i) c[mt][nt][i] = 0.0f;

    const int arow0 = tid >> 2,  akc = (tid & 3) * 8;
    const int brow0 = tid >> 4,  bnc = (tid & 15) * 8;

    const uint32_t a_base = sptr(&Asb[(wm + (lane & 15)) * AS_STRIDE + (lane >> 4) * 8]);
    const uint32_t b_base = sptr(&Bsb[(lane & 15) * BS_STRIDE + wn]);

    const int nk = K >> 5;

#define GEMM_LOAD_STAGE(s, k0)                                                        \
    do {                                                                              \
        cp16(sptr(&Asb[(s) * A_STG + arow0 * AS_STRIDE + akc]),                       \
             A + (size_t)(bm + arow0) * K + (k0) + akc);                              \
        cp16(sptr(&Asb[(s) * A_STG + (arow0 + 64) * AS_STRIDE + akc]),                \
             A + (size_t)(bm + arow0 + 64) * K + (k0) + akc);                         \
        cp16(sptr(&Bsb[(s) * B_STG + brow0 * BS_STRIDE + bnc]),                       \
             B + (size_t)((k0) + brow0) * N + bn + bnc);                              \
        cp16(sptr(&Bsb[(s) * B_STG + (brow0 + 16) * BS_STRIDE + bnc]),                \
             B + (size_t)((k0) + brow0 + 16) * N + bn + bnc);                         \
    } while (0)

    GEMM_LOAD_STAGE(0, 0);
    cp_commit();

    for (int t = 0; t < nk; ++t) {
        cp_wait<0>();
        __syncthreads();
        if (t + 1 < nk) {
            GEMM_LOAD_STAGE((t + 1) & 1, (t + 1) << 5);
            cp_commit();
        }

        const uint32_t ab = a_base + (t & 1) * A_STG * 2;
        const uint32_t bb = b_base + (t & 1) * B_STG * 2;
#pragma unroll
        for (int kt = 0; kt < 2; ++kt) {
            uint32_t a[4][4], b[4][2];
#pragma unroll
            for (int mt = 0; mt < 4; ++mt)
                ldsm_x4(a[mt], ab + (mt * 16 * AS_STRIDE + kt * 16) * 2);
#pragma unroll
            for (int nt = 0; nt < 4; ++nt)
                ldsm_x2t(b[nt], bb + (kt * 16 * BS_STRIDE + nt * 8) * 2);
#pragma unroll
            for (int mt = 0; mt < 4; ++mt)
#pragma unroll
                for (int nt = 0; nt < 4; ++nt)
                    mma16816(c[mt][nt], a[mt], b[nt]);
        }
    }

    const int gmask = (1 << lgGroup) - 1;
    const int gid = lane >> 2;
    const int tig = lane & 3;
#pragma unroll
    for (int mt = 0; mt < 4; ++mt) {
#pragma unroll
        for (int nt = 0; nt < 4; ++nt) {
            int col = bn + wn + nt * 8 + tig * 2;
            int oc = ((col >> lgGroup) * outstride) + base + (col & gmask);
            int r0 = bm + wm + mt * 16 + gid;
            if (sizeof(T) == 4) {
                *(float2*)&((float*)C)[(size_t)r0 * ldc + oc] =
                    make_float2(c[mt][nt][0], c[mt][nt][1]);
                *(float2*)&((float*)C)[(size_t)(r0 + 8) * ldc + oc] =
                    make_float2(c[mt][nt][2], c[mt][nt][3]);
            } else {
                *(__half2*)&((__half*)C)[(size_t)r0 * ldc + oc] =
                    __floats2half2_rn(c[mt][nt][0], c[mt][nt][1]);
                *(__half2*)&((__half*)C)[(size_t)(r0 + 8) * ldc + oc] =
                    __floats2half2_rn(c[mt][nt][2], c[mt][nt][3]);
            }
        }
    }
}

// ----------------------------------------------------------------------------
// RMSNorm over D=128 (+ extra output scale) + fp16 repack -> [b][h][s][d].
// ----------------------------------------------------------------------------
__global__ __launch_bounds__(256)
void rmsnorm_h(const float* __restrict__ in, const float* __restrict__ g,
               __half* __restrict__ out, float pscale)
{
    int row = blockIdx.x * 8 + (threadIdx.x >> 5);   // row = tok*16 + h
    int lane = threadIdx.x & 31;
    float4 v = *((const float4*)(in + (size_t)row * 128) + lane);
    float ss = v.x * v.x + v.y * v.y + v.z * v.z + v.w * v.w;
#pragma unroll
    for (int o = 16; o; o >>= 1) ss += __shfl_xor_sync(0xffffffffu, ss, o);
    float r = rsqrtf(ss * (1.0f / 128.0f) + 1e-6f) * pscale;
    float4 gv = ((const float4*)g)[lane];
    int tok = row >> 4, h = row & 15;
    int b = tok >> 11, s = tok & 2047;
    __half* dst = out + ((size_t)(b * 16 + h) * 2048 + s) * 128 + lane * 4;
    *(__half2*)dst       = __floats2half2_rn(v.x * r * gv.x, v.y * r * gv.y);
    *(__half2*)(dst + 2) = __floats2half2_rn(v.z * r * gv.z, v.w * r * gv.w);
}

// ----------------------------------------------------------------------------
// Tensor-core causal flash attention, FIXED-SHIFT softmax via raw MUFU ex2,
// 128 threads / 4 warps / 64 query rows per CTA, 3 CTAs/SM.
// Single-buffered cp.async K/V pipeline.
// ----------------------------------------------------------------------------
#define KS_STRIDE 136
#define SOFTMAX_SHIFT 2.8853900817779268f   /* 2*log2e */

__global__ __launch_bounds__(128, 3)
void attn_mma(const __half* __restrict__ q, const __half* __restrict__ k,
              const __half* __restrict__ v, __half* __restrict__ o)
{
    __shared__ __half Ks[64 * KS_STRIDE];
    __shared__ __half Vs[64 * KS_STRIDE];

    const int bh = blockIdx.y;
    const int b = bh >> 4, h = bh & 15;
    const int qb = ((int)gridDim.x - 1 - (int)blockIdx.x) * 64;   // heavy first
    const int tid = threadIdx.x;
    const int warp = tid >> 5, lane = tid & 31;
    const size_t base = (size_t)bh * SEQ * HD;
    const int r0 = warp * 16 + (lane >> 2);
    const int w0 = qb + warp * 16;
    const int c2 = (lane & 3) * 2;

    // Q a-frags (pre-scaled by log2e/sqrt(D) in rmsnorm)
    uint32_t aq[8][4];
    {
        const __half* q0 = q + base + (size_t)(qb + r0) * HD;
#pragma unroll
        for (int kc = 0; kc < 8; ++kc) {
            aq[kc][0] = *(const uint32_t*)(q0 + kc * 16 + c2);
            aq[kc][1] = *(const uint32_t*)(q0 + 8 * HD + kc * 16 + c2);
            aq[kc][2] = *(const uint32_t*)(q0 + kc * 16 + c2 + 8);
            aq[kc][3] = *(const uint32_t*)(q0 + 8 * HD + kc * 16 + c2 + 8);
        }
    }

    float oa[16][4];
#pragma unroll
    for (int nt = 0; nt < 16; ++nt)
#pragma unroll
        for (int i = 0; i < 4; ++i) oa[nt][i] = 0.0f;
    float l0 = 0.0f, l1 = 0.0f;          // per-lane partial sums of p

    const uint32_t kaddr = sptr(&Ks[(lane & 7) * KS_STRIDE + (lane >> 3) * 8]);
    const uint32_t vaddr = sptr(&Vs[(lane & 15) * KS_STRIDE + (lane >> 4) * 8]);

#define LOAD_K(t_)                                                                 \
    do {                                                                           \
        const __half* kg_ = k + base + (size_t)(t_) * 64 * HD;                     \
        for (int i = tid; i < 1024; i += 128) {                                    \
            int r_ = i >> 4, c_ = (i & 15) * 8;                                    \
            cp16(sptr(&Ks[r_ * KS_STRIDE + c_]), kg_ + r_ * HD + c_);              \
        }                                                                          \
    } while (0)
#define LOAD_V(t_)                                                                 \
    do {                                                                           \
        const __half* vg_ = v + ((size_t)(b * SEQ + (t_) * 64) * 16 + h) * 128;    \
        for (int i = tid; i < 1024; i += 128) {                                    \
            int r_ = i >> 4, c_ = (i & 15) * 8;                                    \
            cp16(sptr(&Vs[r_ * KS_STRIDE + c_]), vg_ + r_ * 2048 + c_);            \
        }                                                                          \
    } while (0)

    const int ntiles = qb / 64 + 1;      // keys 0 .. qb+63
    LOAD_K(0); cp_commit();
    LOAD_V(0); cp_commit();

    for (int t = 0; t < ntiles; ++t) {
        const int j0 = t * 64;

        cp_wait<1>();            // K(t) resident (V(t) may still be in flight)
        __syncthreads();

        // S = Q K^T
        float s[8][4];
#pragma unroll
        for (int nt = 0; nt < 8; ++nt) {
            s[nt][0] = s[nt][1] = s[nt][2] = s[nt][3] = 0.0f;
            uint32_t bk[4][4];
#pragma unroll
            for (int g = 0; g < 4; ++g)
                ldsm_x4(bk[g], kaddr + (nt * 8 * KS_STRIDE + g * 32) * 2);
#pragma unroll
            for (int kc = 0; kc < 8; ++kc)
                mma16816(s[nt], aq[kc], &bk[kc >> 1][(kc & 1) * 2]);
        }

        cp_wait<0>();            // V(t) resident; K buffer free after barrier
        __syncthreads();
        if (t + 1 < ntiles) LOAD_K(t + 1);
        cp_commit();             // lands during softmax+PV

        if (j0 + 63 > w0) {      // diagonal masking (last tile only)
#pragma unroll
            for (int nt = 0; nt < 8; ++nt) {
#pragma unroll
                for (int i = 0; i < 4; ++i) {
                    int col = j0 + nt * 8 + c2 + (i & 1);
                    int rowq = qb + r0 + (i >> 1) * 8;
                    if (col > rowq) s[nt][i] = -1e30f;
                }
            }
        }

        // fixed-shift MUFU exp2: p = 2^(s - C2); accumulate l per-lane
#pragma unroll
        for (int nt = 0; nt < 8; ++nt) {
            s[nt][0] = fast_ex2(s[nt][0] - SOFTMAX_SHIFT);
            s[nt][1] = fast_ex2(s[nt][1] - SOFTMAX_SHIFT);
            s[nt][2] = fast_ex2(s[nt][2] - SOFTMAX_SHIFT);
            s[nt][3] = fast_ex2(s[nt][3] - SOFTMAX_SHIFT);
            l0 += s[nt][0] + s[nt][1];
            l1 += s[nt][2] + s[nt][3];
        }

        // pack P -> fp16 a-frags
        uint32_t ap[4][4];
#pragma unroll
        for (int kc = 0; kc < 4; ++kc) {
            __half2 t0 = __floats2half2_rn(s[2 * kc][0], s[2 * kc][1]);
            __half2 t1 = __floats2half2_rn(s[2 * kc][2], s[2 * kc][3]);
            __half2 t2 = __floats2half2_rn(s[2 * kc + 1][0], s[2 * kc + 1][1]);
            __half2 t3 = __floats2half2_rn(s[2 * kc + 1][2], s[2 * kc + 1][3]);
            ap[kc][0] = *(uint32_t*)&t0;
            ap[kc][1] = *(uint32_t*)&t1;
            ap[kc][2] = *(uint32_t*)&t2;
            ap[kc][3] = *(uint32_t*)&t3;
        }

        // O += P V (no rescale ever needed)
#pragma unroll
        for (int kc = 0; kc < 4; ++kc) {
#pragma unroll
            for (int ntp = 0; ntp < 8; ++ntp) {
                uint32_t bv[4];
                ldsm_x4t(bv, vaddr + (kc * 16 * KS_STRIDE + ntp * 16) * 2);
                mma16816(oa[ntp * 2], ap[kc], &bv[0]);
                mma16816(oa[ntp * 2 + 1], ap[kc], &bv[2]);
            }
        }

        __syncthreads();         // all warps done reading V(t)
        if (t + 1 < ntiles) LOAD_V(t + 1);
        cp_commit();             // lands during next tile's QK
    }

    // single row-sum reduction of l (4 lanes per row), then normalize
    l0 += __shfl_xor_sync(0xffffffffu, l0, 1);
    l0 += __shfl_xor_sync(0xffffffffu, l0, 2);
    l1 += __shfl_xor_sync(0xffffffffu, l1, 1);
    l1 += __shfl_xor_sync(0xffffffffu, l1, 2);
    float inv0 = 1.0f / l0, inv1 = 1.0f / l1;
    size_t tok0 = (size_t)b * SEQ + qb + r0;
    __half* d0 = o + tok0 * 2048 + h * 128 + c2;
    __half* d1 = d0 + (size_t)8 * 2048;
#pragma unroll
    for (int nt = 0; nt < 16; ++nt) {
        *(__half2*)(d0 + nt * 8) = __floats2half2_rn(oa[nt][0] * inv0, oa[nt][1] * inv0);
        *(__half2*)(d1 + nt * 8) = __floats2half2_rn(oa[nt][2] * inv1, oa[nt][3] * inv1);
    }
}

// ----------------------------------------------------------------------------
extern "C" void kernel_launch(void* const* d_in, const int* in_sizes, int n_in,
                              void* d_out, int out_size)
{
    const float* x   = (const float*)d_in[0];
    const float* Wq  = (const float*)d_in[1];
    const float* Wkv = (const float*)d_in[2];
    const float* Wkr = (const float*)d_in[3];
    const float* Wkn = (const float*)d_in[4];
    const float* Wv  = (const float*)d_in[5];
    const float* Wo  = (const float*)d_in[6];
    const float* gq  = (const float*)d_in[7];
    const float* gk  = (const float*)d_in[8];
    float* out = (float*)d_out;

    float *q, *k;
    __half *hx, *hWq, *hWkv, *hWkrn, *hWv, *hWo, *hlat, *hattn, *hq, *hk, *hv;
    cudaGetSymbolAddress((void**)&q,    g_q);
    cudaGetSymbolAddress((void**)&k,    g_k);
    cudaGetSymbolAddress((void**)&hx,   h_x);
    cudaGetSymbolAddress((void**)&hWq,  h_Wq);
    cudaGetSymbolAddress((void**)&hWkv, h_Wkv);
    cudaGetSymbolAddress((void**)&hWkrn, h_Wkrn);
    cudaGetSymbolAddress((void**)&hWv,  h_Wv);
    cudaGetSymbolAddress((void**)&hWo,  h_Wo);
    cudaGetSymbolAddress((void**)&hlat, h_lat);
    cudaGetSymbolAddress((void**)&hattn, h_attn);
    cudaGetSymbolAddress((void**)&hq,   h_q);
    cudaGetSymbolAddress((void**)&hk,   h_k);
    cudaGetSymbolAddress((void**)&hv,   h_v);

    dim3 blk(256);

    // fused conversions (1 launch)
    convert_all<<<CV_BLOCKS, blk>>>(x, Wq, Wkv, Wkr, Wkn, Wv, Wo,
                                    hx, hWq, hWkv, hWkrn, hWv, hWo);

    // q = x @ Wq -> fp32 [tok][h*128+d]
    hgemm128<float><<<dim3(16, 32), blk>>>(hx, hWq, q, TOKS, 2048, HIDN,
                                           11, 2048, 0, 2048);
    // lat = x @ Wkv -> fp16 directly
    hgemm128<__half><<<dim3(4, 32), blk>>>(hx, hWkv, hlat, TOKS, DLAT, HIDN,
                                           9, DLAT, 0, DLAT);
    // k = lat @ Wkrn (combined, pre-interleaved) -> fp32 [tok][h*128+d]
    hgemm128<float><<<dim3(16, 32), blk>>>(hlat, hWkrn, k, TOKS, 2048, DLAT,
                                           11, 2048, 0, 2048);
    // v = lat @ Wv -> fp16 [tok][h][d] directly
    hgemm128<__half><<<dim3(16, 32), blk>>>(hlat, hWv, hv, TOKS, 2048, DLAT,
                                            11, 2048, 0, 2048);

    // norm + repack q/k to fp16 [b][h][s][d];
    // q gets log2e/sqrt(D) folded in (scores land in log2 domain)
    rmsnorm_h<<<TOKS * NH / 8, blk>>>(q, gq, hq, 0.12751677572069723f);
    rmsnorm_h<<<TOKS * NH / 8, blk>>>(k, gk, hk, 1.0f);

    // causal attention -> h_attn [tok][2048] fp16; 64 q-rows per CTA
    attn_mma<<<dim3(SEQ / 64, NB * NH), dim3(128)>>>(hq, hk, hv, hattn);

    // out = attn @ Wo
    hgemm128<float><<<dim3(16, 32), blk>>>(hattn, hWo, out, TOKS, 2048, 2048,
                                           11, 2048, 0, 2048);
}

// round 14
// speedup vs baseline: 10.8771x; 1.0413x over previous
#include <cuda_runtime.h>
#include <cuda_fp16.h>
#include <math.h>
#include <stdint.h>

// Problem constants
#define TOKS 4096      // B*S = 2*2048
#define SEQ  2048
#define NB   2
#define NH   16
#define HD   128
#define HIDN 2048
#define DLAT 512

// fp32 scratch (GEMM outputs pre-norm)
__device__ float g_q[TOKS * 2048];
__device__ float g_k[TOKS * 2048];

// fp16 scratch
__device__ __half h_x[TOKS * HIDN];
__device__ __half h_Wq[HIDN * 2048];
__device__ __half h_Wkv[HIDN * DLAT];
__device__ __half h_Wkrn[DLAT * 2048];   // combined head-interleaved kr|kn weight
__device__ __half h_Wv[DLAT * 2048];
__device__ __half h_Wo[2048 * HIDN];
__device__ __half h_lat[TOKS * DLAT];
__device__ __half h_attn[TOKS * 2048];
__device__ __half h_q[TOKS * 2048];   // [b][h][s][d], unswizzled, *log2e/sqrt(D)
__device__ __half h_k[TOKS * 2048];   // [b][h][s][d], XOR-swizzled rows
__device__ __half h_v[TOKS * 2048];   // [b][h][s][d], XOR-swizzled rows

// ----------------------------------------------------------------------------
// Fused fp32->fp16 conversion of x + all weights (Wkr/Wkn remap into h_Wkrn).
// ----------------------------------------------------------------------------
#define V4_X    2097152L
#define V4_WQ   1048576L
#define V4_WKV   262144L
#define V4_WKR   131072L
#define V4_WKN   131072L
#define V4_WV    262144L
#define V4_WO   1048576L
#define CV_B0 (V4_X)
#define CV_B1 (CV_B0 + V4_WQ)
#define CV_B2 (CV_B1 + V4_WKV)
#define CV_B3 (CV_B2 + V4_WKR)
#define CV_B4 (CV_B3 + V4_WKN)
#define CV_B5 (CV_B4 + V4_WV)
#define CV_B6 (CV_B5 + V4_WO)
#define CV_BLOCKS (CV_B6 / 256)

__device__ __forceinline__ void cvt4(const float* s, __half* d, long si, long di)
{
    float4 v = *(const float4*)(s + si * 4);
    *(__half2*)(d + di * 4)     = __floats2half2_rn(v.x, v.y);
    *(__half2*)(d + di * 4 + 2) = __floats2half2_rn(v.z, v.w);
}

__global__ __launch_bounds__(256)
void convert_all(const float* __restrict__ x,  const float* __restrict__ Wq,
                 const float* __restrict__ Wkv, const float* __restrict__ Wkr,
                 const float* __restrict__ Wkn, const float* __restrict__ Wv,
                 const float* __restrict__ Wo,
                 __half* __restrict__ hx,  __half* __restrict__ hWq,
                 __half* __restrict__ hWkv, __half* __restrict__ hWkrn,
                 __half* __restrict__ hWv, __half* __restrict__ hWo)
{
    long v4 = (long)blockIdx.x * 256 + threadIdx.x;
    if (v4 < CV_B0)      cvt4(x,   hx,   v4, v4);
    else if (v4 < CV_B1) cvt4(Wq,  hWq,  v4 - CV_B0, v4 - CV_B0);
    else if (v4 < CV_B2) cvt4(Wkv, hWkv, v4 - CV_B1, v4 - CV_B1);
    else if (v4 < CV_B3) {
        long e = v4 - CV_B2;
        long row = e >> 8;
        int j = (int)(e & 255) * 4;
        int h = j >> 6, c = j & 63;
        long dst = row * 2048 + h * 128 + c;
        cvt4(Wkr, hWkrn, e, dst >> 2);
    } else if (v4 < CV_B4) {
        long e = v4 - CV_B3;
        long row = e >> 8;
        int j = (int)(e & 255) * 4;
        int h = j >> 6, c = j & 63;
        long dst = row * 2048 + h * 128 + 64 + c;
        cvt4(Wkn, hWkrn, e, dst >> 2);
    }
    else if (v4 < CV_B5) cvt4(Wv, hWv, v4 - CV_B4, v4 - CV_B4);
    else                 cvt4(Wo, hWo, v4 - CV_B5, v4 - CV_B5);
}

// ----------------------------------------------------------------------------
#define AS_STRIDE 40
#define BS_STRIDE 136
#define A_STG (128 * AS_STRIDE)
#define B_STG (32 * BS_STRIDE)

__device__ __forceinline__ uint32_t sptr(const void* p)
{
    return (uint32_t)__cvta_generic_to_shared(p);
}
__device__ __forceinline__ void ldsm_x4(uint32_t* r, uint32_t addr)
{
    asm volatile("ldmatrix.sync.aligned.m8n8.x4.shared.b16 {%0,%1,%2,%3}, [%4];\n"
                 : "=r"(r[0]), "=r"(r[1]), "=r"(r[2]), "=r"(r[3]) : "r"(addr));
}
__device__ __forceinline__ void ldsm_x2t(uint32_t* r, uint32_t addr)
{
    asm volatile("ldmatrix.sync.aligned.m8n8.x2.trans.shared.b16 {%0,%1}, [%2];\n"
                 : "=r"(r[0]), "=r"(r[1]) : "r"(addr));
}
__device__ __forceinline__ void ldsm_x4t(uint32_t* r, uint32_t addr)
{
    asm volatile("ldmatrix.sync.aligned.m8n8.x4.trans.shared.b16 {%0,%1,%2,%3}, [%4];\n"
                 : "=r"(r[0]), "=r"(r[1]), "=r"(r[2]), "=r"(r[3]) : "r"(addr));
}
__device__ __forceinline__ void mma16816(float* c, const uint32_t* a, const uint32_t* b)
{
    asm volatile(
        "mma.sync.aligned.m16n8k16.row.col.f32.f16.f16.f32 "
        "{%0,%1,%2,%3}, {%4,%5,%6,%7}, {%8,%9}, {%0,%1,%2,%3};\n"
        : "+f"(c[0]), "+f"(c[1]), "+f"(c[2]), "+f"(c[3])
        : "r"(a[0]), "r"(a[1]), "r"(a[2]), "r"(a[3]), "r"(b[0]), "r"(b[1]));
}
__device__ __forceinline__ void cp16(uint32_t saddr, const void* g)
{
    asm volatile("cp.async.cg.shared.global [%0], [%1], 16;\n" :: "r"(saddr), "l"(g));
}
__device__ __forceinline__ void cp_commit()
{
    asm volatile("cp.async.commit_group;\n");
}
template <int N>
__device__ __forceinline__ void cp_wait()
{
    asm volatile("cp.async.wait_group %0;\n" :: "n"(N));
}
__device__ __forceinline__ float fast_ex2(float x)
{
    float y;
    asm("ex2.approx.ftz.f32 %0, %1;\n" : "=f"(y) : "f"(x));
    return y;
}
// mbarrier helpers
__device__ __forceinline__ void mbar_init(uint32_t addr, uint32_t count)
{
    asm volatile("mbarrier.init.shared.b64 [%0], %1;\n" :: "r"(addr), "r"(count) : "memory");
}
__device__ __forceinline__ void mbar_expect_tx(uint32_t addr, uint32_t bytes)
{
    asm volatile("mbarrier.arrive.expect_tx.shared.b64 _, [%0], %1;\n"
                 :: "r"(addr), "r"(bytes) : "memory");
}
__device__ __forceinline__ void mbar_wait(uint32_t addr, uint32_t parity)
{
    asm volatile(
        "{\n\t.reg .pred P;\n"
        "WAIT_%=:\n\t"
        "mbarrier.try_wait.parity.acquire.cta.shared::cta.b64 P, [%0], %1;\n\t"
        "@!P bra WAIT_%=;\n\t}"
        :: "r"(addr), "r"(parity) : "memory");
}
// 1D bulk copy gmem->smem with mbarrier completion (UBLKCP)
__device__ __forceinline__ void bulk_g2s(uint32_t dst, const void* src, uint32_t bytes,
                                         uint32_t mbar)
{
    asm volatile(
        "cp.async.bulk.shared::cta.global.mbarrier::complete_tx::bytes [%0], [%1], %2, [%3];\n"
        :: "r"(dst), "l"(src), "r"(bytes), "r"(mbar) : "memory");
}

// ----------------------------------------------------------------------------
// Tensor-core GEMM. SWZV: store fp16 output in [b][h][s][d] XOR-swizzled
// layout (for V feeding the bulk-TMA attention).
// ----------------------------------------------------------------------------
template <typename T, bool SWZV>
__global__ __launch_bounds__(256, 2)
void hgemm128(const __half* __restrict__ A, const __half* __restrict__ B,
              T* __restrict__ C, int M, int N, int K,
              int lgGroup, int outstride, int base, int ldc)
{
    __shared__ __half Asb[2 * A_STG];
    __shared__ __half Bsb[2 * B_STG];

    const int tid  = threadIdx.x;
    const int warp = tid >> 5;
    const int lane = tid & 31;
    const int bm = blockIdx.y * 128;
    const int bn = blockIdx.x * 128;
    const int wm = (warp & 1) * 64;
    const int wn = (warp >> 1) * 32;

    float c[4][4][4];
#pragma unroll
    for (int mt = 0; mt < 4; ++mt)
#pragma unroll
        for (int nt = 0; nt < 4; ++nt)
#pragma unroll
            for (int i = 0; i < 4; ++i) c[mt][nt][i] = 0.0f;

    const int arow0 = tid >> 2,  akc = (tid & 3) * 8;
    const int brow0 = tid >> 4,  bnc = (tid & 15) * 8;

    const uint32_t a_base = sptr(&Asb[(wm + (lane & 15)) * AS_STRIDE + (lane >> 4) * 8]);
    const uint32_t b_base = sptr(&Bsb[(lane & 15) * BS_STRIDE + wn]);

    const int nk = K >> 5;

#define GEMM_LOAD_STAGE(s, k0)                                                        \
    do {                                                                              \
        cp16(sptr(&Asb[(s) * A_STG + arow0 * AS_STRIDE + akc]),                       \
             A + (size_t)(bm + arow0) * K + (k0) + akc);                              \
        cp16(sptr(&Asb[(s) * A_STG + (arow0 + 64) * AS_STRIDE + akc]),                \
             A + (size_t)(bm + arow0 + 64) * K + (k0) + akc);                         \
        cp16(sptr(&Bsb[(s) * B_STG + brow0 * BS_STRIDE + bnc]),                       \
             B + (size_t)((k0) + brow0) * N + bn + bnc);                              \
        cp16(sptr(&Bsb[(s) * B_STG + (brow0 + 16) * BS_STRIDE + bnc]),                \
             B + (size_t)((k0) + brow0 + 16) * N + bn + bnc);                         \
    } while (0)

    GEMM_LOAD_STAGE(0, 0);
    cp_commit();

    for (int t = 0; t < nk; ++t) {
        cp_wait<0>();
        __syncthreads();
        if (t + 1 < nk) {
            GEMM_LOAD_STAGE((t + 1) & 1, (t + 1) << 5);
            cp_commit();
        }

        const uint32_t ab = a_base + (t & 1) * A_STG * 2;
        const uint32_t bb = b_base + (t & 1) * B_STG * 2;
#pragma unroll
        for (int kt = 0; kt < 2; ++kt) {
            uint32_t a[4][4], b[4][2];
#pragma unroll
            for (int mt = 0; mt < 4; ++mt)
                ldsm_x4(a[mt], ab + (mt * 16 * AS_STRIDE + kt * 16) * 2);
#pragma unroll
            for (int nt = 0; nt < 4; ++nt)
                ldsm_x2t(b[nt], bb + (kt * 16 * BS_STRIDE + nt * 8) * 2);
#pragma unroll
            for (int mt = 0; mt < 4; ++mt)
#pragma unroll
                for (int nt = 0; nt < 4; ++nt)
                    mma16816(c[mt][nt], a[mt], b[nt]);
        }
    }

    const int gmask = (1 << lgGroup) - 1;
    const int gid = lane >> 2;
    const int tig = lane & 3;
#pragma unroll
    for (int mt = 0; mt < 4; ++mt) {
#pragma unroll
        for (int nt = 0; nt < 4; ++nt) {
            int col = bn + wn + nt * 8 + tig * 2;
            int oc = ((col >> lgGroup) * outstride) + base + (col & gmask);
            int r0 = bm + wm + mt * 16 + gid;
            if (sizeof(T) == 4) {
                *(float2*)&((float*)C)[(size_t)r0 * ldc + oc] =
                    make_float2(c[mt][nt][0], c[mt][nt][1]);
                *(float2*)&((float*)C)[(size_t)(r0 + 8) * ldc + oc] =
                    make_float2(c[mt][nt][2], c[mt][nt][3]);
            } else if (SWZV) {
                // [b][h][s][d] + per-row XOR swizzle of 16B chunks
                int hh = oc >> 7, d = oc & 127;
#pragma unroll
                for (int rr = 0; rr < 2; ++rr) {
                    int tok = r0 + rr * 8;
                    int bb2 = tok >> 11, ss = tok & 2047;
                    size_t rb = ((size_t)(bb2 * 16 + hh) * 2048 + ss) * 128;
                    int dd = (((d >> 3) ^ (ss & 7)) << 3) + (d & 7);
                    *(__half2*)&((__half*)C)[rb + dd] =
                        __floats2half2_rn(c[mt][nt][rr * 2], c[mt][nt][rr * 2 + 1]);
                }
            } else {
                *(__half2*)&((__half*)C)[(size_t)r0 * ldc + oc] =
                    __floats2half2_rn(c[mt][nt][0], c[mt][nt][1]);
                *(__half2*)&((__half*)C)[(size_t)(r0 + 8) * ldc + oc] =
                    __floats2half2_rn(c[mt][nt][2], c[mt][nt][3]);
            }
        }
    }
}

// ----------------------------------------------------------------------------
// RMSNorm over D=128 (+ output scale) + fp16 repack -> [b][h][s][d];
// swz!=0 applies the per-row 16B-chunk XOR swizzle (for K).
// ----------------------------------------------------------------------------
__global__ __launch_bounds__(256)
void rmsnorm_h(const float* __restrict__ in, const float* __restrict__ g,
               __half* __restrict__ out, float pscale, int swz)
{
    int row = blockIdx.x * 8 + (threadIdx.x >> 5);   // row = tok*16 + h
    int lane = threadIdx.x & 31;
    float4 v = *((const float4*)(in + (size_t)row * 128) + lane);
    float ss = v.x * v.x + v.y * v.y + v.z * v.z + v.w * v.w;
#pragma unroll
    for (int o = 16; o; o >>= 1) ss += __shfl_xor_sync(0xffffffffu, ss, o);
    float r = rsqrtf(ss * (1.0f / 128.0f) + 1e-6f) * pscale;
    float4 gv = ((const float4*)g)[lane];
    int tok = row >> 4, h = row & 15;
    int b = tok >> 11, s = tok & 2047;
    int xs = swz ? (s & 7) : 0;
    int dd = (((lane >> 1) ^ xs) << 3) + (lane & 1) * 4;
    __half* dst = out + ((size_t)(b * 16 + h) * 2048 + s) * 128 + dd;
    *(__half2*)dst       = __floats2half2_rn(v.x * r * gv.x, v.y * r * gv.y);
    *(__half2*)(dst + 2) = __floats2half2_rn(v.z * r * gv.z, v.w * r * gv.w);
}

// ----------------------------------------------------------------------------
// Tensor-core causal flash attention. K/V tiles arrive via cp.async.bulk
// (2 instructions/tile) into unpadded XOR-swizzled smem; fixed-shift MUFU
// softmax; 128 threads / 64 q-rows / 3 CTAs-SM.
// ----------------------------------------------------------------------------
#define SOFTMAX_SHIFT 2.8853900817779268f   /* 2*log2e */
#define KV_BYTES 16384u

__global__ __launch_bounds__(128, 3)
void attn_mma(const __half* __restrict__ q, const __half* __restrict__ k,
              const __half* __restrict__ v, __half* __restrict__ o)
{
    __shared__ __align__(128) __half Ks[64 * 128];
    __shared__ __align__(128) __half Vs[64 * 128];
    __shared__ __align__(8) unsigned long long mbar[2];   // [0]=K, [1]=V

    const int bh = blockIdx.y;
    const int b = bh >> 4, h = bh & 15;
    const int qb = ((int)gridDim.x - 1 - (int)blockIdx.x) * 64;   // heavy first
    const int tid = threadIdx.x;
    const int lane = tid & 31;
    const int warp = tid >> 5;
    const size_t base = (size_t)bh * SEQ * HD;
    const int r0 = warp * 16 + (lane >> 2);
    const int w0 = qb + warp * 16;
    const int c2 = (lane & 3) * 2;

    const uint32_t mbarK = sptr(&mbar[0]);
    const uint32_t mbarV = sptr(&mbar[1]);
    const uint32_t ksmem = sptr(Ks);
    const uint32_t vsmem = sptr(Vs);

    // Q a-frags (pre-scaled by log2e/sqrt(D); unswizzled layout)
    uint32_t aq[8][4];
    {
        const __half* q0 = q + base + (size_t)(qb + r0) * HD;
#pragma unroll
        for (int kc = 0; kc < 8; ++kc) {
            aq[kc][0] = *(const uint32_t*)(q0 + kc * 16 + c2);
            aq[kc][1] = *(const uint32_t*)(q0 + 8 * HD + kc * 16 + c2);
            aq[kc][2] = *(const uint32_t*)(q0 + kc * 16 + c2 + 8);
            aq[kc][3] = *(const uint32_t*)(q0 + 8 * HD + kc * 16 + c2 + 8);
        }
    }

    float oa[16][4];
#pragma unroll
    for (int nt = 0; nt < 16; ++nt)
#pragma unroll
        for (int i = 0; i < 4; ++i) oa[nt][i] = 0.0f;
    float l0 = 0.0f, l1 = 0.0f;

    // swizzled ldsm lane addressing
    const uint32_t kbase = ksmem + (lane & 7) * 256;
    uint32_t kx[4];
#pragma unroll
    for (int g = 0; g < 4; ++g)
        kx[g] = ((((lane >> 3) + g * 4) ^ (lane & 7)) << 4);
    const uint32_t vbase = vsmem + (lane & 15) * 256;
    uint32_t vx[8];
#pragma unroll
    for (int ntp = 0; ntp < 8; ++ntp)
        vx[ntp] = ((((lane >> 4) + ntp * 2) ^ (lane & 7)) << 4);

    const __half* kg = k + base;   // bhsd swizzled, tiles contiguous 16KB
    const __half* vg = v + base;

    if (tid == 0) {
        mbar_init(mbarK, 1);
        mbar_init(mbarV, 1);
    }
    __syncthreads();
    if (tid == 0) {
        mbar_expect_tx(mbarK, KV_BYTES);
        bulk_g2s(ksmem, kg, KV_BYTES, mbarK);
        mbar_expect_tx(mbarV, KV_BYTES);
        bulk_g2s(vsmem, vg, KV_BYTES, mbarV);
    }

    const int ntiles = qb / 64 + 1;
    for (int t = 0; t < ntiles; ++t) {
        const int j0 = t * 64;
        const uint32_t par = t & 1;

        mbar_wait(mbarK, par);
        __syncthreads();

        // S = Q K^T
        float s[8][4];
#pragma unroll
        for (int nt = 0; nt < 8; ++nt) {
            s[nt][0] = s[nt][1] = s[nt][2] = s[nt][3] = 0.0f;
            uint32_t bk[4][4];
#pragma unroll
            for (int g = 0; g < 4; ++g)
                ldsm_x4(bk[g], kbase + nt * 2048 + kx[g]);
#pragma unroll
            for (int kc = 0; kc < 8; ++kc)
                mma16816(s[nt], aq[kc], &bk[kc >> 1][(kc & 1) * 2]);
        }

        mbar_wait(mbarV, par);
        __syncthreads();          // all warps done with K(t), V(t) resident
        if (tid == 0 && t + 1 < ntiles) {
            mbar_expect_tx(mbarK, KV_BYTES);
            bulk_g2s(ksmem, kg + (size_t)(t + 1) * 8192, KV_BYTES, mbarK);
        }

        if (j0 + 63 > w0) {       // diagonal masking (last tile only)
#pragma unroll
            for (int nt = 0; nt < 8; ++nt) {
#pragma unroll
                for (int i = 0; i < 4; ++i) {
                    int col = j0 + nt * 8 + c2 + (i & 1);
                    int rowq = qb + r0 + (i >> 1) * 8;
                    if (col > rowq) s[nt][i] = -1e30f;
                }
            }
        }

        // fixed-shift MUFU exp2
#pragma unroll
        for (int nt = 0; nt < 8; ++nt) {
            s[nt][0] = fast_ex2(s[nt][0] - SOFTMAX_SHIFT);
            s[nt][1] = fast_ex2(s[nt][1] - SOFTMAX_SHIFT);
            s[nt][2] = fast_ex2(s[nt][2] - SOFTMAX_SHIFT);
            s[nt][3] = fast_ex2(s[nt][3] - SOFTMAX_SHIFT);
            l0 += s[nt][0] + s[nt][1];
            l1 += s[nt][2] + s[nt][3];
        }

        // pack P -> fp16 a-frags
        uint32_t ap[4][4];
#pragma unroll
        for (int kc = 0; kc < 4; ++kc) {
            __half2 t0 = __floats2half2_rn(s[2 * kc][0], s[2 * kc][1]);
            __half2 t1 = __floats2half2_rn(s[2 * kc][2], s[2 * kc][3]);
            __half2 t2 = __floats2half2_rn(s[2 * kc + 1][0], s[2 * kc + 1][1]);
            __half2 t3 = __floats2half2_rn(s[2 * kc + 1][2], s[2 * kc + 1][3]);
            ap[kc][0] = *(uint32_t*)&t0;
            ap[kc][1] = *(uint32_t*)&t1;
            ap[kc][2] = *(uint32_t*)&t2;
            ap[kc][3] = *(uint32_t*)&t3;
        }

        // O += P V
#pragma unroll
        for (int kc = 0; kc < 4; ++kc) {
#pragma unroll
            for (int ntp = 0; ntp < 8; ++ntp) {
                uint32_t bv[4];
                ldsm_x4t(bv, vbase + kc * 4096 + vx[ntp]);
                mma16816(oa[ntp * 2], ap[kc], &bv[0]);
                mma16816(oa[ntp * 2 + 1], ap[kc], &bv[2]);
            }
        }

        __syncthreads();          // all warps done reading V(t)
        if (tid == 0 && t + 1 < ntiles) {
            mbar_expect_tx(mbarV, KV_BYTES);
            bulk_g2s(vsmem, vg + (size_t)(t + 1) * 8192, KV_BYTES, mbarV);
        }
    }

    // row-sum reduction of l (4 lanes per row), then normalize
    l0 += __shfl_xor_sync(0xffffffffu, l0, 1);
    l0 += __shfl_xor_sync(0xffffffffu, l0, 2);
    l1 += __shfl_xor_sync(0xffffffffu, l1, 1);
    l1 += __shfl_xor_sync(0xffffffffu, l1, 2);
    float inv0 = 1.0f / l0, inv1 = 1.0f / l1;
    size_t tok0 = (size_t)b * SEQ + qb + r0;
    __half* d0 = o + tok0 * 2048 + h * 128 + c2;
    __half* d1 = d0 + (size_t)8 * 2048;
#pragma unroll
    for (int nt = 0; nt < 16; ++nt) {
        *(__half2*)(d0 + nt * 8) = __floats2half2_rn(oa[nt][0] * inv0, oa[nt][1] * inv0);
        *(__half2*)(d1 + nt * 8) = __floats2half2_rn(oa[nt][2] * inv1, oa[nt][3] * inv1);
    }
}

// ----------------------------------------------------------------------------
extern "C" void kernel_launch(void* const* d_in, const int* in_sizes, int n_in,
                              void* d_out, int out_size)
{
    const float* x   = (const float*)d_in[0];
    const float* Wq  = (const float*)d_in[1];
    const float* Wkv = (const float*)d_in[2];
    const float* Wkr = (const float*)d_in[3];
    const float* Wkn = (const float*)d_in[4];
    const float* Wv  = (const float*)d_in[5];
    const float* Wo  = (const float*)d_in[6];
    const float* gq  = (const float*)d_in[7];
    const float* gk  = (const float*)d_in[8];
    float* out = (float*)d_out;

    float *q, *k;
    __half *hx, *hWq, *hWkv, *hWkrn, *hWv, *hWo, *hlat, *hattn, *hq, *hk, *hv;
    cudaGetSymbolAddress((void**)&q,    g_q);
    cudaGetSymbolAddress((void**)&k,    g_k);
    cudaGetSymbolAddress((void**)&hx,   h_x);
    cudaGetSymbolAddress((void**)&hWq,  h_Wq);
    cudaGetSymbolAddress((void**)&hWkv, h_Wkv);
    cudaGetSymbolAddress((void**)&hWkrn, h_Wkrn);
    cudaGetSymbolAddress((void**)&hWv,  h_Wv);
    cudaGetSymbolAddress((void**)&hWo,  h_Wo);
    cudaGetSymbolAddress((void**)&hlat, h_lat);
    cudaGetSymbolAddress((void**)&hattn, h_attn);
    cudaGetSymbolAddress((void**)&hq,   h_q);
    cudaGetSymbolAddress((void**)&hk,   h_k);
    cudaGetSymbolAddress((void**)&hv,   h_v);

    dim3 blk(256);

    convert_all<<<CV_BLOCKS, blk>>>(x, Wq, Wkv, Wkr, Wkn, Wv, Wo,
                                    hx, hWq, hWkv, hWkrn, hWv, hWo);

    // q = x @ Wq -> fp32 [tok][h*128+d]
    hgemm128<float, false><<<dim3(16, 32), blk>>>(hx, hWq, q, TOKS, 2048, HIDN,
                                                  11, 2048, 0, 2048);
    // lat = x @ Wkv -> fp16 directly
    hgemm128<__half, false><<<dim3(4, 32), blk>>>(hx, hWkv, hlat, TOKS, DLAT, HIDN,
                                                  9, DLAT, 0, DLAT);
    // k = lat @ Wkrn -> fp32 [tok][h*128+d]
    hgemm128<float, false><<<dim3(16, 32), blk>>>(hlat, hWkrn, k, TOKS, 2048, DLAT,
                                                  11, 2048, 0, 2048);
    // v = lat @ Wv -> fp16 [b][h][s][d] XOR-swizzled directly
    hgemm128<__half, true><<<dim3(16, 32), blk>>>(hlat, hWv, hv, TOKS, 2048, DLAT,
                                                  11, 2048, 0, 2048);

    // norm + repack; q unswizzled w/ log2e/sqrt(D); k swizzled
    rmsnorm_h<<<TOKS * NH / 8, blk>>>(q, gq, hq, 0.12751677572069723f, 0);
    rmsnorm_h<<<TOKS * NH / 8, blk>>>(k, gk, hk, 1.0f, 1);

    // causal attention -> h_attn [tok][2048] fp16
    attn_mma<<<dim3(SEQ / 64, NB * NH), dim3(128)>>>(hq, hk, hv, hattn);

    // out = attn @ Wo
    hgemm128<float, false><<<dim3(16, 32), blk>>>(hattn, hWo, out, TOKS, 2048, 2048,
                                                  11, 2048, 0, 2048);
}

// round 15
// speedup vs baseline: 10.9459x; 1.0063x over previous
#include <cuda_runtime.h>
#include <cuda_fp16.h>
#include <math.h>
#include <stdint.h>

// Problem constants
#define TOKS 4096      // B*S = 2*2048
#define SEQ  2048
#define NB   2
#define NH   16
#define HD   128
#define HIDN 2048
#define DLAT 512

// fp32 scratch (GEMM outputs pre-norm)
__device__ float g_q[TOKS * 2048];
__device__ float g_k[TOKS * 2048];

// fp16 scratch
__device__ __half h_x[TOKS * HIDN];
__device__ __half h_Wq[HIDN * 2048];
__device__ __half h_Wkv[HIDN * DLAT];
__device__ __half h_Wkrn[DLAT * 2048];   // combined head-interleaved kr|kn weight
__device__ __half h_Wv[DLAT * 2048];
__device__ __half h_Wo[2048 * HIDN];
__device__ __half h_lat[TOKS * DLAT];
__device__ __half h_attn[TOKS * 2048];
__device__ __half h_q[TOKS * 2048];   // [b][h][s][d], unswizzled, *log2e/sqrt(D)
__device__ __half h_k[TOKS * 2048];   // [b][h][s][d], XOR-swizzled rows
__device__ __half h_v[TOKS * 2048];   // [b][h][s][d], XOR-swizzled rows

// ----------------------------------------------------------------------------
// Fused fp32->fp16 conversion of x + all weights (Wkr/Wkn remap into h_Wkrn).
// ----------------------------------------------------------------------------
#define V4_X    2097152L
#define V4_WQ   1048576L
#define V4_WKV   262144L
#define V4_WKR   131072L
#define V4_WKN   131072L
#define V4_WV    262144L
#define V4_WO   1048576L
#define CV_B0 (V4_X)
#define CV_B1 (CV_B0 + V4_WQ)
#define CV_B2 (CV_B1 + V4_WKV)
#define CV_B3 (CV_B2 + V4_WKR)
#define CV_B4 (CV_B3 + V4_WKN)
#define CV_B5 (CV_B4 + V4_WV)
#define CV_B6 (CV_B5 + V4_WO)
#define CV_BLOCKS (CV_B6 / 256)

__device__ __forceinline__ void cvt4(const float* s, __half* d, long si, long di)
{
    float4 v = *(const float4*)(s + si * 4);
    *(__half2*)(d + di * 4)     = __floats2half2_rn(v.x, v.y);
    *(__half2*)(d + di * 4 + 2) = __floats2half2_rn(v.z, v.w);
}

__global__ __launch_bounds__(256)
void convert_all(const float* __restrict__ x,  const float* __restrict__ Wq,
                 const float* __restrict__ Wkv, const float* __restrict__ Wkr,
                 const float* __restrict__ Wkn, const float* __restrict__ Wv,
                 const float* __restrict__ Wo,
                 __half* __restrict__ hx,  __half* __restrict__ hWq,
                 __half* __restrict__ hWkv, __half* __restrict__ hWkrn,
                 __half* __restrict__ hWv, __half* __restrict__ hWo)
{
    long v4 = (long)blockIdx.x * 256 + threadIdx.x;
    if (v4 < CV_B0)      cvt4(x,   hx,   v4, v4);
    else if (v4 < CV_B1) cvt4(Wq,  hWq,  v4 - CV_B0, v4 - CV_B0);
    else if (v4 < CV_B2) cvt4(Wkv, hWkv, v4 - CV_B1, v4 - CV_B1);
    else if (v4 < CV_B3) {
        long e = v4 - CV_B2;
        long row = e >> 8;
        int j = (int)(e & 255) * 4;
        int h = j >> 6, c = j & 63;
        long dst = row * 2048 + h * 128 + c;
        cvt4(Wkr, hWkrn, e, dst >> 2);
    } else if (v4 < CV_B4) {
        long e = v4 - CV_B3;
        long row = e >> 8;
        int j = (int)(e & 255) * 4;
        int h = j >> 6, c = j & 63;
        long dst = row * 2048 + h * 128 + 64 + c;
        cvt4(Wkn, hWkrn, e, dst >> 2);
    }
    else if (v4 < CV_B5) cvt4(Wv, hWv, v4 - CV_B4, v4 - CV_B4);
    else                 cvt4(Wo, hWo, v4 - CV_B5, v4 - CV_B5);
}

// ----------------------------------------------------------------------------
#define AS_STRIDE 40
#define BS_STRIDE 136
#define A_STG (128 * AS_STRIDE)
#define B_STG (32 * BS_STRIDE)

__device__ __forceinline__ uint32_t sptr(const void* p)
{
    return (uint32_t)__cvta_generic_to_shared(p);
}
__device__ __forceinline__ void ldsm_x4(uint32_t* r, uint32_t addr)
{
    asm volatile("ldmatrix.sync.aligned.m8n8.x4.shared.b16 {%0,%1,%2,%3}, [%4];\n"
                 : "=r"(r[0]), "=r"(r[1]), "=r"(r[2]), "=r"(r[3]) : "r"(addr));
}
__device__ __forceinline__ void ldsm_x2t(uint32_t* r, uint32_t addr)
{
    asm volatile("ldmatrix.sync.aligned.m8n8.x2.trans.shared.b16 {%0,%1}, [%2];\n"
                 : "=r"(r[0]), "=r"(r[1]) : "r"(addr));
}
__device__ __forceinline__ void ldsm_x4t(uint32_t* r, uint32_t addr)
{
    asm volatile("ldmatrix.sync.aligned.m8n8.x4.trans.shared.b16 {%0,%1,%2,%3}, [%4];\n"
                 : "=r"(r[0]), "=r"(r[1]), "=r"(r[2]), "=r"(r[3]) : "r"(addr));
}
__device__ __forceinline__ void mma16816(float* c, const uint32_t* a, const uint32_t* b)
{
    asm volatile(
        "mma.sync.aligned.m16n8k16.row.col.f32.f16.f16.f32 "
        "{%0,%1,%2,%3}, {%4,%5,%6,%7}, {%8,%9}, {%0,%1,%2,%3};\n"
        : "+f"(c[0]), "+f"(c[1]), "+f"(c[2]), "+f"(c[3])
        : "r"(a[0]), "r"(a[1]), "r"(a[2]), "r"(a[3]), "r"(b[0]), "r"(b[1]));
}
__device__ __forceinline__ void cp16(uint32_t saddr, const void* g)
{
    asm volatile("cp.async.cg.shared.global [%0], [%1], 16;\n" :: "r"(saddr), "l"(g));
}
__device__ __forceinline__ void cp_commit()
{
    asm volatile("cp.async.commit_group;\n");
}
template <int N>
__device__ __forceinline__ void cp_wait()
{
    asm volatile("cp.async.wait_group %0;\n" :: "n"(N));
}
__device__ __forceinline__ float fast_ex2(float x)
{
    float y;
    asm("ex2.approx.ftz.f32 %0, %1;\n" : "=f"(y) : "f"(x));
    return y;
}
// mbarrier helpers
__device__ __forceinline__ void mbar_init(uint32_t addr, uint32_t count)
{
    asm volatile("mbarrier.init.shared.b64 [%0], %1;\n" :: "r"(addr), "r"(count) : "memory");
}
__device__ __forceinline__ void mbar_expect_tx(uint32_t addr, uint32_t bytes)
{
    asm volatile("mbarrier.arrive.expect_tx.shared.b64 _, [%0], %1;\n"
                 :: "r"(addr), "r"(bytes) : "memory");
}
__device__ __forceinline__ void mbar_wait(uint32_t addr, uint32_t parity)
{
    asm volatile(
        "{\n\t.reg .pred P;\n"
        "WAIT_%=:\n\t"
        "mbarrier.try_wait.parity.acquire.cta.shared::cta.b64 P, [%0], %1;\n\t"
        "@!P bra WAIT_%=;\n\t}"
        :: "r"(addr), "r"(parity) : "memory");
}
__device__ __forceinline__ void bulk_g2s(uint32_t dst, const void* src, uint32_t bytes,
                                         uint32_t mbar)
{
    asm volatile(
        "cp.async.bulk.shared::cta.global.mbarrier::complete_tx::bytes [%0], [%1], %2, [%3];\n"
        :: "r"(dst), "l"(src), "r"(bytes), "r"(mbar) : "memory");
}

// ----------------------------------------------------------------------------
// Tensor-core GEMM. SWZV: store fp16 output in [b][h][s][d] XOR-swizzled.
// ----------------------------------------------------------------------------
template <typename T, bool SWZV>
__global__ __launch_bounds__(256, 2)
void hgemm128(const __half* __restrict__ A, const __half* __restrict__ B,
              T* __restrict__ C, int M, int N, int K,
              int lgGroup, int outstride, int base, int ldc)
{
    __shared__ __half Asb[2 * A_STG];
    __shared__ __half Bsb[2 * B_STG];

    const int tid  = threadIdx.x;
    const int warp = tid >> 5;
    const int lane = tid & 31;
    const int bm = blockIdx.y * 128;
    const int bn = blockIdx.x * 128;
    const int wm = (warp & 1) * 64;
    const int wn = (warp >> 1) * 32;

    float c[4][4][4];
#pragma unroll
    for (int mt = 0; mt < 4; ++mt)
#pragma unroll
        for (int nt = 0; nt < 4; ++nt)
#pragma unroll
            for (int i = 0; i < 4; ++i) c[mt][nt][i] = 0.0f;

    const int arow0 = tid >> 2,  akc = (tid & 3) * 8;
    const int brow0 = tid >> 4,  bnc = (tid & 15) * 8;

    const uint32_t a_base = sptr(&Asb[(wm + (lane & 15)) * AS_STRIDE + (lane >> 4) * 8]);
    const uint32_t b_base = sptr(&Bsb[(lane & 15) * BS_STRIDE + wn]);

    const int nk = K >> 5;

#define GEMM_LOAD_STAGE(s, k0)                                                        \
    do {                                                                              \
        cp16(sptr(&Asb[(s) * A_STG + arow0 * AS_STRIDE + akc]),                       \
             A + (size_t)(bm + arow0) * K + (k0) + akc);                              \
        cp16(sptr(&Asb[(s) * A_STG + (arow0 + 64) * AS_STRIDE + akc]),                \
             A + (size_t)(bm + arow0 + 64) * K + (k0) + akc);                         \
        cp16(sptr(&Bsb[(s) * B_STG + brow0 * BS_STRIDE + bnc]),                       \
             B + (size_t)((k0) + brow0) * N + bn + bnc);                              \
        cp16(sptr(&Bsb[(s) * B_STG + (brow0 + 16) * BS_STRIDE + bnc]),                \
             B + (size_t)((k0) + brow0 + 16) * N + bn + bnc);                         \
    } while (0)

    GEMM_LOAD_STAGE(0, 0);
    cp_commit();

    for (int t = 0; t < nk; ++t) {
        cp_wait<0>();
        __syncthreads();
        if (t + 1 < nk) {
            GEMM_LOAD_STAGE((t + 1) & 1, (t + 1) << 5);
            cp_commit();
        }

        const uint32_t ab = a_base + (t & 1) * A_STG * 2;
        const uint32_t bb = b_base + (t & 1) * B_STG * 2;
#pragma unroll
        for (int kt = 0; kt < 2; ++kt) {
            uint32_t a[4][4], b[4][2];
#pragma unroll
            for (int mt = 0; mt < 4; ++mt)
                ldsm_x4(a[mt], ab + (mt * 16 * AS_STRIDE + kt * 16) * 2);
#pragma unroll
            for (int nt = 0; nt < 4; ++nt)
                ldsm_x2t(b[nt], bb + (kt * 16 * BS_STRIDE + nt * 8) * 2);
#pragma unroll
            for (int mt = 0; mt < 4; ++mt)
#pragma unroll
                for (int nt = 0; nt < 4; ++nt)
                    mma16816(c[mt][nt], a[mt], b[nt]);
        }
    }

    const int gmask = (1 << lgGroup) - 1;
    const int gid = lane >> 2;
    const int tig = lane & 3;
#pragma unroll
    for (int mt = 0; mt < 4; ++mt) {
#pragma unroll
        for (int nt = 0; nt < 4; ++nt) {
            int col = bn + wn + nt * 8 + tig * 2;
            int oc = ((col >> lgGroup) * outstride) + base + (col & gmask);
            int r0 = bm + wm + mt * 16 + gid;
            if (sizeof(T) == 4) {
                *(float2*)&((float*)C)[(size_t)r0 * ldc + oc] =
                    make_float2(c[mt][nt][0], c[mt][nt][1]);
                *(float2*)&((float*)C)[(size_t)(r0 + 8) * ldc + oc] =
                    make_float2(c[mt][nt][2], c[mt][nt][3]);
            } else if (SWZV) {
                int hh = oc >> 7, d = oc & 127;
#pragma unroll
                for (int rr = 0; rr < 2; ++rr) {
                    int tok = r0 + rr * 8;
                    int bb2 = tok >> 11, ss = tok & 2047;
                    size_t rb = ((size_t)(bb2 * 16 + hh) * 2048 + ss) * 128;
                    int dd = (((d >> 3) ^ (ss & 7)) << 3) + (d & 7);
                    *(__half2*)&((__half*)C)[rb + dd] =
                        __floats2half2_rn(c[mt][nt][rr * 2], c[mt][nt][rr * 2 + 1]);
                }
            } else {
                *(__half2*)&((__half*)C)[(size_t)r0 * ldc + oc] =
                    __floats2half2_rn(c[mt][nt][0], c[mt][nt][1]);
                *(__half2*)&((__half*)C)[(size_t)(r0 + 8) * ldc + oc] =
                    __floats2half2_rn(c[mt][nt][2], c[mt][nt][3]);
            }
        }
    }
}

// ----------------------------------------------------------------------------
// RMSNorm + fp16 repack -> [b][h][s][d]; swz applies 16B-chunk XOR (for K).
// ----------------------------------------------------------------------------
__global__ __launch_bounds__(256)
void rmsnorm_h(const float* __restrict__ in, const float* __restrict__ g,
               __half* __restrict__ out, float pscale, int swz)
{
    int row = blockIdx.x * 8 + (threadIdx.x >> 5);   // row = tok*16 + h
    int lane = threadIdx.x & 31;
    float4 v = *((const float4*)(in + (size_t)row * 128) + lane);
    float ss = v.x * v.x + v.y * v.y + v.z * v.z + v.w * v.w;
#pragma unroll
    for (int o = 16; o; o >>= 1) ss += __shfl_xor_sync(0xffffffffu, ss, o);
    float r = rsqrtf(ss * (1.0f / 128.0f) + 1e-6f) * pscale;
    float4 gv = ((const float4*)g)[lane];
    int tok = row >> 4, h = row & 15;
    int b = tok >> 11, s = tok & 2047;
    int xs = swz ? (s & 7) : 0;
    int dd = (((lane >> 1) ^ xs) << 3) + (lane & 1) * 4;
    __half* dst = out + ((size_t)(b * 16 + h) * 2048 + s) * 128 + dd;
    *(__half2*)dst       = __floats2half2_rn(v.x * r * gv.x, v.y * r * gv.y);
    *(__half2*)(dst + 2) = __floats2half2_rn(v.z * r * gv.z, v.w * r * gv.w);
}

// ----------------------------------------------------------------------------
// Tensor-core causal flash attention: 32-key tiles, DOUBLE-BUFFERED combined
// K+V stages (2 x 16KB, bulk-copy, one mbar per stage), prefetch distance 2,
// one mbar-wait + one syncthreads per tile. Fixed-shift MUFU softmax.
// 128 threads / 64 q-rows / 3 CTAs-SM.
// ----------------------------------------------------------------------------
#define SOFTMAX_SHIFT 2.8853900817779268f   /* 2*log2e */
#define STG_BYTES 16384u          // K 8KB + V 8KB per stage
#define KTILE_B 8192u

__global__ __launch_bounds__(128, 3)
void attn_mma(const __half* __restrict__ q, const __half* __restrict__ k,
              const __half* __restrict__ v, __half* __restrict__ o)
{
    __shared__ __align__(128) __half KV[2][8192];         // 2 stages x 16KB
    __shared__ __align__(8) unsigned long long mbar[2];

    const int bh = blockIdx.y;
    const int b = bh >> 4, h = bh & 15;
    const int qb = ((int)gridDim.x - 1 - (int)blockIdx.x) * 64;   // heavy first
    const int tid = threadIdx.x;
    const int lane = tid & 31;
    const int warp = tid >> 5;
    const size_t base = (size_t)bh * SEQ * HD;
    const int r0 = warp * 16 + (lane >> 2);
    const int w0 = qb + warp * 16;
    const int c2 = (lane & 3) * 2;

    const uint32_t mb0 = sptr(&mbar[0]);
    const uint32_t smem0 = sptr(KV);

    // Q a-frags
    uint32_t aq[8][4];
    {
        const __half* q0 = q + base + (size_t)(qb + r0) * HD;
#pragma unroll
        for (int kc = 0; kc < 8; ++kc) {
            aq[kc][0] = *(const uint32_t*)(q0 + kc * 16 + c2);
            aq[kc][1] = *(const uint32_t*)(q0 + 8 * HD + kc * 16 + c2);
            aq[kc][2] = *(const uint32_t*)(q0 + kc * 16 + c2 + 8);
            aq[kc][3] = *(const uint32_t*)(q0 + 8 * HD + kc * 16 + c2 + 8);
        }
    }

    float oa[16][4];
#pragma unroll
    for (int nt = 0; nt < 16; ++nt)
#pragma unroll
        for (int i = 0; i < 4; ++i) oa[nt][i] = 0.0f;
    float l0 = 0.0f, l1 = 0.0f;

    // swizzled ldsm lane addressing (K rows 0-31 keys, V rows 0-31 keys)
    const uint32_t krow = (lane & 7) * 256;
    uint32_t kx[4];
#pragma unroll
    for (int g = 0; g < 4; ++g)
        kx[g] = ((((lane >> 3) + g * 4) ^ (lane & 7)) << 4);
    const uint32_t vrow = (lane & 15) * 256;
    uint32_t vx[8];
#pragma unroll
    for (int ntp = 0; ntp < 8; ++ntp)
        vx[ntp] = ((((lane >> 4) + ntp * 2) ^ (lane & 7)) << 4);

    const __half* kg = k + base;   // 32-key tiles = contiguous 8KB each
    const __half* vg = v + base;
    const int ntiles = qb / 32 + 2;   // keys 0 .. qb+63

    if (tid == 0) {
        mbar_init(mb0, 1);
        mbar_init(mb0 + 8, 1);
    }
    __syncthreads();
    if (tid == 0) {
        mbar_expect_tx(mb0, STG_BYTES);
        bulk_g2s(smem0, kg, KTILE_B, mb0);
        bulk_g2s(smem0 + KTILE_B, vg, KTILE_B, mb0);
        mbar_expect_tx(mb0 + 8, STG_BYTES);
        bulk_g2s(smem0 + STG_BYTES, kg + 4096, KTILE_B, mb0 + 8);
        bulk_g2s(smem0 + STG_BYTES + KTILE_B, vg + 4096, KTILE_B, mb0 + 8);
    }

    for (int t = 0; t < ntiles; ++t) {
        const int j0 = t * 32;
        const int stg = t & 1;
        const uint32_t kbase = smem0 + stg * STG_BYTES;
        const uint32_t vbase = kbase + KTILE_B;

        mbar_wait(mb0 + stg * 8, (t >> 1) & 1);

        if (j0 <= w0 + 15) {                       // tile live for this warp
            // S = Q K^T  (32 keys)
            float s[4][4];
#pragma unroll
            for (int nt = 0; nt < 4; ++nt) {
                s[nt][0] = s[nt][1] = s[nt][2] = s[nt][3] = 0.0f;
                uint32_t bk[4][4];
#pragma unroll
                for (int g = 0; g < 4; ++g)
                    ldsm_x4(bk[g], kbase + krow + nt * 2048 + kx[g]);
#pragma unroll
                for (int kc = 0; kc < 8; ++kc)
                    mma16816(s[nt], aq[kc], &bk[kc >> 1][(kc & 1) * 2]);
            }

            if (j0 + 31 > w0) {                    // diagonal masking
#pragma unroll
                for (int nt = 0; nt < 4; ++nt) {
#pragma unroll
                    for (int i = 0; i < 4; ++i) {
                        int col = j0 + nt * 8 + c2 + (i & 1);
                        int rowq = qb + r0 + (i >> 1) * 8;
                        if (col > rowq) s[nt][i] = -1e30f;
                    }
                }
            }

            // fixed-shift MUFU exp2
#pragma unroll
            for (int nt = 0; nt < 4; ++nt) {
                s[nt][0] = fast_ex2(s[nt][0] - SOFTMAX_SHIFT);
                s[nt][1] = fast_ex2(s[nt][1] - SOFTMAX_SHIFT);
                s[nt][2] = fast_ex2(s[nt][2] - SOFTMAX_SHIFT);
                s[nt][3] = fast_ex2(s[nt][3] - SOFTMAX_SHIFT);
                l0 += s[nt][0] + s[nt][1];
                l1 += s[nt][2] + s[nt][3];
            }

            // pack P -> fp16 a-frags (2 x 16-key chunks)
            uint32_t ap[2][4];
#pragma unroll
            for (int kc = 0; kc < 2; ++kc) {
                __half2 t0 = __floats2half2_rn(s[2 * kc][0], s[2 * kc][1]);
                __half2 t1 = __floats2half2_rn(s[2 * kc][2], s[2 * kc][3]);
                __half2 t2 = __floats2half2_rn(s[2 * kc + 1][0], s[2 * kc + 1][1]);
                __half2 t3 = __floats2half2_rn(s[2 * kc + 1][2], s[2 * kc + 1][3]);
                ap[kc][0] = *(uint32_t*)&t0;
                ap[kc][1] = *(uint32_t*)&t1;
                ap[kc][2] = *(uint32_t*)&t2;
                ap[kc][3] = *(uint32_t*)&t3;
            }

            // O += P V
#pragma unroll
            for (int kc = 0; kc < 2; ++kc) {
#pragma unroll
                for (int ntp = 0; ntp < 8; ++ntp) {
                    uint32_t bv[4];
                    ldsm_x4t(bv, vbase + vrow + kc * 4096 + vx[ntp]);
                    mma16816(oa[ntp * 2], ap[kc], &bv[0]);
                    mma16816(oa[ntp * 2 + 1], ap[kc], &bv[2]);
                }
            }
        }

        __syncthreads();          // stage (t&1) free for reuse
        if (tid == 0 && t + 2 < ntiles) {
            const __half* kg2 = kg + (size_t)(t + 2) * 4096;
            const __half* vg2 = vg + (size_t)(t + 2) * 4096;
            mbar_expect_tx(mb0 + stg * 8, STG_BYTES);
            bulk_g2s(kbase, kg2, KTILE_B, mb0 + stg * 8);
            bulk_g2s(vbase, vg2, KTILE_B, mb0 + stg * 8);
        }
    }

    // row-sum reduction of l (4 lanes per row), then normalize
    l0 += __shfl_xor_sync(0xffffffffu, l0, 1);
    l0 += __shfl_xor_sync(0xffffffffu, l0, 2);
    l1 += __shfl_xor_sync(0xffffffffu, l1, 1);
    l1 += __shfl_xor_sync(0xffffffffu, l1, 2);
    float inv0 = 1.0f / l0, inv1 = 1.0f / l1;
    size_t tok0 = (size_t)b * SEQ + qb + r0;
    __half* d0 = o + tok0 * 2048 + h * 128 + c2;
    __half* d1 = d0 + (size_t)8 * 2048;
#pragma unroll
    for (int nt = 0; nt < 16; ++nt) {
        *(__half2*)(d0 + nt * 8) = __floats2half2_rn(oa[nt][0] * inv0, oa[nt][1] * inv0);
        *(__half2*)(d1 + nt * 8) = __floats2half2_rn(oa[nt][2] * inv1, oa[nt][3] * inv1);
    }
}

// ----------------------------------------------------------------------------
extern "C" void kernel_launch(void* const* d_in, const int* in_sizes, int n_in,
                              void* d_out, int out_size)
{
    const float* x   = (const float*)d_in[0];
    const float* Wq  = (const float*)d_in[1];
    const float* Wkv = (const float*)d_in[2];
    const float* Wkr = (const float*)d_in[3];
    const float* Wkn = (const float*)d_in[4];
    const float* Wv  = (const float*)d_in[5];
    const float* Wo  = (const float*)d_in[6];
    const float* gq  = (const float*)d_in[7];
    const float* gk  = (const float*)d_in[8];
    float* out = (float*)d_out;

    float *q, *k;
    __half *hx, *hWq, *hWkv, *hWkrn, *hWv, *hWo, *hlat, *hattn, *hq, *hk, *hv;
    cudaGetSymbolAddress((void**)&q,    g_q);
    cudaGetSymbolAddress((void**)&k,    g_k);
    cudaGetSymbolAddress((void**)&hx,   h_x);
    cudaGetSymbolAddress((void**)&hWq,  h_Wq);
    cudaGetSymbolAddress((void**)&hWkv, h_Wkv);
    cudaGetSymbolAddress((void**)&hWkrn, h_Wkrn);
    cudaGetSymbolAddress((void**)&hWv,  h_Wv);
    cudaGetSymbolAddress((void**)&hWo,  h_Wo);
    cudaGetSymbolAddress((void**)&hlat, h_lat);
    cudaGetSymbolAddress((void**)&hattn, h_attn);
    cudaGetSymbolAddress((void**)&hq,   h_q);
    cudaGetSymbolAddress((void**)&hk,   h_k);
    cudaGetSymbolAddress((void**)&hv,   h_v);

    dim3 blk(256);

    convert_all<<<CV_BLOCKS, blk>>>(x, Wq, Wkv, Wkr, Wkn, Wv, Wo,
                                    hx, hWq, hWkv, hWkrn, hWv, hWo);

    hgemm128<float, false><<<dim3(16, 32), blk>>>(hx, hWq, q, TOKS, 2048, HIDN,
                                                  11, 2048, 0, 2048);
    hgemm128<__half, false><<<dim3(4, 32), blk>>>(hx, hWkv, hlat, TOKS, DLAT, HIDN,
                                                  9, DLAT, 0, DLAT);
    hgemm128<float, false><<<dim3(16, 32), blk>>>(hlat, hWkrn, k, TOKS, 2048, DLAT,
                                                  11, 2048, 0, 2048);
    hgemm128<__half, true><<<dim3(16, 32), blk>>>(hlat, hWv, hv, TOKS, 2048, DLAT,
                                                  11, 2048, 0, 2048);

    rmsnorm_h<<<TOKS * NH / 8, blk>>>(q, gq, hq, 0.12751677572069723f, 0);
    rmsnorm_h<<<TOKS * NH / 8, blk>>>(k, gk, hk, 1.0f, 1);

    attn_mma<<<dim3(SEQ / 64, NB * NH), dim3(128)>>>(hq, hk, hv, hattn);

    hgemm128<float, false><<<dim3(16, 32), blk>>>(hattn, hWo, out, TOKS, 2048, 2048,
                                                  11, 2048, 0, 2048);
}